// round 6
// baseline (speedup 1.0000x reference)
#include <cuda_runtime.h>

#define LN_EPS 1e-5f
typedef unsigned long long ull;

// ---- scratch ----
__device__ float g_s1[64*128*1024];
__device__ float g_s2[64*128*256];
__device__ float g_y3[64*192*256];
__device__ float g_kp[64*32*128];
__device__ float g_vp[64*32*192];
__device__ float g_gT[2][16384];

__device__ __forceinline__ float tanh_fast(float x){
    float y; asm("tanh.approx.f32 %0, %1;" : "=f"(y) : "f"(x)); return y;
}
__device__ __forceinline__ ull pk2(float lo, float hi){
    ull r; asm("mov.b64 %0, {%1, %2};" : "=l"(r) : "f"(lo), "f"(hi)); return r;
}
__device__ __forceinline__ ull pkdup(float v){ return pk2(v, v); }
__device__ __forceinline__ void upk2(ull p, float& lo, float& hi){
    asm("mov.b64 {%0, %1}, %2;" : "=f"(lo), "=f"(hi) : "l"(p));
}
__device__ __forceinline__ ull ffma2(ull a, ull b, ull c){
    ull d; asm("fma.rn.f32x2 %0, %1, %2, %3;" : "=l"(d) : "l"(a), "l"(b), "l"(c)); return d;
}

// ---- prep: transpose gammas ----
__global__ void prep_kernel(const float* __restrict__ g1, const float* __restrict__ g2){
    int bwhich = blockIdx.x >> 6;
    int e = ((blockIdx.x & 63) << 8) + threadIdx.x;
    const float* g = bwhich ? g2 : g1;
    int d = e >> 7, c = e & 127;
    g_gT[bwhich][c*128 + d] = g[e];
}

// ---- conv1: 3->128, 5x5, s2, p2 (64x64 -> 32x32). grid (64,4,2), 256 thr ----
__global__ void conv1_kernel(const float* __restrict__ x, const float* __restrict__ w,
                             const float* __restrict__ b){
    __shared__ float sw[4800];
    __shared__ float sin_[3885];
    int bp = blockIdx.x, tile = blockIdx.y, z = blockIdx.z;
    int t = threadIdx.x;
    for (int e = t; e < 4800; e += 256) sw[e] = w[z*4800 + e];
    int ty0 = (tile>>1)*16, tx0 = (tile&1)*16;
    int iy0 = 2*ty0 - 2, ix0 = 2*tx0 - 2;
    const float* xb = x + bp*12288;
    for (int e = t; e < 3675; e += 256){
        int c = e/1225, rem = e - c*1225, r = rem/35, col = rem - r*35;
        int gy = iy0 + r, gx = ix0 + col;
        float v = 0.f;
        if (gy>=0 && gy<64 && gx>=0 && gx<64) v = xb[c*4096 + gy*64 + gx];
        sin_[(c*35 + r)*37 + col] = v;
    }
    __syncthreads();
    int px4 = t & 63, cog = t >> 6;
    int ly = px4 >> 2, lx0 = (px4 & 3)*4;
    float* ob = g_s1 + bp*131072;
    for (int p = 0; p < 2; p++){
        int col0 = cog*16 + p*8;
        float acc[8][4];
        #pragma unroll
        for (int i = 0; i < 8; i++){
            float bb = b[z*64 + col0 + i];
            #pragma unroll
            for (int j = 0; j < 4; j++) acc[i][j] = bb;
        }
        #pragma unroll 1
        for (int c = 0; c < 3; c++){
            #pragma unroll
            for (int ky = 0; ky < 5; ky++){
                #pragma unroll
                for (int kx = 0; kx < 5; kx++){
                    float xv[4];
                    #pragma unroll
                    for (int j = 0; j < 4; j++)
                        xv[j] = sin_[(c*35 + 2*ly + ky)*37 + 2*lx0 + 2*j + kx];
                    #pragma unroll
                    for (int i = 0; i < 8; i++){
                        float wv = sw[(col0+i)*75 + c*25 + ky*5 + kx];
                        #pragma unroll
                        for (int j = 0; j < 4; j++) acc[i][j] = fmaf(wv, xv[j], acc[i][j]);
                    }
                }
            }
        }
        #pragma unroll
        for (int i = 0; i < 8; i++){
            float4 o = make_float4(acc[i][0], acc[i][1], acc[i][2], acc[i][3]);
            *reinterpret_cast<float4*>(ob + (z*64+col0+i)*1024 + (ty0+ly)*32 + tx0 + lx0) = o;
        }
    }
}

// ---- GDN in-place (f32x2). grid BP*HW/64, 256 thr ----
__global__ void gdn_kernel(int stage, const float* __restrict__ beta){
    __shared__ float sA[2048];
    __shared__ float sB[1088];
    int HW = (stage == 1) ? 1024 : 256;
    float* x = (stage == 1) ? g_s1 : g_s2;
    const float* gT = g_gT[stage-1];
    int chunks = HW >> 6;
    int bp = blockIdx.x / chunks;
    int p0 = (blockIdx.x - bp*chunks) * 64;
    int t = threadIdx.x;
    int i = t >> 4, j = t & 15;
    float* xb = x + bp*128*HW;
    ull acc[8][2];
    #pragma unroll
    for (int ii = 0; ii < 8; ii++){
        float bb = beta[i*8 + ii];
        acc[ii][0] = pkdup(bb); acc[ii][1] = pkdup(bb);
    }
    for (int c0 = 0; c0 < 128; c0 += 16){
        __syncthreads();
        for (int e = t; e < 2048; e += 256) sA[e] = gT[c0*128 + e];
        for (int e = t; e < 1024; e += 256){
            int cc = e >> 6, p = e & 63;
            float v = xb[(c0+cc)*HW + p0 + p];
            sB[cc*68 + p] = v*v;
        }
        __syncthreads();
        #pragma unroll
        for (int cc = 0; cc < 16; cc++){
            const ull* xp = reinterpret_cast<const ull*>(sB + cc*68 + j*4);
            ull x0 = xp[0], x1 = xp[1];
            float4 ga = *reinterpret_cast<const float4*>(sA + cc*128 + i*8);
            float4 gb = *reinterpret_cast<const float4*>(sA + cc*128 + i*8 + 4);
            float gs[8] = {ga.x,ga.y,ga.z,ga.w,gb.x,gb.y,gb.z,gb.w};
            #pragma unroll
            for (int ii = 0; ii < 8; ii++){
                ull wp = pkdup(gs[ii]);
                acc[ii][0] = ffma2(x0, wp, acc[ii][0]);
                acc[ii][1] = ffma2(x1, wp, acc[ii][1]);
            }
        }
    }
    #pragma unroll
    for (int ii = 0; ii < 8; ii++){
        int d = i*8 + ii;
        float a0,a1,a2,a3;
        upk2(acc[ii][0], a0, a1);
        upk2(acc[ii][1], a2, a3);
        float4 xv = *reinterpret_cast<const float4*>(xb + d*HW + p0 + j*4);
        float4 o;
        o.x = xv.x * rsqrtf(a0);
        o.y = xv.y * rsqrtf(a1);
        o.z = xv.z * rsqrtf(a2);
        o.w = xv.w * rsqrtf(a3);
        *reinterpret_cast<float4*>(xb + d*HW + p0 + j*4) = o;
    }
}

// ---- conv2: pre-paired float2 smem, dup weights. grid (64,8,2), 128 thr ----
// dyn smem: P = 8ci x 19 x 35 float2 (42560B), W2 = 16co x 200 float2 (25600B)
__global__ void __launch_bounds__(128) conv2_kernel(const float* __restrict__ w,
                                                    const float* __restrict__ b){
    extern __shared__ float2 smc2[];
    float2* sP = smc2;          // 5320 float2
    float2* sW = smc2 + 5320;   // 3200 float2
    int bp = blockIdx.x, co0 = blockIdx.y*16, ry0 = blockIdx.z*8;
    int t = threadIdx.x;
    int pxg = t & 31, cg = t >> 5;
    int ly = pxg >> 2, lx0 = (pxg & 3)*4;
    ull acc[4][2];
    #pragma unroll
    for (int i = 0; i < 4; i++){
        float bb = b[co0 + cg*4 + i];
        acc[i][0] = pkdup(bb); acc[i][1] = pkdup(bb);
    }
    const float* xb = g_s1 + bp*131072;
    int iy0 = 2*ry0 - 2;
    for (int ci0 = 0; ci0 < 128; ci0 += 8){
        __syncthreads();
        // P[ci][r][c] = (X(c-2), X(c)); staging col c <-> input gx = c-2
        for (int e = t; e < 5320; e += 128){
            int ci = e/665, rem = e - ci*665, r = rem/35, c = rem - r*35;
            int gy = iy0 + r;
            const float* row = xb + (ci0+ci)*1024 + gy*32;
            bool gok = (gy >= 0) && (gy < 32);
            int gx0 = c - 2, gx1 = c;
            float v0 = (gok && gx0 >= 0 && gx0 < 32) ? row[gx0] : 0.f;
            float v1 = (gok && gx1 < 32) ? row[gx1] : 0.f;
            sP[(ci*19 + r)*35 + c] = make_float2(v0, v1);
        }
        for (int e = t; e < 3200; e += 128){
            int i = e/200, rem = e - i*200;
            float v = w[(co0+i)*3200 + ci0*25 + rem];
            sW[e] = make_float2(v, v);
        }
        __syncthreads();
        #pragma unroll 1
        for (int ci = 0; ci < 8; ci++){
            #pragma unroll 1
            for (int ky = 0; ky < 5; ky++){
                const float2* prow = sP + (ci*19 + 2*ly + ky)*35 + 2*lx0;
                const float2* wrow = sW + cg*800 + ci*25 + ky*5;
                #pragma unroll
                for (int kx = 0; kx < 5; kx++){
                    ull xp0 = *reinterpret_cast<const ull*>(prow + kx);
                    ull xp1 = *reinterpret_cast<const ull*>(prow + kx + 4);
                    #pragma unroll
                    for (int i = 0; i < 4; i++){
                        ull wp = *reinterpret_cast<const ull*>(wrow + i*200 + kx);
                        acc[i][0] = ffma2(xp0, wp, acc[i][0]);
                        acc[i][1] = ffma2(xp1, wp, acc[i][1]);
                    }
                }
            }
        }
    }
    float* ob = g_s2 + bp*32768;
    #pragma unroll
    for (int i = 0; i < 4; i++){
        float* orow = ob + (co0 + cg*4 + i)*256 + (ry0+ly)*16 + lx0;
        *reinterpret_cast<ull*>(orow)     = acc[i][0];
        *reinterpret_cast<ull*>(orow + 2) = acc[i][1];
    }
}

// ---- conv3: pre-paired float2 smem, dup weights. grid (64,12,2), 128 thr ----
__global__ void __launch_bounds__(128) conv3_kernel(const float* __restrict__ w,
                                                    const float* __restrict__ b){
    __shared__ float2 sP[1440];   // 8ci x 10 x 18
    __shared__ float2 sW[1152];   // 16co x 72
    int bp = blockIdx.x, co0 = blockIdx.y*16, ry0 = blockIdx.z*8;
    int t = threadIdx.x;
    int pxg = t & 31, cg = t >> 5;
    int ly = pxg >> 2, lx0 = (pxg & 3)*4;
    ull acc[4][2];
    #pragma unroll
    for (int i = 0; i < 4; i++){
        float bb = b[co0 + cg*4 + i];
        acc[i][0] = pkdup(bb); acc[i][1] = pkdup(bb);
    }
    const float* xb = g_s2 + bp*32768;
    int iy0 = ry0 - 1;
    for (int ci0 = 0; ci0 < 128; ci0 += 8){
        __syncthreads();
        // P[ci][r][c] = (X(c-1), X(c)); staging col c <-> input gx = c-1
        for (int e = t; e < 1440; e += 128){
            int ci = e/180, rem = e - ci*180, r = rem/18, c = rem - r*18;
            int gy = iy0 + r;
            const float* row = xb + (ci0+ci)*256 + gy*16;
            bool gok = (gy >= 0) && (gy < 16);
            int gx0 = c - 1, gx1 = c;
            float v0 = (gok && gx0 >= 0 && gx0 < 16) ? row[gx0] : 0.f;
            float v1 = (gok && gx1 < 16) ? row[gx1] : 0.f;
            sP[(ci*10 + r)*18 + c] = make_float2(v0, v1);
        }
        for (int e = t; e < 1152; e += 128){
            int i = e/72, rem = e - i*72;
            float v = w[(co0+i)*1152 + ci0*9 + rem];
            sW[e] = make_float2(v, v);
        }
        __syncthreads();
        #pragma unroll 1
        for (int ci = 0; ci < 8; ci++){
            #pragma unroll 1
            for (int ky = 0; ky < 3; ky++){
                const float2* prow = sP + (ci*10 + ly + ky)*18 + lx0;
                const float2* wrow = sW + cg*288 + ci*9 + ky*3;
                #pragma unroll
                for (int kx = 0; kx < 3; kx++){
                    ull xp0 = *reinterpret_cast<const ull*>(prow + kx);
                    ull xp1 = *reinterpret_cast<const ull*>(prow + kx + 2);
                    #pragma unroll
                    for (int i = 0; i < 4; i++){
                        ull wp = *reinterpret_cast<const ull*>(wrow + i*72 + kx);
                        acc[i][0] = ffma2(xp0, wp, acc[i][0]);
                        acc[i][1] = ffma2(xp1, wp, acc[i][1]);
                    }
                }
            }
        }
    }
    float* ob = g_y3 + bp*49152;
    #pragma unroll
    for (int i = 0; i < 4; i++){
        float* orow = ob + (co0 + cg*4 + i)*256 + (ry0+ly)*16 + lx0;
        *reinterpret_cast<ull*>(orow)     = acc[i][0];
        *reinterpret_cast<ull*>(orow + 2) = acc[i][1];
    }
}

// ---- kv: LN + k_proj + v_proj. grid (64,5), 256 thr ----
__global__ void kv_kernel(const float* __restrict__ yg, const float* __restrict__ lnw,
                          const float* __restrict__ lnb, const float* __restrict__ Wk,
                          const float* __restrict__ Wv){
    __shared__ float s_kv[32*193];
    __shared__ float s_w[64*33];
    int bp = blockIdx.x;
    int r0 = blockIdx.y * 64;
    int t = threadIdx.x;
    int w = t >> 5, l = t & 31;
    for (int e = t; e < 6144; e += 256){
        int c = e >> 5, k = e & 31;
        s_kv[k*193 + c] = yg[bp*6144 + c*32 + k];
    }
    __syncthreads();
    {
        float lwv[6], lbv[6];
        #pragma unroll
        for (int i = 0; i < 6; i++){ lwv[i] = lnw[l+32*i]; lbv[i] = lnb[l+32*i]; }
        for (int ki = 0; ki < 4; ki++){
            int k = w*4 + ki;
            float v[6]; float s = 0.f;
            #pragma unroll
            for (int i = 0; i < 6; i++){ v[i] = s_kv[k*193 + l + 32*i]; s += v[i]; }
            #pragma unroll
            for (int o = 16; o > 0; o >>= 1) s += __shfl_xor_sync(0xffffffffu, s, o);
            float mu = s * (1.f/192.f);
            float vs = 0.f;
            #pragma unroll
            for (int i = 0; i < 6; i++){ float d = v[i]-mu; vs += d*d; }
            #pragma unroll
            for (int o = 16; o > 0; o >>= 1) vs += __shfl_xor_sync(0xffffffffu, vs, o);
            float rs = rsqrtf(vs * (1.f/192.f) + LN_EPS);
            #pragma unroll
            for (int i = 0; i < 6; i++)
                s_kv[k*193 + l + 32*i] = (v[i]-mu)*rs*lwv[i] + lbv[i];
        }
    }
    int kq = t & 7, rp = t >> 3;
    {
        float acc[2][4];
        #pragma unroll
        for (int i = 0; i < 2; i++)
            #pragma unroll
            for (int kk = 0; kk < 4; kk++) acc[i][kk] = 0.f;
        for (int c0 = 0; c0 < 192; c0 += 32){
            __syncthreads();
            for (int e = t; e < 2048; e += 256){
                int rr = e >> 5, cc = e & 31;
                int row = r0 + rr;
                s_w[rr*33 + cc] = (row < 128) ? Wk[row*192 + c0 + cc]
                                              : Wv[(row-128)*192 + c0 + cc];
            }
            __syncthreads();
            for (int cc = 0; cc < 32; cc++){
                float wv0 = s_w[(rp*2)*33 + cc], wv1 = s_w[(rp*2+1)*33 + cc];
                #pragma unroll
                for (int kk = 0; kk < 4; kk++){
                    float kvv = s_kv[(kq*4+kk)*193 + c0 + cc];
                    acc[0][kk] = fmaf(wv0, kvv, acc[0][kk]);
                    acc[1][kk] = fmaf(wv1, kvv, acc[1][kk]);
                }
            }
        }
        #pragma unroll
        for (int i = 0; i < 2; i++){
            int row = r0 + rp*2 + i;
            #pragma unroll
            for (int kk = 0; kk < 4; kk++){
                int k = kq*4 + kk;
                if (row < 128) g_kp[bp*4096 + k*128 + row] = acc[i][kk];
                else           g_vp[bp*6144 + k*192 + (row-128)] = acc[i][kk];
            }
        }
    }
}

// ---- attention: grid 512, 256 thr, 95872 B dyn smem ----
__global__ void attn_kernel(const float* __restrict__ lnqw, const float* __restrict__ lnqb,
                            const float* __restrict__ Wq, const float* __restrict__ vw,
                            const float* __restrict__ out_w, const float* __restrict__ out_b,
                            const float* __restrict__ lnow, const float* __restrict__ lnob,
                            float* __restrict__ out){
    extern __shared__ float sm[];
    float* s_qn  = sm;
    float* s_w   = sm + 6176;
    float* s_kp  = sm + 12512;
    float* s_e   = sm + 16736;
    float* s_ctx = sm + 17792;
    int bp = blockIdx.x >> 3;
    int q0 = (blockIdx.x & 7) << 5;
    int t = threadIdx.x;
    int w = t >> 5, l = t & 31;
    const float* y3 = g_y3 + bp*49152;
    for (int e = t; e < 6144; e += 256){
        int m = e >> 5, q = e & 31;
        s_qn[q*193 + m] = y3[m*256 + q0 + q];
    }
    for (int e = t; e < 4096; e += 256){
        int k = e >> 7;
        s_kp[k*132 + (e & 127)] = g_kp[bp*4096 + e];
    }
    __syncthreads();
    {
        float lwv[6], lbv[6];
        #pragma unroll
        for (int i = 0; i < 6; i++){ lwv[i] = lnqw[l+32*i]; lbv[i] = lnqb[l+32*i]; }
        for (int qi = 0; qi < 4; qi++){
            int q = w*4 + qi;
            float v[6]; float s = 0.f;
            #pragma unroll
            for (int i = 0; i < 6; i++){ v[i] = s_qn[q*193 + l + 32*i]; s += v[i]; }
            #pragma unroll
            for (int o = 16; o > 0; o >>= 1) s += __shfl_xor_sync(0xffffffffu, s, o);
            float mu = s * (1.f/192.f);
            float vs = 0.f;
            #pragma unroll
            for (int i = 0; i < 6; i++){ float d = v[i]-mu; vs += d*d; }
            #pragma unroll
            for (int o = 16; o > 0; o >>= 1) vs += __shfl_xor_sync(0xffffffffu, vs, o);
            float rs = rsqrtf(vs * (1.f/192.f) + LN_EPS);
            #pragma unroll
            for (int i = 0; i < 6; i++)
                s_qn[q*193 + l + 32*i] = (v[i]-mu)*rs*lwv[i] + lbv[i];
        }
    }
    float qp[4][4];
    #pragma unroll
    for (int a = 0; a < 4; a++)
        #pragma unroll
        for (int b2 = 0; b2 < 4; b2++) qp[a][b2] = 0.f;
    for (int c0 = 0; c0 < 192; c0 += 32){
        __syncthreads();
        for (int e = t; e < 4096; e += 256){
            int d = e >> 5, cc = e & 31;
            s_w[d*33 + cc] = Wq[d*192 + c0 + cc];
        }
        __syncthreads();
        for (int cc = 0; cc < 32; cc++){
            float wv[4], qv[4];
            #pragma unroll
            for (int j = 0; j < 4; j++) wv[j] = s_w[(l+32*j)*33 + cc];
            #pragma unroll
            for (int qi = 0; qi < 4; qi++) qv[qi] = s_qn[(w*4+qi)*193 + c0 + cc];
            #pragma unroll
            for (int qi = 0; qi < 4; qi++)
                #pragma unroll
                for (int j = 0; j < 4; j++) qp[qi][j] = fmaf(qv[qi], wv[j], qp[qi][j]);
        }
    }
    __syncthreads();
    float* s_vp = s_w;
    for (int e = t; e < 6144; e += 256){
        int k = e / 192, m = e - k*192;
        s_vp[k*193 + m] = g_vp[bp*6144 + e];
    }
    float vv[4];
    #pragma unroll
    for (int j = 0; j < 4; j++) vv[j] = vw[l + 32*j];
    for (int k = 0; k < 32; k++){
        float kp4[4];
        #pragma unroll
        for (int j = 0; j < 4; j++) kp4[j] = s_kp[k*132 + l + 32*j];
        #pragma unroll
        for (int qi = 0; qi < 4; qi++){
            float s = 0.f;
            #pragma unroll
            for (int j = 0; j < 4; j++)
                s = fmaf(tanh_fast(qp[qi][j] + kp4[j]), vv[j], s);
            #pragma unroll
            for (int o = 16; o > 0; o >>= 1) s += __shfl_xor_sync(0xffffffffu, s, o);
            if (l == 0) s_e[(w*4+qi)*33 + k] = s;
        }
    }
    __syncwarp();
    for (int qi = 0; qi < 4; qi++){
        int q = w*4 + qi;
        float ev = s_e[q*33 + l];
        float mx = ev;
        #pragma unroll
        for (int o = 16; o > 0; o >>= 1) mx = fmaxf(mx, __shfl_xor_sync(0xffffffffu, mx, o));
        float p = __expf(ev - mx);
        float s = p;
        #pragma unroll
        for (int o = 16; o > 0; o >>= 1) s += __shfl_xor_sync(0xffffffffu, s, o);
        s_e[q*33 + l] = p / s;
    }
    __syncthreads();
    {
        int qr = t >> 3, mg = t & 7;
        float acc[24];
        #pragma unroll
        for (int i = 0; i < 24; i++) acc[i] = 0.f;
        for (int k = 0; k < 32; k++){
            float a = s_e[qr*33 + k];
            #pragma unroll
            for (int i = 0; i < 24; i++)
                acc[i] = fmaf(a, s_vp[k*193 + mg + 8*i], acc[i]);
        }
        #pragma unroll
        for (int i = 0; i < 24; i++) s_ctx[qr*193 + mg + 8*i] = acc[i];
    }
    __syncthreads();
    {
        int qh = t >> 4, ng = t & 15;
        float acc0[12], acc1[12];
        #pragma unroll
        for (int i = 0; i < 12; i++){ acc0[i] = 0.f; acc1[i] = 0.f; }
        for (int m0 = 0; m0 < 192; m0 += 32){
            __syncthreads();
            for (int e = t; e < 6144; e += 256){
                int n = e >> 5, mm = e & 31;
                s_w[n*33 + mm] = out_w[n*192 + m0 + mm];
            }
            __syncthreads();
            for (int mm = 0; mm < 32; mm++){
                float c0v = s_ctx[(2*qh)*193 + m0 + mm];
                float c1v = s_ctx[(2*qh+1)*193 + m0 + mm];
                #pragma unroll
                for (int i = 0; i < 12; i++){
                    float wv = s_w[(ng+16*i)*33 + mm];
                    acc0[i] = fmaf(c0v, wv, acc0[i]);
                    acc1[i] = fmaf(c1v, wv, acc1[i]);
                }
            }
        }
        float val0[12], val1[12];
        float s0 = 0.f, s1 = 0.f;
        #pragma unroll
        for (int i = 0; i < 12; i++){
            int n = ng + 16*i;
            val0[i] = acc0[i] + out_b[n] + s_qn[(2*qh)*193 + n];
            val1[i] = acc1[i] + out_b[n] + s_qn[(2*qh+1)*193 + n];
            s0 += val0[i]; s1 += val1[i];
        }
        #pragma unroll
        for (int o = 8; o > 0; o >>= 1){
            s0 += __shfl_xor_sync(0xffffffffu, s0, o);
            s1 += __shfl_xor_sync(0xffffffffu, s1, o);
        }
        float mu0 = s0*(1.f/192.f), mu1 = s1*(1.f/192.f);
        float vs0 = 0.f, vs1 = 0.f;
        #pragma unroll
        for (int i = 0; i < 12; i++){
            float d0 = val0[i]-mu0, d1 = val1[i]-mu1;
            vs0 += d0*d0; vs1 += d1*d1;
        }
        #pragma unroll
        for (int o = 8; o > 0; o >>= 1){
            vs0 += __shfl_xor_sync(0xffffffffu, vs0, o);
            vs1 += __shfl_xor_sync(0xffffffffu, vs1, o);
        }
        float r0 = rsqrtf(vs0*(1.f/192.f) + LN_EPS);
        float r1 = rsqrtf(vs1*(1.f/192.f) + LN_EPS);
        __syncthreads();
        #pragma unroll
        for (int i = 0; i < 12; i++){
            int n = ng + 16*i;
            s_ctx[(2*qh)*193 + n]   = (val0[i]-mu0)*r0*lnow[n] + lnob[n];
            s_ctx[(2*qh+1)*193 + n] = (val1[i]-mu1)*r1*lnow[n] + lnob[n];
        }
    }
    __syncthreads();
    for (int e = t; e < 6144; e += 256){
        int n = e >> 5, q = e & 31;
        out[bp*49152 + n*256 + q0 + q] = s_ctx[q*193 + n];
    }
}

extern "C" void kernel_launch(void* const* d_in, const int* in_sizes, int n_in,
                              void* d_out, int out_size){
    const float* x_p    = (const float*)d_in[0];
    const float* y_g    = (const float*)d_in[1];
    const float* conv1w = (const float*)d_in[2];
    const float* conv1b = (const float*)d_in[3];
    const float* gamma1 = (const float*)d_in[4];
    const float* beta1  = (const float*)d_in[5];
    const float* conv2w = (const float*)d_in[6];
    const float* conv2b = (const float*)d_in[7];
    const float* gamma2 = (const float*)d_in[8];
    const float* beta2  = (const float*)d_in[9];
    const float* conv3w = (const float*)d_in[10];
    const float* conv3b = (const float*)d_in[11];
    const float* lnqw   = (const float*)d_in[12];
    const float* lnqb   = (const float*)d_in[13];
    const float* lnkw   = (const float*)d_in[14];
    const float* lnkb   = (const float*)d_in[15];
    const float* lnow   = (const float*)d_in[16];
    const float* lnob   = (const float*)d_in[17];
    const float* Wq     = (const float*)d_in[18];
    const float* Wk     = (const float*)d_in[19];
    const float* vw     = (const float*)d_in[20];
    const float* Wv     = (const float*)d_in[21];
    const float* outw   = (const float*)d_in[22];
    const float* outb   = (const float*)d_in[23];
    float* out = (float*)d_out;

    cudaFuncSetAttribute(attn_kernel, cudaFuncAttributeMaxDynamicSharedMemorySize, 98304);
    cudaFuncSetAttribute(conv2_kernel, cudaFuncAttributeMaxDynamicSharedMemorySize, 68160);

    prep_kernel<<<128, 256>>>(gamma1, gamma2);
    conv1_kernel<<<dim3(64,4,2), 256>>>(x_p, conv1w, conv1b);
    gdn_kernel<<<1024, 256>>>(1, beta1);
    conv2_kernel<<<dim3(64,8,2), 128, 68160>>>(conv2w, conv2b);
    gdn_kernel<<<256, 256>>>(2, beta2);
    conv3_kernel<<<dim3(64,12,2), 128>>>(conv3w, conv3b);
    kv_kernel<<<dim3(64,5), 256>>>(y_g, lnkw, lnkb, Wk, Wv);
    attn_kernel<<<512, 256, 95872>>>(lnqw, lnqb, Wq, vw, outw, outb, lnow, lnob, out);
}

// round 7
// speedup vs baseline: 1.2824x; 1.2824x over previous
#include <cuda_runtime.h>

#define LN_EPS 1e-5f
typedef unsigned long long ull;

// ---- scratch ----
__device__ float g_s1[64*128*1024];
__device__ float g_s2[64*128*256];
__device__ float g_y3[64*192*256];
__device__ float g_kp[64*32*128];
__device__ float g_vp[64*32*192];
__device__ float g_gT[2][16384];

__device__ __forceinline__ float tanh_fast(float x){
    float y; asm("tanh.approx.f32 %0, %1;" : "=f"(y) : "f"(x)); return y;
}
__device__ __forceinline__ ull pk2(float lo, float hi){
    ull r; asm("mov.b64 %0, {%1, %2};" : "=l"(r) : "f"(lo), "f"(hi)); return r;
}
__device__ __forceinline__ ull pkdup(float v){ return pk2(v, v); }
__device__ __forceinline__ void upk2(ull p, float& lo, float& hi){
    asm("mov.b64 {%0, %1}, %2;" : "=f"(lo), "=f"(hi) : "l"(p));
}
__device__ __forceinline__ ull ffma2(ull a, ull b, ull c){
    ull d; asm("fma.rn.f32x2 %0, %1, %2, %3;" : "=l"(d) : "l"(a), "l"(b), "l"(c)); return d;
}

// ---- prep: transpose gammas ----
__global__ void prep_kernel(const float* __restrict__ g1, const float* __restrict__ g2){
    int bwhich = blockIdx.x >> 6;
    int e = ((blockIdx.x & 63) << 8) + threadIdx.x;
    const float* g = bwhich ? g2 : g1;
    int d = e >> 7, c = e & 127;
    g_gT[bwhich][c*128 + d] = g[e];
}

// ---- conv1: 3->128, 5x5, s2, p2 (64x64 -> 32x32). grid (64,4,2), 256 thr ----
__global__ void conv1_kernel(const float* __restrict__ x, const float* __restrict__ w,
                             const float* __restrict__ b){
    __shared__ float sw[4800];
    __shared__ float sin_[3885];
    int bp = blockIdx.x, tile = blockIdx.y, z = blockIdx.z;
    int t = threadIdx.x;
    for (int e = t; e < 4800; e += 256) sw[e] = w[z*4800 + e];
    int ty0 = (tile>>1)*16, tx0 = (tile&1)*16;
    int iy0 = 2*ty0 - 2, ix0 = 2*tx0 - 2;
    const float* xb = x + bp*12288;
    for (int e = t; e < 3675; e += 256){
        int c = e/1225, rem = e - c*1225, r = rem/35, col = rem - r*35;
        int gy = iy0 + r, gx = ix0 + col;
        float v = 0.f;
        if (gy>=0 && gy<64 && gx>=0 && gx<64) v = xb[c*4096 + gy*64 + gx];
        sin_[(c*35 + r)*37 + col] = v;
    }
    __syncthreads();
    int px4 = t & 63, cog = t >> 6;
    int ly = px4 >> 2, lx0 = (px4 & 3)*4;
    float* ob = g_s1 + bp*131072;
    for (int p = 0; p < 2; p++){
        int col0 = cog*16 + p*8;
        float acc[8][4];
        #pragma unroll
        for (int i = 0; i < 8; i++){
            float bb = b[z*64 + col0 + i];
            #pragma unroll
            for (int j = 0; j < 4; j++) acc[i][j] = bb;
        }
        #pragma unroll 1
        for (int c = 0; c < 3; c++){
            #pragma unroll
            for (int ky = 0; ky < 5; ky++){
                #pragma unroll
                for (int kx = 0; kx < 5; kx++){
                    float xv[4];
                    #pragma unroll
                    for (int j = 0; j < 4; j++)
                        xv[j] = sin_[(c*35 + 2*ly + ky)*37 + 2*lx0 + 2*j + kx];
                    #pragma unroll
                    for (int i = 0; i < 8; i++){
                        float wv = sw[(col0+i)*75 + c*25 + ky*5 + kx];
                        #pragma unroll
                        for (int j = 0; j < 4; j++) acc[i][j] = fmaf(wv, xv[j], acc[i][j]);
                    }
                }
            }
        }
        #pragma unroll
        for (int i = 0; i < 8; i++){
            float4 o = make_float4(acc[i][0], acc[i][1], acc[i][2], acc[i][3]);
            *reinterpret_cast<float4*>(ob + (z*64+col0+i)*1024 + (ty0+ly)*32 + tx0 + lx0) = o;
        }
    }
}

// ---- GDN in-place (f32x2). grid BP*HW/64, 256 thr ----
__global__ void gdn_kernel(int stage, const float* __restrict__ beta){
    __shared__ float sA[2048];
    __shared__ float sB[1088];
    int HW = (stage == 1) ? 1024 : 256;
    float* x = (stage == 1) ? g_s1 : g_s2;
    const float* gT = g_gT[stage-1];
    int chunks = HW >> 6;
    int bp = blockIdx.x / chunks;
    int p0 = (blockIdx.x - bp*chunks) * 64;
    int t = threadIdx.x;
    int i = t >> 4, j = t & 15;
    float* xb = x + bp*128*HW;
    ull acc[8][2];
    #pragma unroll
    for (int ii = 0; ii < 8; ii++){
        float bb = beta[i*8 + ii];
        acc[ii][0] = pkdup(bb); acc[ii][1] = pkdup(bb);
    }
    for (int c0 = 0; c0 < 128; c0 += 16){
        __syncthreads();
        for (int e = t; e < 2048; e += 256) sA[e] = gT[c0*128 + e];
        for (int e = t; e < 1024; e += 256){
            int cc = e >> 6, p = e & 63;
            float v = xb[(c0+cc)*HW + p0 + p];
            sB[cc*68 + p] = v*v;
        }
        __syncthreads();
        #pragma unroll
        for (int cc = 0; cc < 16; cc++){
            const ull* xp = reinterpret_cast<const ull*>(sB + cc*68 + j*4);
            ull x0 = xp[0], x1 = xp[1];
            float4 ga = *reinterpret_cast<const float4*>(sA + cc*128 + i*8);
            float4 gb = *reinterpret_cast<const float4*>(sA + cc*128 + i*8 + 4);
            float gs[8] = {ga.x,ga.y,ga.z,ga.w,gb.x,gb.y,gb.z,gb.w};
            #pragma unroll
            for (int ii = 0; ii < 8; ii++){
                ull wp = pkdup(gs[ii]);
                acc[ii][0] = ffma2(x0, wp, acc[ii][0]);
                acc[ii][1] = ffma2(x1, wp, acc[ii][1]);
            }
        }
    }
    #pragma unroll
    for (int ii = 0; ii < 8; ii++){
        int d = i*8 + ii;
        float a0,a1,a2,a3;
        upk2(acc[ii][0], a0, a1);
        upk2(acc[ii][1], a2, a3);
        float4 xv = *reinterpret_cast<const float4*>(xb + d*HW + p0 + j*4);
        float4 o;
        o.x = xv.x * rsqrtf(a0);
        o.y = xv.y * rsqrtf(a1);
        o.z = xv.z * rsqrtf(a2);
        o.w = xv.w * rsqrtf(a3);
        *reinterpret_cast<float4*>(xb + d*HW + p0 + j*4) = o;
    }
}

// ---- conv2: scalar x tile + dup-float2 weights. grid (64,8,2), 128 thr ----
__global__ void __launch_bounds__(128) conv2_kernel(const float* __restrict__ w,
                                                    const float* __restrict__ b){
    __shared__ float sin_[5624];    // 8ci x 19 x 37 (scalar, conflict-free)
    __shared__ float2 sW[3200];     // 16co x 200, duplicated
    int bp = blockIdx.x, co0 = blockIdx.y*16, ry0 = blockIdx.z*8;
    int t = threadIdx.x;
    int pxg = t & 31, cg = t >> 5;
    int ly = pxg >> 2, lx0 = (pxg & 3)*4;
    ull acc[4][2];
    #pragma unroll
    for (int i = 0; i < 4; i++){
        float bb = b[co0 + cg*4 + i];
        acc[i][0] = pkdup(bb); acc[i][1] = pkdup(bb);
    }
    const float* xb = g_s1 + bp*131072;
    int iy0 = 2*ry0 - 2;
    for (int ci0 = 0; ci0 < 128; ci0 += 8){
        __syncthreads();
        for (int e = t; e < 5320; e += 128){
            int ci = e/665, rem = e - ci*665, r = rem/35, col = rem - r*35;
            int gy = iy0 + r, gx = col - 2;
            float v = 0.f;
            if (gy>=0 && gy<32 && gx>=0 && gx<32) v = xb[(ci0+ci)*1024 + gy*32 + gx];
            sin_[(ci*19 + r)*37 + col] = v;
        }
        for (int e = t; e < 3200; e += 128){
            int i = e/200, rem = e - i*200;
            float v = w[(co0+i)*3200 + ci0*25 + rem];
            sW[e] = make_float2(v, v);
        }
        __syncthreads();
        #pragma unroll 1
        for (int ci = 0; ci < 8; ci++){
            #pragma unroll 1
            for (int ky = 0; ky < 5; ky++){
                const float* srow = sin_ + (ci*19 + 2*ly + ky)*37 + 2*lx0;
                const float2* wrow = sW + cg*800 + ci*25 + ky*5;
                #pragma unroll
                for (int kx = 0; kx < 5; kx++){
                    ull xp0 = pk2(srow[kx], srow[kx + 2]);
                    ull xp1 = pk2(srow[kx + 4], srow[kx + 6]);
                    #pragma unroll
                    for (int i = 0; i < 4; i++){
                        ull wp = *reinterpret_cast<const ull*>(wrow + i*200 + kx);
                        acc[i][0] = ffma2(xp0, wp, acc[i][0]);
                        acc[i][1] = ffma2(xp1, wp, acc[i][1]);
                    }
                }
            }
        }
    }
    float* ob = g_s2 + bp*32768;
    #pragma unroll
    for (int i = 0; i < 4; i++){
        float* orow = ob + (co0 + cg*4 + i)*256 + (ry0+ly)*16 + lx0;
        *reinterpret_cast<ull*>(orow)     = acc[i][0];
        *reinterpret_cast<ull*>(orow + 2) = acc[i][1];
    }
}

// ---- conv3: scalar x tile + dup-float2 weights. grid (64,12,2), 128 thr ----
__global__ void __launch_bounds__(128) conv3_kernel(const float* __restrict__ w,
                                                    const float* __restrict__ b){
    __shared__ float sin_[1680];    // 8ci x 10 x 21
    __shared__ float2 sW[1152];     // 16co x 72, duplicated
    int bp = blockIdx.x, co0 = blockIdx.y*16, ry0 = blockIdx.z*8;
    int t = threadIdx.x;
    int pxg = t & 31, cg = t >> 5;
    int ly = pxg >> 2, lx0 = (pxg & 3)*4;
    ull acc[4][2];
    #pragma unroll
    for (int i = 0; i < 4; i++){
        float bb = b[co0 + cg*4 + i];
        acc[i][0] = pkdup(bb); acc[i][1] = pkdup(bb);
    }
    const float* xb = g_s2 + bp*32768;
    int iy0 = ry0 - 1;
    for (int ci0 = 0; ci0 < 128; ci0 += 8){
        __syncthreads();
        for (int e = t; e < 1440; e += 128){
            int ci = e/180, rem = e - ci*180, r = rem/18, col = rem - r*18;
            int gy = iy0 + r, gx = col - 1;
            float v = 0.f;
            if (gy>=0 && gy<16 && gx>=0 && gx<16) v = xb[(ci0+ci)*256 + gy*16 + gx];
            sin_[(ci*10 + r)*21 + col] = v;
        }
        for (int e = t; e < 1152; e += 128){
            int i = e/72, rem = e - i*72;
            float v = w[(co0+i)*1152 + ci0*9 + rem];
            sW[e] = make_float2(v, v);
        }
        __syncthreads();
        #pragma unroll 1
        for (int ci = 0; ci < 8; ci++){
            #pragma unroll 1
            for (int ky = 0; ky < 3; ky++){
                const float* srow = sin_ + (ci*10 + ly + ky)*21 + lx0;
                const float2* wrow = sW + cg*288 + ci*9 + ky*3;
                #pragma unroll
                for (int kx = 0; kx < 3; kx++){
                    ull xp0 = pk2(srow[kx], srow[kx + 1]);
                    ull xp1 = pk2(srow[kx + 2], srow[kx + 3]);
                    #pragma unroll
                    for (int i = 0; i < 4; i++){
                        ull wp = *reinterpret_cast<const ull*>(wrow + i*72 + kx);
                        acc[i][0] = ffma2(xp0, wp, acc[i][0]);
                        acc[i][1] = ffma2(xp1, wp, acc[i][1]);
                    }
                }
            }
        }
    }
    float* ob = g_y3 + bp*49152;
    #pragma unroll
    for (int i = 0; i < 4; i++){
        float* orow = ob + (co0 + cg*4 + i)*256 + (ry0+ly)*16 + lx0;
        *reinterpret_cast<ull*>(orow)     = acc[i][0];
        *reinterpret_cast<ull*>(orow + 2) = acc[i][1];
    }
}

// ---- kv: LN + k_proj + v_proj. grid (64,5), 256 thr ----
__global__ void kv_kernel(const float* __restrict__ yg, const float* __restrict__ lnw,
                          const float* __restrict__ lnb, const float* __restrict__ Wk,
                          const float* __restrict__ Wv){
    __shared__ float s_kv[32*193];
    __shared__ float s_w[64*33];
    int bp = blockIdx.x;
    int r0 = blockIdx.y * 64;
    int t = threadIdx.x;
    int w = t >> 5, l = t & 31;
    for (int e = t; e < 6144; e += 256){
        int c = e >> 5, k = e & 31;
        s_kv[k*193 + c] = yg[bp*6144 + c*32 + k];
    }
    __syncthreads();
    {
        float lwv[6], lbv[6];
        #pragma unroll
        for (int i = 0; i < 6; i++){ lwv[i] = lnw[l+32*i]; lbv[i] = lnb[l+32*i]; }
        for (int ki = 0; ki < 4; ki++){
            int k = w*4 + ki;
            float v[6]; float s = 0.f;
            #pragma unroll
            for (int i = 0; i < 6; i++){ v[i] = s_kv[k*193 + l + 32*i]; s += v[i]; }
            #pragma unroll
            for (int o = 16; o > 0; o >>= 1) s += __shfl_xor_sync(0xffffffffu, s, o);
            float mu = s * (1.f/192.f);
            float vs = 0.f;
            #pragma unroll
            for (int i = 0; i < 6; i++){ float d = v[i]-mu; vs += d*d; }
            #pragma unroll
            for (int o = 16; o > 0; o >>= 1) vs += __shfl_xor_sync(0xffffffffu, vs, o);
            float rs = rsqrtf(vs * (1.f/192.f) + LN_EPS);
            #pragma unroll
            for (int i = 0; i < 6; i++)
                s_kv[k*193 + l + 32*i] = (v[i]-mu)*rs*lwv[i] + lbv[i];
        }
    }
    int kq = t & 7, rp = t >> 3;
    {
        float acc[2][4];
        #pragma unroll
        for (int i = 0; i < 2; i++)
            #pragma unroll
            for (int kk = 0; kk < 4; kk++) acc[i][kk] = 0.f;
        for (int c0 = 0; c0 < 192; c0 += 32){
            __syncthreads();
            for (int e = t; e < 2048; e += 256){
                int rr = e >> 5, cc = e & 31;
                int row = r0 + rr;
                s_w[rr*33 + cc] = (row < 128) ? Wk[row*192 + c0 + cc]
                                              : Wv[(row-128)*192 + c0 + cc];
            }
            __syncthreads();
            for (int cc = 0; cc < 32; cc++){
                float wv0 = s_w[(rp*2)*33 + cc], wv1 = s_w[(rp*2+1)*33 + cc];
                #pragma unroll
                for (int kk = 0; kk < 4; kk++){
                    float kvv = s_kv[(kq*4+kk)*193 + c0 + cc];
                    acc[0][kk] = fmaf(wv0, kvv, acc[0][kk]);
                    acc[1][kk] = fmaf(wv1, kvv, acc[1][kk]);
                }
            }
        }
        #pragma unroll
        for (int i = 0; i < 2; i++){
            int row = r0 + rp*2 + i;
            #pragma unroll
            for (int kk = 0; kk < 4; kk++){
                int k = kq*4 + kk;
                if (row < 128) g_kp[bp*4096 + k*128 + row] = acc[i][kk];
                else           g_vp[bp*6144 + k*192 + (row-128)] = acc[i][kk];
            }
        }
    }
}

// ---- attention: grid 512, 256 thr, 95872 B dyn smem ----
__global__ void attn_kernel(const float* __restrict__ lnqw, const float* __restrict__ lnqb,
                            const float* __restrict__ Wq, const float* __restrict__ vw,
                            const float* __restrict__ out_w, const float* __restrict__ out_b,
                            const float* __restrict__ lnow, const float* __restrict__ lnob,
                            float* __restrict__ out){
    extern __shared__ float sm[];
    float* s_qn  = sm;
    float* s_w   = sm + 6176;
    float* s_kp  = sm + 12512;
    float* s_e   = sm + 16736;
    float* s_ctx = sm + 17792;
    int bp = blockIdx.x >> 3;
    int q0 = (blockIdx.x & 7) << 5;
    int t = threadIdx.x;
    int w = t >> 5, l = t & 31;
    const float* y3 = g_y3 + bp*49152;
    for (int e = t; e < 6144; e += 256){
        int m = e >> 5, q = e & 31;
        s_qn[q*193 + m] = y3[m*256 + q0 + q];
    }
    for (int e = t; e < 4096; e += 256){
        int k = e >> 7;
        s_kp[k*132 + (e & 127)] = g_kp[bp*4096 + e];
    }
    __syncthreads();
    {
        float lwv[6], lbv[6];
        #pragma unroll
        for (int i = 0; i < 6; i++){ lwv[i] = lnqw[l+32*i]; lbv[i] = lnqb[l+32*i]; }
        for (int qi = 0; qi < 4; qi++){
            int q = w*4 + qi;
            float v[6]; float s = 0.f;
            #pragma unroll
            for (int i = 0; i < 6; i++){ v[i] = s_qn[q*193 + l + 32*i]; s += v[i]; }
            #pragma unroll
            for (int o = 16; o > 0; o >>= 1) s += __shfl_xor_sync(0xffffffffu, s, o);
            float mu = s * (1.f/192.f);
            float vs = 0.f;
            #pragma unroll
            for (int i = 0; i < 6; i++){ float d = v[i]-mu; vs += d*d; }
            #pragma unroll
            for (int o = 16; o > 0; o >>= 1) vs += __shfl_xor_sync(0xffffffffu, vs, o);
            float rs = rsqrtf(vs * (1.f/192.f) + LN_EPS);
            #pragma unroll
            for (int i = 0; i < 6; i++)
                s_qn[q*193 + l + 32*i] = (v[i]-mu)*rs*lwv[i] + lbv[i];
        }
    }
    float qp[4][4];
    #pragma unroll
    for (int a = 0; a < 4; a++)
        #pragma unroll
        for (int b2 = 0; b2 < 4; b2++) qp[a][b2] = 0.f;
    for (int c0 = 0; c0 < 192; c0 += 32){
        __syncthreads();
        for (int e = t; e < 4096; e += 256){
            int d = e >> 5, cc = e & 31;
            s_w[d*33 + cc] = Wq[d*192 + c0 + cc];
        }
        __syncthreads();
        for (int cc = 0; cc < 32; cc++){
            float wv[4], qv[4];
            #pragma unroll
            for (int j = 0; j < 4; j++) wv[j] = s_w[(l+32*j)*33 + cc];
            #pragma unroll
            for (int qi = 0; qi < 4; qi++) qv[qi] = s_qn[(w*4+qi)*193 + c0 + cc];
            #pragma unroll
            for (int qi = 0; qi < 4; qi++)
                #pragma unroll
                for (int j = 0; j < 4; j++) qp[qi][j] = fmaf(qv[qi], wv[j], qp[qi][j]);
        }
    }
    __syncthreads();
    float* s_vp = s_w;
    for (int e = t; e < 6144; e += 256){
        int k = e / 192, m = e - k*192;
        s_vp[k*193 + m] = g_vp[bp*6144 + e];
    }
    float vv[4];
    #pragma unroll
    for (int j = 0; j < 4; j++) vv[j] = vw[l + 32*j];
    for (int k = 0; k < 32; k++){
        float kp4[4];
        #pragma unroll
        for (int j = 0; j < 4; j++) kp4[j] = s_kp[k*132 + l + 32*j];
        #pragma unroll
        for (int qi = 0; qi < 4; qi++){
            float s = 0.f;
            #pragma unroll
            for (int j = 0; j < 4; j++)
                s = fmaf(tanh_fast(qp[qi][j] + kp4[j]), vv[j], s);
            #pragma unroll
            for (int o = 16; o > 0; o >>= 1) s += __shfl_xor_sync(0xffffffffu, s, o);
            if (l == 0) s_e[(w*4+qi)*33 + k] = s;
        }
    }
    __syncwarp();
    for (int qi = 0; qi < 4; qi++){
        int q = w*4 + qi;
        float ev = s_e[q*33 + l];
        float mx = ev;
        #pragma unroll
        for (int o = 16; o > 0; o >>= 1) mx = fmaxf(mx, __shfl_xor_sync(0xffffffffu, mx, o));
        float p = __expf(ev - mx);
        float s = p;
        #pragma unroll
        for (int o = 16; o > 0; o >>= 1) s += __shfl_xor_sync(0xffffffffu, s, o);
        s_e[q*33 + l] = p / s;
    }
    __syncthreads();
    {
        int qr = t >> 3, mg = t & 7;
        float acc[24];
        #pragma unroll
        for (int i = 0; i < 24; i++) acc[i] = 0.f;
        for (int k = 0; k < 32; k++){
            float a = s_e[qr*33 + k];
            #pragma unroll
            for (int i = 0; i < 24; i++)
                acc[i] = fmaf(a, s_vp[k*193 + mg + 8*i], acc[i]);
        }
        #pragma unroll
        for (int i = 0; i < 24; i++) s_ctx[qr*193 + mg + 8*i] = acc[i];
    }
    __syncthreads();
    {
        int qh = t >> 4, ng = t & 15;
        float acc0[12], acc1[12];
        #pragma unroll
        for (int i = 0; i < 12; i++){ acc0[i] = 0.f; acc1[i] = 0.f; }
        for (int m0 = 0; m0 < 192; m0 += 32){
            __syncthreads();
            for (int e = t; e < 6144; e += 256){
                int n = e >> 5, mm = e & 31;
                s_w[n*33 + mm] = out_w[n*192 + m0 + mm];
            }
            __syncthreads();
            for (int mm = 0; mm < 32; mm++){
                float c0v = s_ctx[(2*qh)*193 + m0 + mm];
                float c1v = s_ctx[(2*qh+1)*193 + m0 + mm];
                #pragma unroll
                for (int i = 0; i < 12; i++){
                    float wv = s_w[(ng+16*i)*33 + mm];
                    acc0[i] = fmaf(c0v, wv, acc0[i]);
                    acc1[i] = fmaf(c1v, wv, acc1[i]);
                }
            }
        }
        float val0[12], val1[12];
        float s0 = 0.f, s1 = 0.f;
        #pragma unroll
        for (int i = 0; i < 12; i++){
            int n = ng + 16*i;
            val0[i] = acc0[i] + out_b[n] + s_qn[(2*qh)*193 + n];
            val1[i] = acc1[i] + out_b[n] + s_qn[(2*qh+1)*193 + n];
            s0 += val0[i]; s1 += val1[i];
        }
        #pragma unroll
        for (int o = 8; o > 0; o >>= 1){
            s0 += __shfl_xor_sync(0xffffffffu, s0, o);
            s1 += __shfl_xor_sync(0xffffffffu, s1, o);
        }
        float mu0 = s0*(1.f/192.f), mu1 = s1*(1.f/192.f);
        float vs0 = 0.f, vs1 = 0.f;
        #pragma unroll
        for (int i = 0; i < 12; i++){
            float d0 = val0[i]-mu0, d1 = val1[i]-mu1;
            vs0 += d0*d0; vs1 += d1*d1;
        }
        #pragma unroll
        for (int o = 8; o > 0; o >>= 1){
            vs0 += __shfl_xor_sync(0xffffffffu, vs0, o);
            vs1 += __shfl_xor_sync(0xffffffffu, vs1, o);
        }
        float r0 = rsqrtf(vs0*(1.f/192.f) + LN_EPS);
        float r1 = rsqrtf(vs1*(1.f/192.f) + LN_EPS);
        __syncthreads();
        #pragma unroll
        for (int i = 0; i < 12; i++){
            int n = ng + 16*i;
            s_ctx[(2*qh)*193 + n]   = (val0[i]-mu0)*r0*lnow[n] + lnob[n];
            s_ctx[(2*qh+1)*193 + n] = (val1[i]-mu1)*r1*lnow[n] + lnob[n];
        }
    }
    __syncthreads();
    for (int e = t; e < 6144; e += 256){
        int n = e >> 5, q = e & 31;
        out[bp*49152 + n*256 + q0 + q] = s_ctx[q*193 + n];
    }
}

extern "C" void kernel_launch(void* const* d_in, const int* in_sizes, int n_in,
                              void* d_out, int out_size){
    const float* x_p    = (const float*)d_in[0];
    const float* y_g    = (const float*)d_in[1];
    const float* conv1w = (const float*)d_in[2];
    const float* conv1b = (const float*)d_in[3];
    const float* gamma1 = (const float*)d_in[4];
    const float* beta1  = (const float*)d_in[5];
    const float* conv2w = (const float*)d_in[6];
    const float* conv2b = (const float*)d_in[7];
    const float* gamma2 = (const float*)d_in[8];
    const float* beta2  = (const float*)d_in[9];
    const float* conv3w = (const float*)d_in[10];
    const float* conv3b = (const float*)d_in[11];
    const float* lnqw   = (const float*)d_in[12];
    const float* lnqb   = (const float*)d_in[13];
    const float* lnkw   = (const float*)d_in[14];
    const float* lnkb   = (const float*)d_in[15];
    const float* lnow   = (const float*)d_in[16];
    const float* lnob   = (const float*)d_in[17];
    const float* Wq     = (const float*)d_in[18];
    const float* Wk     = (const float*)d_in[19];
    const float* vw     = (const float*)d_in[20];
    const float* Wv     = (const float*)d_in[21];
    const float* outw   = (const float*)d_in[22];
    const float* outb   = (const float*)d_in[23];
    float* out = (float*)d_out;

    cudaFuncSetAttribute(attn_kernel, cudaFuncAttributeMaxDynamicSharedMemorySize, 98304);

    prep_kernel<<<128, 256>>>(gamma1, gamma2);
    conv1_kernel<<<dim3(64,4,2), 256>>>(x_p, conv1w, conv1b);
    gdn_kernel<<<1024, 256>>>(1, beta1);
    conv2_kernel<<<dim3(64,8,2), 128>>>(conv2w, conv2b);
    gdn_kernel<<<256, 256>>>(2, beta2);
    conv3_kernel<<<dim3(64,12,2), 128>>>(conv3w, conv3b);
    kv_kernel<<<dim3(64,5), 256>>>(y_g, lnkw, lnkb, Wk, Wv);
    attn_kernel<<<512, 256, 95872>>>(lnqw, lnqb, Wq, vw, outw, outb, lnow, lnob, out);
}

// round 8
// speedup vs baseline: 1.4129x; 1.1018x over previous
#include <cuda_runtime.h>

#define LN_EPS 1e-5f
typedef unsigned long long ull;

// ---- scratch ----
__device__ float g_s1[64*128*1024];
__device__ float g_s2[64*128*256];
__device__ float g_y3[64*192*256];
__device__ float g_kp[64*32*128];
__device__ float g_vp[64*32*192];
__device__ float g_gT[2][16384];
__device__ float g_xcol[64*3200*256];   // conv2 im2col

__device__ __forceinline__ float tanh_fast(float x){
    float y; asm("tanh.approx.f32 %0, %1;" : "=f"(y) : "f"(x)); return y;
}
__device__ __forceinline__ ull pk2(float lo, float hi){
    ull r; asm("mov.b64 %0, {%1, %2};" : "=l"(r) : "f"(lo), "f"(hi)); return r;
}
__device__ __forceinline__ ull pkdup(float v){ return pk2(v, v); }
__device__ __forceinline__ void upk2(ull p, float& lo, float& hi){
    asm("mov.b64 {%0, %1}, %2;" : "=f"(lo), "=f"(hi) : "l"(p));
}
__device__ __forceinline__ ull ffma2(ull a, ull b, ull c){
    ull d; asm("fma.rn.f32x2 %0, %1, %2, %3;" : "=l"(d) : "l"(a), "l"(b), "l"(c)); return d;
}
__device__ __forceinline__ unsigned f2tf(float f){
    unsigned t; asm("cvt.rna.tf32.f32 %0, %1;" : "=r"(t) : "f"(f)); return t;
}

// ---- prep: transpose gammas ----
__global__ void prep_kernel(const float* __restrict__ g1, const float* __restrict__ g2){
    int bwhich = blockIdx.x >> 6;
    int e = ((blockIdx.x & 63) << 8) + threadIdx.x;
    const float* g = bwhich ? g2 : g1;
    int d = e >> 7, c = e & 127;
    g_gT[bwhich][c*128 + d] = g[e];
}

// ---- conv1: 3->128, 5x5, s2, p2 (64x64 -> 32x32). grid (64,4,2), 256 thr ----
__global__ void conv1_kernel(const float* __restrict__ x, const float* __restrict__ w,
                             const float* __restrict__ b){
    __shared__ float sw[4800];
    __shared__ float sin_[3885];
    int bp = blockIdx.x, tile = blockIdx.y, z = blockIdx.z;
    int t = threadIdx.x;
    for (int e = t; e < 4800; e += 256) sw[e] = w[z*4800 + e];
    int ty0 = (tile>>1)*16, tx0 = (tile&1)*16;
    int iy0 = 2*ty0 - 2, ix0 = 2*tx0 - 2;
    const float* xb = x + bp*12288;
    for (int e = t; e < 3675; e += 256){
        int c = e/1225, rem = e - c*1225, r = rem/35, col = rem - r*35;
        int gy = iy0 + r, gx = ix0 + col;
        float v = 0.f;
        if (gy>=0 && gy<64 && gx>=0 && gx<64) v = xb[c*4096 + gy*64 + gx];
        sin_[(c*35 + r)*37 + col] = v;
    }
    __syncthreads();
    int px4 = t & 63, cog = t >> 6;
    int ly = px4 >> 2, lx0 = (px4 & 3)*4;
    float* ob = g_s1 + bp*131072;
    for (int p = 0; p < 2; p++){
        int col0 = cog*16 + p*8;
        float acc[8][4];
        #pragma unroll
        for (int i = 0; i < 8; i++){
            float bb = b[z*64 + col0 + i];
            #pragma unroll
            for (int j = 0; j < 4; j++) acc[i][j] = bb;
        }
        #pragma unroll 1
        for (int c = 0; c < 3; c++){
            #pragma unroll
            for (int ky = 0; ky < 5; ky++){
                #pragma unroll
                for (int kx = 0; kx < 5; kx++){
                    float xv[4];
                    #pragma unroll
                    for (int j = 0; j < 4; j++)
                        xv[j] = sin_[(c*35 + 2*ly + ky)*37 + 2*lx0 + 2*j + kx];
                    #pragma unroll
                    for (int i = 0; i < 8; i++){
                        float wv = sw[(col0+i)*75 + c*25 + ky*5 + kx];
                        #pragma unroll
                        for (int j = 0; j < 4; j++) acc[i][j] = fmaf(wv, xv[j], acc[i][j]);
                    }
                }
            }
        }
        #pragma unroll
        for (int i = 0; i < 8; i++){
            float4 o = make_float4(acc[i][0], acc[i][1], acc[i][2], acc[i][3]);
            *reinterpret_cast<float4*>(ob + (z*64+col0+i)*1024 + (ty0+ly)*32 + tx0 + lx0) = o;
        }
    }
}

// ---- GDN in-place (f32x2). grid BP*HW/64, 256 thr ----
__global__ void gdn_kernel(int stage, const float* __restrict__ beta){
    __shared__ float sA[2048];
    __shared__ float sB[1088];
    int HW = (stage == 1) ? 1024 : 256;
    float* x = (stage == 1) ? g_s1 : g_s2;
    const float* gT = g_gT[stage-1];
    int chunks = HW >> 6;
    int bp = blockIdx.x / chunks;
    int p0 = (blockIdx.x - bp*chunks) * 64;
    int t = threadIdx.x;
    int i = t >> 4, j = t & 15;
    float* xb = x + bp*128*HW;
    ull acc[8][2];
    #pragma unroll
    for (int ii = 0; ii < 8; ii++){
        float bb = beta[i*8 + ii];
        acc[ii][0] = pkdup(bb); acc[ii][1] = pkdup(bb);
    }
    for (int c0 = 0; c0 < 128; c0 += 16){
        __syncthreads();
        for (int e = t; e < 2048; e += 256) sA[e] = gT[c0*128 + e];
        for (int e = t; e < 1024; e += 256){
            int cc = e >> 6, p = e & 63;
            float v = xb[(c0+cc)*HW + p0 + p];
            sB[cc*68 + p] = v*v;
        }
        __syncthreads();
        #pragma unroll
        for (int cc = 0; cc < 16; cc++){
            const ull* xp = reinterpret_cast<const ull*>(sB + cc*68 + j*4);
            ull x0 = xp[0], x1 = xp[1];
            float4 ga = *reinterpret_cast<const float4*>(sA + cc*128 + i*8);
            float4 gb = *reinterpret_cast<const float4*>(sA + cc*128 + i*8 + 4);
            float gs[8] = {ga.x,ga.y,ga.z,ga.w,gb.x,gb.y,gb.z,gb.w};
            #pragma unroll
            for (int ii = 0; ii < 8; ii++){
                ull wp = pkdup(gs[ii]);
                acc[ii][0] = ffma2(x0, wp, acc[ii][0]);
                acc[ii][1] = ffma2(x1, wp, acc[ii][1]);
            }
        }
    }
    #pragma unroll
    for (int ii = 0; ii < 8; ii++){
        int d = i*8 + ii;
        float a0,a1,a2,a3;
        upk2(acc[ii][0], a0, a1);
        upk2(acc[ii][1], a2, a3);
        float4 xv = *reinterpret_cast<const float4*>(xb + d*HW + p0 + j*4);
        float4 o;
        o.x = xv.x * rsqrtf(a0);
        o.y = xv.y * rsqrtf(a1);
        o.z = xv.z * rsqrtf(a2);
        o.w = xv.w * rsqrtf(a3);
        *reinterpret_cast<float4*>(xb + d*HW + p0 + j*4) = o;
    }
}

// ---- conv2 im2col: grid (800, 64), 256 thr ----
__global__ void im2col2_kernel(){
    int bp = blockIdx.y;
    int t = threadIdx.x;
    int oy = t >> 4, ox = t & 15;
    const float* xb = g_s1 + bp*131072;
    float* xc = g_xcol + bp*819200;
    #pragma unroll 1
    for (int kk = 0; kk < 4; kk++){
        int k = blockIdx.x*4 + kk;
        int ci = k / 25, r = k - ci*25;
        int ky = r / 5, kx = r - ky*5;
        int iy = 2*oy - 2 + ky, ix = 2*ox - 2 + kx;
        float v = 0.f;
        if (iy>=0 && iy<32 && ix>=0 && ix<32) v = xb[ci*1024 + iy*32 + ix];
        xc[k*256 + t] = v;
    }
}

// ---- conv2 GEMM (tf32 mma): C[128,256] = W[128,3200] @ Xcol. grid (64,4), 256 thr ----
__global__ void __launch_bounds__(256) conv2gemm_kernel(const float* __restrict__ w,
                                                        const float* __restrict__ bias){
    __shared__ unsigned sW[128*36];   // stride 36 -> bank 4g+tig (conflict-free)
    __shared__ unsigned sX[32*72];    // stride 72 -> bank 8tig+g (conflict-free)
    int bp = blockIdx.x, n0b = blockIdx.y * 64;
    int t = threadIdx.x;
    int warp = t >> 5, lane = t & 31;
    int g = lane >> 2, tig = lane & 3;
    int m0 = (warp >> 1) * 32;
    int n0 = (warp & 1) * 32;
    float c[2][4][4];
    #pragma unroll
    for (int mt = 0; mt < 2; mt++)
        #pragma unroll
        for (int nt = 0; nt < 4; nt++)
            #pragma unroll
            for (int q = 0; q < 4; q++) c[mt][nt][q] = 0.f;
    const float* xcb = g_xcol + bp*819200 + n0b;
    for (int kc = 0; kc < 3200; kc += 32){
        __syncthreads();
        for (int e = t; e < 4096; e += 256){
            int co = e >> 5, kk = e & 31;
            sW[co*36 + kk] = f2tf(w[co*3200 + kc + kk]);
        }
        for (int e = t; e < 2048; e += 256){
            int kk = e >> 6, px = e & 63;
            sX[kk*72 + px] = f2tf(xcb[(kc + kk)*256 + px]);
        }
        __syncthreads();
        #pragma unroll
        for (int ks = 0; ks < 4; ks++){
            int k0 = ks*8;
            unsigned a[2][4], bb[4][2];
            #pragma unroll
            for (int mt = 0; mt < 2; mt++){
                int m = m0 + mt*16;
                a[mt][0] = sW[(m+g)*36 + k0 + tig];
                a[mt][1] = sW[(m+g+8)*36 + k0 + tig];
                a[mt][2] = sW[(m+g)*36 + k0 + tig + 4];
                a[mt][3] = sW[(m+g+8)*36 + k0 + tig + 4];
            }
            #pragma unroll
            for (int nt = 0; nt < 4; nt++){
                int n = n0 + nt*8;
                bb[nt][0] = sX[(k0+tig)*72 + n + g];
                bb[nt][1] = sX[(k0+tig+4)*72 + n + g];
            }
            #pragma unroll
            for (int mt = 0; mt < 2; mt++)
                #pragma unroll
                for (int nt = 0; nt < 4; nt++)
                    asm volatile(
                        "mma.sync.aligned.m16n8k8.row.col.f32.tf32.tf32.f32 "
                        "{%0,%1,%2,%3}, {%4,%5,%6,%7}, {%8,%9}, {%0,%1,%2,%3};"
                        : "+f"(c[mt][nt][0]), "+f"(c[mt][nt][1]),
                          "+f"(c[mt][nt][2]), "+f"(c[mt][nt][3])
                        : "r"(a[mt][0]), "r"(a[mt][1]), "r"(a[mt][2]), "r"(a[mt][3]),
                          "r"(bb[nt][0]), "r"(bb[nt][1]));
        }
    }
    float* ob = g_s2 + bp*32768;
    #pragma unroll
    for (int mt = 0; mt < 2; mt++){
        int coA = m0 + mt*16 + g;
        int coB = coA + 8;
        float bA = bias[coA], bB = bias[coB];
        #pragma unroll
        for (int nt = 0; nt < 4; nt++){
            int px = n0b + n0 + nt*8 + 2*tig;
            *reinterpret_cast<float2*>(ob + coA*256 + px) =
                make_float2(c[mt][nt][0] + bA, c[mt][nt][1] + bA);
            *reinterpret_cast<float2*>(ob + coB*256 + px) =
                make_float2(c[mt][nt][2] + bB, c[mt][nt][3] + bB);
        }
    }
}

// ---- conv3: scalar x tile + pkdup weights (R5). grid (64,12,2), 128 thr ----
__global__ void __launch_bounds__(128) conv3_kernel(const float* __restrict__ w,
                                                    const float* __restrict__ b){
    __shared__ float sin_[2100];
    __shared__ float sw[1152];
    int bp = blockIdx.x, co0 = blockIdx.y*16, ry0 = blockIdx.z*8;
    int t = threadIdx.x;
    int pxg = t & 31, cg = t >> 5;
    int ly = pxg >> 2, lx0 = (pxg & 3)*4;
    ull acc[4][2];
    #pragma unroll
    for (int i = 0; i < 4; i++){
        float bb = b[co0 + cg*4 + i];
        acc[i][0] = pkdup(bb); acc[i][1] = pkdup(bb);
    }
    const float* xb = g_s2 + bp*32768;
    int iy0 = ry0 - 1;
    for (int ci0 = 0; ci0 < 128; ci0 += 8){
        __syncthreads();
        for (int e = t; e < 1440; e += 128){
            int ci = e/180, rem = e - ci*180, r = rem/18, col = rem - r*18;
            int gy = iy0 + r, gx = col - 1;
            float v = 0.f;
            if (gy>=0 && gy<16 && gx>=0 && gx<16) v = xb[(ci0+ci)*256 + gy*16 + gx];
            sin_[(ci*10 + r)*21 + col] = v;
        }
        for (int e = t; e < 1152; e += 128){
            int i = e/72, rem = e - i*72;
            sw[e] = w[(co0+i)*1152 + ci0*9 + rem];
        }
        __syncthreads();
        #pragma unroll 1
        for (int ci = 0; ci < 8; ci++){
            #pragma unroll 1
            for (int ky = 0; ky < 3; ky++){
                const float* srow = sin_ + (ci*10 + ly + ky)*21 + lx0;
                const float* wrow = sw + cg*288 + ci*9 + ky*3;
                #pragma unroll
                for (int kx = 0; kx < 3; kx++){
                    ull xp0 = pk2(srow[kx], srow[kx + 1]);
                    ull xp1 = pk2(srow[kx + 2], srow[kx + 3]);
                    #pragma unroll
                    for (int i = 0; i < 4; i++){
                        ull wp = pkdup(wrow[i*72 + kx]);
                        acc[i][0] = ffma2(xp0, wp, acc[i][0]);
                        acc[i][1] = ffma2(xp1, wp, acc[i][1]);
                    }
                }
            }
        }
    }
    float* ob = g_y3 + bp*49152;
    #pragma unroll
    for (int i = 0; i < 4; i++){
        float* orow = ob + (co0 + cg*4 + i)*256 + (ry0+ly)*16 + lx0;
        *reinterpret_cast<ull*>(orow)     = acc[i][0];
        *reinterpret_cast<ull*>(orow + 2) = acc[i][1];
    }
}

// ---- kv: LN + k_proj + v_proj. grid (64,5), 256 thr ----
__global__ void kv_kernel(const float* __restrict__ yg, const float* __restrict__ lnw,
                          const float* __restrict__ lnb, const float* __restrict__ Wk,
                          const float* __restrict__ Wv){
    __shared__ float s_kv[32*193];
    __shared__ float s_w[64*33];
    int bp = blockIdx.x;
    int r0 = blockIdx.y * 64;
    int t = threadIdx.x;
    int w = t >> 5, l = t & 31;
    for (int e = t; e < 6144; e += 256){
        int c = e >> 5, k = e & 31;
        s_kv[k*193 + c] = yg[bp*6144 + c*32 + k];
    }
    __syncthreads();
    {
        float lwv[6], lbv[6];
        #pragma unroll
        for (int i = 0; i < 6; i++){ lwv[i] = lnw[l+32*i]; lbv[i] = lnb[l+32*i]; }
        for (int ki = 0; ki < 4; ki++){
            int k = w*4 + ki;
            float v[6]; float s = 0.f;
            #pragma unroll
            for (int i = 0; i < 6; i++){ v[i] = s_kv[k*193 + l + 32*i]; s += v[i]; }
            #pragma unroll
            for (int o = 16; o > 0; o >>= 1) s += __shfl_xor_sync(0xffffffffu, s, o);
            float mu = s * (1.f/192.f);
            float vs = 0.f;
            #pragma unroll
            for (int i = 0; i < 6; i++){ float d = v[i]-mu; vs += d*d; }
            #pragma unroll
            for (int o = 16; o > 0; o >>= 1) vs += __shfl_xor_sync(0xffffffffu, vs, o);
            float rs = rsqrtf(vs * (1.f/192.f) + LN_EPS);
            #pragma unroll
            for (int i = 0; i < 6; i++)
                s_kv[k*193 + l + 32*i] = (v[i]-mu)*rs*lwv[i] + lbv[i];
        }
    }
    int kq = t & 7, rp = t >> 3;
    {
        float acc[2][4];
        #pragma unroll
        for (int i = 0; i < 2; i++)
            #pragma unroll
            for (int kk = 0; kk < 4; kk++) acc[i][kk] = 0.f;
        for (int c0 = 0; c0 < 192; c0 += 32){
            __syncthreads();
            for (int e = t; e < 2048; e += 256){
                int rr = e >> 5, cc = e & 31;
                int row = r0 + rr;
                s_w[rr*33 + cc] = (row < 128) ? Wk[row*192 + c0 + cc]
                                              : Wv[(row-128)*192 + c0 + cc];
            }
            __syncthreads();
            for (int cc = 0; cc < 32; cc++){
                float wv0 = s_w[(rp*2)*33 + cc], wv1 = s_w[(rp*2+1)*33 + cc];
                #pragma unroll
                for (int kk = 0; kk < 4; kk++){
                    float kvv = s_kv[(kq*4+kk)*193 + c0 + cc];
                    acc[0][kk] = fmaf(wv0, kvv, acc[0][kk]);
                    acc[1][kk] = fmaf(wv1, kvv, acc[1][kk]);
                }
            }
        }
        #pragma unroll
        for (int i = 0; i < 2; i++){
            int row = r0 + rp*2 + i;
            #pragma unroll
            for (int kk = 0; kk < 4; kk++){
                int k = kq*4 + kk;
                if (row < 128) g_kp[bp*4096 + k*128 + row] = acc[i][kk];
                else           g_vp[bp*6144 + k*192 + (row-128)] = acc[i][kk];
            }
        }
    }
}

// ---- attention: grid 512, 256 thr, 95872 B dyn smem ----
__global__ void attn_kernel(const float* __restrict__ lnqw, const float* __restrict__ lnqb,
                            const float* __restrict__ Wq, const float* __restrict__ vw,
                            const float* __restrict__ out_w, const float* __restrict__ out_b,
                            const float* __restrict__ lnow, const float* __restrict__ lnob,
                            float* __restrict__ out){
    extern __shared__ float sm[];
    float* s_qn  = sm;
    float* s_w   = sm + 6176;
    float* s_kp  = sm + 12512;
    float* s_e   = sm + 16736;
    float* s_ctx = sm + 17792;
    int bp = blockIdx.x >> 3;
    int q0 = (blockIdx.x & 7) << 5;
    int t = threadIdx.x;
    int w = t >> 5, l = t & 31;
    const float* y3 = g_y3 + bp*49152;
    for (int e = t; e < 6144; e += 256){
        int m = e >> 5, q = e & 31;
        s_qn[q*193 + m] = y3[m*256 + q0 + q];
    }
    for (int e = t; e < 4096; e += 256){
        int k = e >> 7;
        s_kp[k*132 + (e & 127)] = g_kp[bp*4096 + e];
    }
    __syncthreads();
    {
        float lwv[6], lbv[6];
        #pragma unroll
        for (int i = 0; i < 6; i++){ lwv[i] = lnqw[l+32*i]; lbv[i] = lnqb[l+32*i]; }
        for (int qi = 0; qi < 4; qi++){
            int q = w*4 + qi;
            float v[6]; float s = 0.f;
            #pragma unroll
            for (int i = 0; i < 6; i++){ v[i] = s_qn[q*193 + l + 32*i]; s += v[i]; }
            #pragma unroll
            for (int o = 16; o > 0; o >>= 1) s += __shfl_xor_sync(0xffffffffu, s, o);
            float mu = s * (1.f/192.f);
            float vs = 0.f;
            #pragma unroll
            for (int i = 0; i < 6; i++){ float d = v[i]-mu; vs += d*d; }
            #pragma unroll
            for (int o = 16; o > 0; o >>= 1) vs += __shfl_xor_sync(0xffffffffu, vs, o);
            float rs = rsqrtf(vs * (1.f/192.f) + LN_EPS);
            #pragma unroll
            for (int i = 0; i < 6; i++)
                s_qn[q*193 + l + 32*i] = (v[i]-mu)*rs*lwv[i] + lbv[i];
        }
    }
    float qp[4][4];
    #pragma unroll
    for (int a = 0; a < 4; a++)
        #pragma unroll
        for (int b2 = 0; b2 < 4; b2++) qp[a][b2] = 0.f;
    for (int c0 = 0; c0 < 192; c0 += 32){
        __syncthreads();
        for (int e = t; e < 4096; e += 256){
            int d = e >> 5, cc = e & 31;
            s_w[d*33 + cc] = Wq[d*192 + c0 + cc];
        }
        __syncthreads();
        for (int cc = 0; cc < 32; cc++){
            float wv[4], qv[4];
            #pragma unroll
            for (int j = 0; j < 4; j++) wv[j] = s_w[(l+32*j)*33 + cc];
            #pragma unroll
            for (int qi = 0; qi < 4; qi++) qv[qi] = s_qn[(w*4+qi)*193 + c0 + cc];
            #pragma unroll
            for (int qi = 0; qi < 4; qi++)
                #pragma unroll
                for (int j = 0; j < 4; j++) qp[qi][j] = fmaf(qv[qi], wv[j], qp[qi][j]);
        }
    }
    __syncthreads();
    float* s_vp = s_w;
    for (int e = t; e < 6144; e += 256){
        int k = e / 192, m = e - k*192;
        s_vp[k*193 + m] = g_vp[bp*6144 + e];
    }
    float vv[4];
    #pragma unroll
    for (int j = 0; j < 4; j++) vv[j] = vw[l + 32*j];
    for (int k = 0; k < 32; k++){
        float kp4[4];
        #pragma unroll
        for (int j = 0; j < 4; j++) kp4[j] = s_kp[k*132 + l + 32*j];
        #pragma unroll
        for (int qi = 0; qi < 4; qi++){
            float s = 0.f;
            #pragma unroll
            for (int j = 0; j < 4; j++)
                s = fmaf(tanh_fast(qp[qi][j] + kp4[j]), vv[j], s);
            #pragma unroll
            for (int o = 16; o > 0; o >>= 1) s += __shfl_xor_sync(0xffffffffu, s, o);
            if (l == 0) s_e[(w*4+qi)*33 + k] = s;
        }
    }
    __syncwarp();
    for (int qi = 0; qi < 4; qi++){
        int q = w*4 + qi;
        float ev = s_e[q*33 + l];
        float mx = ev;
        #pragma unroll
        for (int o = 16; o > 0; o >>= 1) mx = fmaxf(mx, __shfl_xor_sync(0xffffffffu, mx, o));
        float p = __expf(ev - mx);
        float s = p;
        #pragma unroll
        for (int o = 16; o > 0; o >>= 1) s += __shfl_xor_sync(0xffffffffu, s, o);
        s_e[q*33 + l] = p / s;
    }
    __syncthreads();
    {
        int qr = t >> 3, mg = t & 7;
        float acc[24];
        #pragma unroll
        for (int i = 0; i < 24; i++) acc[i] = 0.f;
        for (int k = 0; k < 32; k++){
            float a = s_e[qr*33 + k];
            #pragma unroll
            for (int i = 0; i < 24; i++)
                acc[i] = fmaf(a, s_vp[k*193 + mg + 8*i], acc[i]);
        }
        #pragma unroll
        for (int i = 0; i < 24; i++) s_ctx[qr*193 + mg + 8*i] = acc[i];
    }
    __syncthreads();
    {
        int qh = t >> 4, ng = t & 15;
        float acc0[12], acc1[12];
        #pragma unroll
        for (int i = 0; i < 12; i++){ acc0[i] = 0.f; acc1[i] = 0.f; }
        for (int m0 = 0; m0 < 192; m0 += 32){
            __syncthreads();
            for (int e = t; e < 6144; e += 256){
                int n = e >> 5, mm = e & 31;
                s_w[n*33 + mm] = out_w[n*192 + m0 + mm];
            }
            __syncthreads();
            for (int mm = 0; mm < 32; mm++){
                float c0v = s_ctx[(2*qh)*193 + m0 + mm];
                float c1v = s_ctx[(2*qh+1)*193 + m0 + mm];
                #pragma unroll
                for (int i = 0; i < 12; i++){
                    float wv = s_w[(ng+16*i)*33 + mm];
                    acc0[i] = fmaf(c0v, wv, acc0[i]);
                    acc1[i] = fmaf(c1v, wv, acc1[i]);
                }
            }
        }
        float val0[12], val1[12];
        float s0 = 0.f, s1 = 0.f;
        #pragma unroll
        for (int i = 0; i < 12; i++){
            int n = ng + 16*i;
            val0[i] = acc0[i] + out_b[n] + s_qn[(2*qh)*193 + n];
            val1[i] = acc1[i] + out_b[n] + s_qn[(2*qh+1)*193 + n];
            s0 += val0[i]; s1 += val1[i];
        }
        #pragma unroll
        for (int o = 8; o > 0; o >>= 1){
            s0 += __shfl_xor_sync(0xffffffffu, s0, o);
            s1 += __shfl_xor_sync(0xffffffffu, s1, o);
        }
        float mu0 = s0*(1.f/192.f), mu1 = s1*(1.f/192.f);
        float vs0 = 0.f, vs1 = 0.f;
        #pragma unroll
        for (int i = 0; i < 12; i++){
            float d0 = val0[i]-mu0, d1 = val1[i]-mu1;
            vs0 += d0*d0; vs1 += d1*d1;
        }
        #pragma unroll
        for (int o = 8; o > 0; o >>= 1){
            vs0 += __shfl_xor_sync(0xffffffffu, vs0, o);
            vs1 += __shfl_xor_sync(0xffffffffu, vs1, o);
        }
        float r0 = rsqrtf(vs0*(1.f/192.f) + LN_EPS);
        float r1 = rsqrtf(vs1*(1.f/192.f) + LN_EPS);
        __syncthreads();
        #pragma unroll
        for (int i = 0; i < 12; i++){
            int n = ng + 16*i;
            s_ctx[(2*qh)*193 + n]   = (val0[i]-mu0)*r0*lnow[n] + lnob[n];
            s_ctx[(2*qh+1)*193 + n] = (val1[i]-mu1)*r1*lnow[n] + lnob[n];
        }
    }
    __syncthreads();
    for (int e = t; e < 6144; e += 256){
        int n = e >> 5, q = e & 31;
        out[bp*49152 + n*256 + q0 + q] = s_ctx[q*193 + n];
    }
}

extern "C" void kernel_launch(void* const* d_in, const int* in_sizes, int n_in,
                              void* d_out, int out_size){
    const float* x_p    = (const float*)d_in[0];
    const float* y_g    = (const float*)d_in[1];
    const float* conv1w = (const float*)d_in[2];
    const float* conv1b = (const float*)d_in[3];
    const float* gamma1 = (const float*)d_in[4];
    const float* beta1  = (const float*)d_in[5];
    const float* conv2w = (const float*)d_in[6];
    const float* conv2b = (const float*)d_in[7];
    const float* gamma2 = (const float*)d_in[8];
    const float* beta2  = (const float*)d_in[9];
    const float* conv3w = (const float*)d_in[10];
    const float* conv3b = (const float*)d_in[11];
    const float* lnqw   = (const float*)d_in[12];
    const float* lnqb   = (const float*)d_in[13];
    const float* lnkw   = (const float*)d_in[14];
    const float* lnkb   = (const float*)d_in[15];
    const float* lnow   = (const float*)d_in[16];
    const float* lnob   = (const float*)d_in[17];
    const float* Wq     = (const float*)d_in[18];
    const float* Wk     = (const float*)d_in[19];
    const float* vw     = (const float*)d_in[20];
    const float* Wv     = (const float*)d_in[21];
    const float* outw   = (const float*)d_in[22];
    const float* outb   = (const float*)d_in[23];
    float* out = (float*)d_out;

    cudaFuncSetAttribute(attn_kernel, cudaFuncAttributeMaxDynamicSharedMemorySize, 98304);

    prep_kernel<<<128, 256>>>(gamma1, gamma2);
    conv1_kernel<<<dim3(64,4,2), 256>>>(x_p, conv1w, conv1b);
    gdn_kernel<<<1024, 256>>>(1, beta1);
    im2col2_kernel<<<dim3(800,64), 256>>>();
    conv2gemm_kernel<<<dim3(64,4), 256>>>(conv2w, conv2b);
    gdn_kernel<<<256, 256>>>(2, beta2);
    conv3_kernel<<<dim3(64,12,2), 128>>>(conv3w, conv3b);
    kv_kernel<<<dim3(64,5), 256>>>(y_g, lnkw, lnkb, Wk, Wv);
    attn_kernel<<<512, 256, 95872>>>(lnqw, lnqb, Wq, vw, outw, outb, lnow, lnob, out);
}

// round 9
// speedup vs baseline: 1.7081x; 1.2089x over previous
#include <cuda_runtime.h>

#define LN_EPS 1e-5f
typedef unsigned long long ull;

// ---- scratch ----
__device__ float g_s1[64*128*1024];
__device__ float g_s2[64*128*256];
__device__ float g_y3[64*192*256];
__device__ float g_kp[64*32*128];
__device__ float g_vp[64*32*192];
__device__ float g_gT[2][16384];
__device__ unsigned g_xcol[64*3200*256];    // conv2 im2col (tf32 bits)
__device__ unsigned g_x3col[64*1152*256];   // conv3 im2col (tf32 bits)
__device__ unsigned g_w2tf[128*3200];       // conv2 W (tf32 bits)
__device__ unsigned g_w3tf[192*1152];       // conv3 W (tf32 bits)

__device__ __forceinline__ float tanh_fast(float x){
    float y; asm("tanh.approx.f32 %0, %1;" : "=f"(y) : "f"(x)); return y;
}
__device__ __forceinline__ ull pk2(float lo, float hi){
    ull r; asm("mov.b64 %0, {%1, %2};" : "=l"(r) : "f"(lo), "f"(hi)); return r;
}
__device__ __forceinline__ ull pkdup(float v){ return pk2(v, v); }
__device__ __forceinline__ void upk2(ull p, float& lo, float& hi){
    asm("mov.b64 {%0, %1}, %2;" : "=f"(lo), "=f"(hi) : "l"(p));
}
__device__ __forceinline__ ull ffma2(ull a, ull b, ull c){
    ull d; asm("fma.rn.f32x2 %0, %1, %2, %3;" : "=l"(d) : "l"(a), "l"(b), "l"(c)); return d;
}
__device__ __forceinline__ unsigned f2tf(float f){
    unsigned t; asm("cvt.rna.tf32.f32 %0, %1;" : "=r"(t) : "f"(f)); return t;
}

// ---- conv1 (+ gamma transpose fold): grid (64,4,2), 256 thr ----
__global__ void conv1_kernel(const float* __restrict__ x, const float* __restrict__ w,
                             const float* __restrict__ b, const float* __restrict__ g1,
                             const float* __restrict__ g2){
    __shared__ float sw[4800];
    __shared__ float sin_[3885];
    int bp = blockIdx.x, tile = blockIdx.y, z = blockIdx.z;
    int t = threadIdx.x;
    if (z == 0){
        int blk = bp*4 + tile;
        for (int i = t; i < 128; i += 256){
            int e = blk*128 + i;
            int which = e >> 14, idx = e & 16383;
            const float* g = which ? g2 : g1;
            g_gT[which][(idx & 127)*128 + (idx >> 7)] = g[idx];
        }
    }
    for (int e = t; e < 4800; e += 256) sw[e] = w[z*4800 + e];
    int ty0 = (tile>>1)*16, tx0 = (tile&1)*16;
    int iy0 = 2*ty0 - 2, ix0 = 2*tx0 - 2;
    const float* xb = x + bp*12288;
    for (int e = t; e < 3675; e += 256){
        int c = e/1225, rem = e - c*1225, r = rem/35, col = rem - r*35;
        int gy = iy0 + r, gx = ix0 + col;
        float v = 0.f;
        if (gy>=0 && gy<64 && gx>=0 && gx<64) v = xb[c*4096 + gy*64 + gx];
        sin_[(c*35 + r)*37 + col] = v;
    }
    __syncthreads();
    int px4 = t & 63, cog = t >> 6;
    int ly = px4 >> 2, lx0 = (px4 & 3)*4;
    float* ob = g_s1 + bp*131072;
    for (int p = 0; p < 2; p++){
        int col0 = cog*16 + p*8;
        float acc[8][4];
        #pragma unroll
        for (int i = 0; i < 8; i++){
            float bb = b[z*64 + col0 + i];
            #pragma unroll
            for (int j = 0; j < 4; j++) acc[i][j] = bb;
        }
        #pragma unroll 1
        for (int c = 0; c < 3; c++){
            #pragma unroll
            for (int ky = 0; ky < 5; ky++){
                #pragma unroll
                for (int kx = 0; kx < 5; kx++){
                    float xv[4];
                    #pragma unroll
                    for (int j = 0; j < 4; j++)
                        xv[j] = sin_[(c*35 + 2*ly + ky)*37 + 2*lx0 + 2*j + kx];
                    #pragma unroll
                    for (int i = 0; i < 8; i++){
                        float wv = sw[(col0+i)*75 + c*25 + ky*5 + kx];
                        #pragma unroll
                        for (int j = 0; j < 4; j++) acc[i][j] = fmaf(wv, xv[j], acc[i][j]);
                    }
                }
            }
        }
        #pragma unroll
        for (int i = 0; i < 8; i++){
            float4 o = make_float4(acc[i][0], acc[i][1], acc[i][2], acc[i][3]);
            *reinterpret_cast<float4*>(ob + (z*64+col0+i)*1024 + (ty0+ly)*32 + tx0 + lx0) = o;
        }
    }
}

// ---- GDN in-place (f32x2) + W tf32-convert fold on stage 1 ----
__global__ void gdn_kernel(int stage, const float* __restrict__ beta,
                           const float* __restrict__ w2, const float* __restrict__ w3){
    __shared__ float sA[2048];
    __shared__ float sB[1088];
    int HW = (stage == 1) ? 1024 : 256;
    float* x = (stage == 1) ? g_s1 : g_s2;
    const float* gT = g_gT[stage-1];
    int chunks = HW >> 6;
    int bp = blockIdx.x / chunks;
    int p0 = (blockIdx.x - bp*chunks) * 64;
    int t = threadIdx.x;
    if (stage == 1){
        int base2 = blockIdx.x * 400;
        for (int i = t; i < 400; i += 256) g_w2tf[base2 + i] = f2tf(w2[base2 + i]);
        int base3 = blockIdx.x * 216;
        for (int i = t; i < 216; i += 256) g_w3tf[base3 + i] = f2tf(w3[base3 + i]);
    }
    int i = t >> 4, j = t & 15;
    float* xb = x + bp*128*HW;
    ull acc[8][2];
    #pragma unroll
    for (int ii = 0; ii < 8; ii++){
        float bb = beta[i*8 + ii];
        acc[ii][0] = pkdup(bb); acc[ii][1] = pkdup(bb);
    }
    for (int c0 = 0; c0 < 128; c0 += 16){
        __syncthreads();
        for (int e = t; e < 2048; e += 256) sA[e] = gT[c0*128 + e];
        for (int e = t; e < 1024; e += 256){
            int cc = e >> 6, p = e & 63;
            float v = xb[(c0+cc)*HW + p0 + p];
            sB[cc*68 + p] = v*v;
        }
        __syncthreads();
        #pragma unroll
        for (int cc = 0; cc < 16; cc++){
            const ull* xp = reinterpret_cast<const ull*>(sB + cc*68 + j*4);
            ull x0 = xp[0], x1 = xp[1];
            float4 ga = *reinterpret_cast<const float4*>(sA + cc*128 + i*8);
            float4 gb = *reinterpret_cast<const float4*>(sA + cc*128 + i*8 + 4);
            float gs[8] = {ga.x,ga.y,ga.z,ga.w,gb.x,gb.y,gb.z,gb.w};
            #pragma unroll
            for (int ii = 0; ii < 8; ii++){
                ull wp = pkdup(gs[ii]);
                acc[ii][0] = ffma2(x0, wp, acc[ii][0]);
                acc[ii][1] = ffma2(x1, wp, acc[ii][1]);
            }
        }
    }
    #pragma unroll
    for (int ii = 0; ii < 8; ii++){
        int d = i*8 + ii;
        float a0,a1,a2,a3;
        upk2(acc[ii][0], a0, a1);
        upk2(acc[ii][1], a2, a3);
        float4 xv = *reinterpret_cast<const float4*>(xb + d*HW + p0 + j*4);
        float4 o;
        o.x = xv.x * rsqrtf(a0);
        o.y = xv.y * rsqrtf(a1);
        o.z = xv.z * rsqrtf(a2);
        o.w = xv.w * rsqrtf(a3);
        *reinterpret_cast<float4*>(xb + d*HW + p0 + j*4) = o;
    }
}

// ---- conv2 im2col (tf32 out): grid (800,64), 256 thr ----
__global__ void im2col2_kernel(){
    int bp = blockIdx.y;
    int t = threadIdx.x;
    int oy = t >> 4, ox = t & 15;
    const float* xb = g_s1 + bp*131072;
    unsigned* xc = g_xcol + bp*819200;
    #pragma unroll 1
    for (int kk = 0; kk < 4; kk++){
        int k = blockIdx.x*4 + kk;
        int ci = k / 25, r = k - ci*25;
        int ky = r / 5, kx = r - ky*5;
        int iy = 2*oy - 2 + ky, ix = 2*ox - 2 + kx;
        float v = 0.f;
        if (iy>=0 && iy<32 && ix>=0 && ix<32) v = xb[ci*1024 + iy*32 + ix];
        xc[k*256 + t] = f2tf(v);
    }
}

// ---- conv3 im2col (tf32 out): grid (288,64), 256 thr ----
__global__ void im2col3_kernel(){
    int bp = blockIdx.y;
    int t = threadIdx.x;
    int oy = t >> 4, ox = t & 15;
    const float* xb = g_s2 + bp*32768;
    unsigned* xc = g_x3col + bp*294912;
    #pragma unroll 1
    for (int kk = 0; kk < 4; kk++){
        int k = blockIdx.x*4 + kk;
        int ci = k / 9, r = k - ci*9;
        int ky = r / 3, kx = r - ky*3;
        int iy = oy - 1 + ky, ix = ox - 1 + kx;
        float v = 0.f;
        if (iy>=0 && iy<16 && ix>=0 && ix<16) v = xb[ci*256 + iy*16 + ix];
        xc[k*256 + t] = f2tf(v);
    }
}

// ---- conv2 GEMM (tf32 mma, preconverted): grid (64,4), 256 thr ----
__global__ void __launch_bounds__(256) conv2gemm_kernel(const float* __restrict__ bias){
    __shared__ unsigned sW[128*36];
    __shared__ unsigned sX[32*72];
    int bp = blockIdx.x, n0b = blockIdx.y * 64;
    int t = threadIdx.x;
    int warp = t >> 5, lane = t & 31;
    int g = lane >> 2, tig = lane & 3;
    int m0 = (warp >> 1) * 32;
    int n0 = (warp & 1) * 32;
    float c[2][4][4];
    #pragma unroll
    for (int mt = 0; mt < 2; mt++)
        #pragma unroll
        for (int nt = 0; nt < 4; nt++)
            #pragma unroll
            for (int q = 0; q < 4; q++) c[mt][nt][q] = 0.f;
    const unsigned* xcb = g_xcol + bp*819200 + n0b;
    for (int kc = 0; kc < 3200; kc += 32){
        __syncthreads();
        for (int e = t; e < 1024; e += 256){
            int co = e >> 3, kk = (e & 7) * 4;
            *reinterpret_cast<uint4*>(&sW[co*36 + kk]) =
                *reinterpret_cast<const uint4*>(&g_w2tf[co*3200 + kc + kk]);
        }
        for (int e = t; e < 512; e += 256){
            int kk = e >> 4, px = (e & 15) * 4;
            *reinterpret_cast<uint4*>(&sX[kk*72 + px]) =
                *reinterpret_cast<const uint4*>(&xcb[(kc + kk)*256 + px]);
        }
        __syncthreads();
        #pragma unroll
        for (int ks = 0; ks < 4; ks++){
            int k0 = ks*8;
            unsigned a[2][4], bb[4][2];
            #pragma unroll
            for (int mt = 0; mt < 2; mt++){
                int m = m0 + mt*16;
                a[mt][0] = sW[(m+g)*36 + k0 + tig];
                a[mt][1] = sW[(m+g+8)*36 + k0 + tig];
                a[mt][2] = sW[(m+g)*36 + k0 + tig + 4];
                a[mt][3] = sW[(m+g+8)*36 + k0 + tig + 4];
            }
            #pragma unroll
            for (int nt = 0; nt < 4; nt++){
                int n = n0 + nt*8;
                bb[nt][0] = sX[(k0+tig)*72 + n + g];
                bb[nt][1] = sX[(k0+tig+4)*72 + n + g];
            }
            #pragma unroll
            for (int mt = 0; mt < 2; mt++)
                #pragma unroll
                for (int nt = 0; nt < 4; nt++)
                    asm volatile(
                        "mma.sync.aligned.m16n8k8.row.col.f32.tf32.tf32.f32 "
                        "{%0,%1,%2,%3}, {%4,%5,%6,%7}, {%8,%9}, {%0,%1,%2,%3};"
                        : "+f"(c[mt][nt][0]), "+f"(c[mt][nt][1]),
                          "+f"(c[mt][nt][2]), "+f"(c[mt][nt][3])
                        : "r"(a[mt][0]), "r"(a[mt][1]), "r"(a[mt][2]), "r"(a[mt][3]),
                          "r"(bb[nt][0]), "r"(bb[nt][1]));
        }
    }
    float* ob = g_s2 + bp*32768;
    #pragma unroll
    for (int mt = 0; mt < 2; mt++){
        int coA = m0 + mt*16 + g;
        int coB = coA + 8;
        float bA = bias[coA], bB = bias[coB];
        #pragma unroll
        for (int nt = 0; nt < 4; nt++){
            int px = n0b + n0 + nt*8 + 2*tig;
            *reinterpret_cast<float2*>(ob + coA*256 + px) =
                make_float2(c[mt][nt][0] + bA, c[mt][nt][1] + bA);
            *reinterpret_cast<float2*>(ob + coB*256 + px) =
                make_float2(c[mt][nt][2] + bB, c[mt][nt][3] + bB);
        }
    }
}

// ---- conv3 GEMM (tf32 mma): grid (64,4), 384 thr (12 warps, 192co x 64px) ----
__global__ void __launch_bounds__(384) conv3gemm_kernel(const float* __restrict__ bias){
    __shared__ unsigned sW[192*36];
    __shared__ unsigned sX[32*72];
    int bp = blockIdx.x, n0b = blockIdx.y * 64;
    int t = threadIdx.x;
    int warp = t >> 5, lane = t & 31;
    int g = lane >> 2, tig = lane & 3;
    int m0 = (warp >> 1) * 32;   // 0..160
    int n0 = (warp & 1) * 32;
    float c[2][4][4];
    #pragma unroll
    for (int mt = 0; mt < 2; mt++)
        #pragma unroll
        for (int nt = 0; nt < 4; nt++)
            #pragma unroll
            for (int q = 0; q < 4; q++) c[mt][nt][q] = 0.f;
    const unsigned* xcb = g_x3col + bp*294912 + n0b;
    for (int kc = 0; kc < 1152; kc += 32){
        __syncthreads();
        for (int e = t; e < 1536; e += 384){
            int co = e >> 3, kk = (e & 7) * 4;
            *reinterpret_cast<uint4*>(&sW[co*36 + kk]) =
                *reinterpret_cast<const uint4*>(&g_w3tf[co*1152 + kc + kk]);
        }
        for (int e = t; e < 512; e += 384){
            int kk = e >> 4, px = (e & 15) * 4;
            *reinterpret_cast<uint4*>(&sX[kk*72 + px]) =
                *reinterpret_cast<const uint4*>(&xcb[(kc + kk)*256 + px]);
        }
        __syncthreads();
        #pragma unroll
        for (int ks = 0; ks < 4; ks++){
            int k0 = ks*8;
            unsigned a[2][4], bb[4][2];
            #pragma unroll
            for (int mt = 0; mt < 2; mt++){
                int m = m0 + mt*16;
                a[mt][0] = sW[(m+g)*36 + k0 + tig];
                a[mt][1] = sW[(m+g+8)*36 + k0 + tig];
                a[mt][2] = sW[(m+g)*36 + k0 + tig + 4];
                a[mt][3] = sW[(m+g+8)*36 + k0 + tig + 4];
            }
            #pragma unroll
            for (int nt = 0; nt < 4; nt++){
                int n = n0 + nt*8;
                bb[nt][0] = sX[(k0+tig)*72 + n + g];
                bb[nt][1] = sX[(k0+tig+4)*72 + n + g];
            }
            #pragma unroll
            for (int mt = 0; mt < 2; mt++)
                #pragma unroll
                for (int nt = 0; nt < 4; nt++)
                    asm volatile(
                        "mma.sync.aligned.m16n8k8.row.col.f32.tf32.tf32.f32 "
                        "{%0,%1,%2,%3}, {%4,%5,%6,%7}, {%8,%9}, {%0,%1,%2,%3};"
                        : "+f"(c[mt][nt][0]), "+f"(c[mt][nt][1]),
                          "+f"(c[mt][nt][2]), "+f"(c[mt][nt][3])
                        : "r"(a[mt][0]), "r"(a[mt][1]), "r"(a[mt][2]), "r"(a[mt][3]),
                          "r"(bb[nt][0]), "r"(bb[nt][1]));
        }
    }
    float* ob = g_y3 + bp*49152;
    #pragma unroll
    for (int mt = 0; mt < 2; mt++){
        int coA = m0 + mt*16 + g;
        int coB = coA + 8;
        float bA = bias[coA], bB = bias[coB];
        #pragma unroll
        for (int nt = 0; nt < 4; nt++){
            int px = n0b + n0 + nt*8 + 2*tig;
            *reinterpret_cast<float2*>(ob + coA*256 + px) =
                make_float2(c[mt][nt][0] + bA, c[mt][nt][1] + bA);
            *reinterpret_cast<float2*>(ob + coB*256 + px) =
                make_float2(c[mt][nt][2] + bB, c[mt][nt][3] + bB);
        }
    }
}

// ---- kv: LN + k_proj + v_proj. grid (64,5), 256 thr ----
__global__ void kv_kernel(const float* __restrict__ yg, const float* __restrict__ lnw,
                          const float* __restrict__ lnb, const float* __restrict__ Wk,
                          const float* __restrict__ Wv){
    __shared__ float s_kv[32*193];
    __shared__ float s_w[64*33];
    int bp = blockIdx.x;
    int r0 = blockIdx.y * 64;
    int t = threadIdx.x;
    int w = t >> 5, l = t & 31;
    for (int e = t; e < 6144; e += 256){
        int c = e >> 5, k = e & 31;
        s_kv[k*193 + c] = yg[bp*6144 + c*32 + k];
    }
    __syncthreads();
    {
        float lwv[6], lbv[6];
        #pragma unroll
        for (int i = 0; i < 6; i++){ lwv[i] = lnw[l+32*i]; lbv[i] = lnb[l+32*i]; }
        for (int ki = 0; ki < 4; ki++){
            int k = w*4 + ki;
            float v[6]; float s = 0.f;
            #pragma unroll
            for (int i = 0; i < 6; i++){ v[i] = s_kv[k*193 + l + 32*i]; s += v[i]; }
            #pragma unroll
            for (int o = 16; o > 0; o >>= 1) s += __shfl_xor_sync(0xffffffffu, s, o);
            float mu = s * (1.f/192.f);
            float vs = 0.f;
            #pragma unroll
            for (int i = 0; i < 6; i++){ float d = v[i]-mu; vs += d*d; }
            #pragma unroll
            for (int o = 16; o > 0; o >>= 1) vs += __shfl_xor_sync(0xffffffffu, vs, o);
            float rs = rsqrtf(vs * (1.f/192.f) + LN_EPS);
            #pragma unroll
            for (int i = 0; i < 6; i++)
                s_kv[k*193 + l + 32*i] = (v[i]-mu)*rs*lwv[i] + lbv[i];
        }
    }
    int kq = t & 7, rp = t >> 3;
    {
        float acc[2][4];
        #pragma unroll
        for (int i = 0; i < 2; i++)
            #pragma unroll
            for (int kk = 0; kk < 4; kk++) acc[i][kk] = 0.f;
        for (int c0 = 0; c0 < 192; c0 += 32){
            __syncthreads();
            for (int e = t; e < 2048; e += 256){
                int rr = e >> 5, cc = e & 31;
                int row = r0 + rr;
                s_w[rr*33 + cc] = (row < 128) ? Wk[row*192 + c0 + cc]
                                              : Wv[(row-128)*192 + c0 + cc];
            }
            __syncthreads();
            for (int cc = 0; cc < 32; cc++){
                float wv0 = s_w[(rp*2)*33 + cc], wv1 = s_w[(rp*2+1)*33 + cc];
                #pragma unroll
                for (int kk = 0; kk < 4; kk++){
                    float kvv = s_kv[(kq*4+kk)*193 + c0 + cc];
                    acc[0][kk] = fmaf(wv0, kvv, acc[0][kk]);
                    acc[1][kk] = fmaf(wv1, kvv, acc[1][kk]);
                }
            }
        }
        #pragma unroll
        for (int i = 0; i < 2; i++){
            int row = r0 + rp*2 + i;
            #pragma unroll
            for (int kk = 0; kk < 4; kk++){
                int k = kq*4 + kk;
                if (row < 128) g_kp[bp*4096 + k*128 + row] = acc[i][kk];
                else           g_vp[bp*6144 + k*192 + (row-128)] = acc[i][kk];
            }
        }
    }
}

// ---- attention: grid 512, 256 thr, 95872 B dyn smem ----
__global__ void attn_kernel(const float* __restrict__ lnqw, const float* __restrict__ lnqb,
                            const float* __restrict__ Wq, const float* __restrict__ vw,
                            const float* __restrict__ out_w, const float* __restrict__ out_b,
                            const float* __restrict__ lnow, const float* __restrict__ lnob,
                            float* __restrict__ out){
    extern __shared__ float sm[];
    float* s_qn  = sm;
    float* s_w   = sm + 6176;
    float* s_kp  = sm + 12512;
    float* s_e   = sm + 16736;
    float* s_ctx = sm + 17792;
    int bp = blockIdx.x >> 3;
    int q0 = (blockIdx.x & 7) << 5;
    int t = threadIdx.x;
    int w = t >> 5, l = t & 31;
    const float* y3 = g_y3 + bp*49152;
    for (int e = t; e < 6144; e += 256){
        int m = e >> 5, q = e & 31;
        s_qn[q*193 + m] = y3[m*256 + q0 + q];
    }
    for (int e = t; e < 4096; e += 256){
        int k = e >> 7;
        s_kp[k*132 + (e & 127)] = g_kp[bp*4096 + e];
    }
    __syncthreads();
    {
        float lwv[6], lbv[6];
        #pragma unroll
        for (int i = 0; i < 6; i++){ lwv[i] = lnqw[l+32*i]; lbv[i] = lnqb[l+32*i]; }
        for (int qi = 0; qi < 4; qi++){
            int q = w*4 + qi;
            float v[6]; float s = 0.f;
            #pragma unroll
            for (int i = 0; i < 6; i++){ v[i] = s_qn[q*193 + l + 32*i]; s += v[i]; }
            #pragma unroll
            for (int o = 16; o > 0; o >>= 1) s += __shfl_xor_sync(0xffffffffu, s, o);
            float mu = s * (1.f/192.f);
            float vs = 0.f;
            #pragma unroll
            for (int i = 0; i < 6; i++){ float d = v[i]-mu; vs += d*d; }
            #pragma unroll
            for (int o = 16; o > 0; o >>= 1) vs += __shfl_xor_sync(0xffffffffu, vs, o);
            float rs = rsqrtf(vs * (1.f/192.f) + LN_EPS);
            #pragma unroll
            for (int i = 0; i < 6; i++)
                s_qn[q*193 + l + 32*i] = (v[i]-mu)*rs*lwv[i] + lbv[i];
        }
    }
    float qp[4][4];
    #pragma unroll
    for (int a = 0; a < 4; a++)
        #pragma unroll
        for (int b2 = 0; b2 < 4; b2++) qp[a][b2] = 0.f;
    for (int c0 = 0; c0 < 192; c0 += 32){
        __syncthreads();
        for (int e = t; e < 4096; e += 256){
            int d = e >> 5, cc = e & 31;
            s_w[d*33 + cc] = Wq[d*192 + c0 + cc];
        }
        __syncthreads();
        for (int cc = 0; cc < 32; cc++){
            float wv[4], qv[4];
            #pragma unroll
            for (int j = 0; j < 4; j++) wv[j] = s_w[(l+32*j)*33 + cc];
            #pragma unroll
            for (int qi = 0; qi < 4; qi++) qv[qi] = s_qn[(w*4+qi)*193 + c0 + cc];
            #pragma unroll
            for (int qi = 0; qi < 4; qi++)
                #pragma unroll
                for (int j = 0; j < 4; j++) qp[qi][j] = fmaf(qv[qi], wv[j], qp[qi][j]);
        }
    }
    __syncthreads();
    float* s_vp = s_w;
    for (int e = t; e < 6144; e += 256){
        int k = e / 192, m = e - k*192;
        s_vp[k*193 + m] = g_vp[bp*6144 + e];
    }
    float vv[4];
    #pragma unroll
    for (int j = 0; j < 4; j++) vv[j] = vw[l + 32*j];
    for (int k = 0; k < 32; k++){
        float kp4[4];
        #pragma unroll
        for (int j = 0; j < 4; j++) kp4[j] = s_kp[k*132 + l + 32*j];
        #pragma unroll
        for (int qi = 0; qi < 4; qi++){
            float s = 0.f;
            #pragma unroll
            for (int j = 0; j < 4; j++)
                s = fmaf(tanh_fast(qp[qi][j] + kp4[j]), vv[j], s);
            #pragma unroll
            for (int o = 16; o > 0; o >>= 1) s += __shfl_xor_sync(0xffffffffu, s, o);
            if (l == 0) s_e[(w*4+qi)*33 + k] = s;
        }
    }
    __syncwarp();
    for (int qi = 0; qi < 4; qi++){
        int q = w*4 + qi;
        float ev = s_e[q*33 + l];
        float mx = ev;
        #pragma unroll
        for (int o = 16; o > 0; o >>= 1) mx = fmaxf(mx, __shfl_xor_sync(0xffffffffu, mx, o));
        float p = __expf(ev - mx);
        float s = p;
        #pragma unroll
        for (int o = 16; o > 0; o >>= 1) s += __shfl_xor_sync(0xffffffffu, s, o);
        s_e[q*33 + l] = p / s;
    }
    __syncthreads();
    {
        int qr = t >> 3, mg = t & 7;
        float acc[24];
        #pragma unroll
        for (int i = 0; i < 24; i++) acc[i] = 0.f;
        for (int k = 0; k < 32; k++){
            float a = s_e[qr*33 + k];
            #pragma unroll
            for (int i = 0; i < 24; i++)
                acc[i] = fmaf(a, s_vp[k*193 + mg + 8*i], acc[i]);
        }
        #pragma unroll
        for (int i = 0; i < 24; i++) s_ctx[qr*193 + mg + 8*i] = acc[i];
    }
    __syncthreads();
    {
        int qh = t >> 4, ng = t & 15;
        float acc0[12], acc1[12];
        #pragma unroll
        for (int i = 0; i < 12; i++){ acc0[i] = 0.f; acc1[i] = 0.f; }
        for (int m0 = 0; m0 < 192; m0 += 32){
            __syncthreads();
            for (int e = t; e < 6144; e += 256){
                int n = e >> 5, mm = e & 31;
                s_w[n*33 + mm] = out_w[n*192 + m0 + mm];
            }
            __syncthreads();
            for (int mm = 0; mm < 32; mm++){
                float c0v = s_ctx[(2*qh)*193 + m0 + mm];
                float c1v = s_ctx[(2*qh+1)*193 + m0 + mm];
                #pragma unroll
                for (int i = 0; i < 12; i++){
                    float wv = s_w[(ng+16*i)*33 + mm];
                    acc0[i] = fmaf(c0v, wv, acc0[i]);
                    acc1[i] = fmaf(c1v, wv, acc1[i]);
                }
            }
        }
        float val0[12], val1[12];
        float s0 = 0.f, s1 = 0.f;
        #pragma unroll
        for (int i = 0; i < 12; i++){
            int n = ng + 16*i;
            val0[i] = acc0[i] + out_b[n] + s_qn[(2*qh)*193 + n];
            val1[i] = acc1[i] + out_b[n] + s_qn[(2*qh+1)*193 + n];
            s0 += val0[i]; s1 += val1[i];
        }
        #pragma unroll
        for (int o = 8; o > 0; o >>= 1){
            s0 += __shfl_xor_sync(0xffffffffu, s0, o);
            s1 += __shfl_xor_sync(0xffffffffu, s1, o);
        }
        float mu0 = s0*(1.f/192.f), mu1 = s1*(1.f/192.f);
        float vs0 = 0.f, vs1 = 0.f;
        #pragma unroll
        for (int i = 0; i < 12; i++){
            float d0 = val0[i]-mu0, d1 = val1[i]-mu1;
            vs0 += d0*d0; vs1 += d1*d1;
        }
        #pragma unroll
        for (int o = 8; o > 0; o >>= 1){
            vs0 += __shfl_xor_sync(0xffffffffu, vs0, o);
            vs1 += __shfl_xor_sync(0xffffffffu, vs1, o);
        }
        float r0 = rsqrtf(vs0*(1.f/192.f) + LN_EPS);
        float r1 = rsqrtf(vs1*(1.f/192.f) + LN_EPS);
        __syncthreads();
        #pragma unroll
        for (int i = 0; i < 12; i++){
            int n = ng + 16*i;
            s_ctx[(2*qh)*193 + n]   = (val0[i]-mu0)*r0*lnow[n] + lnob[n];
            s_ctx[(2*qh+1)*193 + n] = (val1[i]-mu1)*r1*lnow[n] + lnob[n];
        }
    }
    __syncthreads();
    for (int e = t; e < 6144; e += 256){
        int n = e >> 5, q = e & 31;
        out[bp*49152 + n*256 + q0 + q] = s_ctx[q*193 + n];
    }
}

extern "C" void kernel_launch(void* const* d_in, const int* in_sizes, int n_in,
                              void* d_out, int out_size){
    const float* x_p    = (const float*)d_in[0];
    const float* y_g    = (const float*)d_in[1];
    const float* conv1w = (const float*)d_in[2];
    const float* conv1b = (const float*)d_in[3];
    const float* gamma1 = (const float*)d_in[4];
    const float* beta1  = (const float*)d_in[5];
    const float* conv2w = (const float*)d_in[6];
    const float* conv2b = (const float*)d_in[7];
    const float* gamma2 = (const float*)d_in[8];
    const float* beta2  = (const float*)d_in[9];
    const float* conv3w = (const float*)d_in[10];
    const float* conv3b = (const float*)d_in[11];
    const float* lnqw   = (const float*)d_in[12];
    const float* lnqb   = (const float*)d_in[13];
    const float* lnkw   = (const float*)d_in[14];
    const float* lnkb   = (const float*)d_in[15];
    const float* lnow   = (const float*)d_in[16];
    const float* lnob   = (const float*)d_in[17];
    const float* Wq     = (const float*)d_in[18];
    const float* Wk     = (const float*)d_in[19];
    const float* vw     = (const float*)d_in[20];
    const float* Wv     = (const float*)d_in[21];
    const float* outw   = (const float*)d_in[22];
    const float* outb   = (const float*)d_in[23];
    float* out = (float*)d_out;

    cudaFuncSetAttribute(attn_kernel, cudaFuncAttributeMaxDynamicSharedMemorySize, 98304);

    conv1_kernel<<<dim3(64,4,2), 256>>>(x_p, conv1w, conv1b, gamma1, gamma2);  // idx 0
    gdn_kernel<<<1024, 256>>>(1, beta1, conv2w, conv3w);                        // idx 1
    im2col2_kernel<<<dim3(800,64), 256>>>();                                    // idx 2
    conv2gemm_kernel<<<dim3(64,4), 256>>>(conv2b);                              // idx 3 (profiled)
    gdn_kernel<<<256, 256>>>(2, beta2, nullptr, nullptr);                       // idx 4
    im2col3_kernel<<<dim3(288,64), 256>>>();                                    // idx 5
    conv3gemm_kernel<<<dim3(64,4), 384>>>(conv3b);                              // idx 6
    kv_kernel<<<dim3(64,5), 256>>>(y_g, lnkw, lnkb, Wk, Wv);                    // idx 7
    attn_kernel<<<512, 256, 95872>>>(lnqw, lnqb, Wq, vw, outw, outb, lnow, lnob, out);
}

// round 10
// speedup vs baseline: 2.3554x; 1.3790x over previous
#include <cuda_runtime.h>

#define LN_EPS 1e-5f
typedef unsigned long long ull;

// ---- scratch ----
__device__ float g_s1[64*128*1024];
__device__ float g_s2[64*128*256];
__device__ float g_y3[64*192*256];
__device__ float g_kp[64*32*128];
__device__ float g_vp[64*32*192];
__device__ float g_gT[2][16384];
__device__ unsigned g_xcol[64*3200*256];
__device__ unsigned g_x3col[64*1152*256];
__device__ unsigned g_w2tf[128*3200];
__device__ unsigned g_w3tf[192*1152];

__device__ __forceinline__ float tanh_fast(float x){
    float y; asm("tanh.approx.f32 %0, %1;" : "=f"(y) : "f"(x)); return y;
}
__device__ __forceinline__ ull pk2(float lo, float hi){
    ull r; asm("mov.b64 %0, {%1, %2};" : "=l"(r) : "f"(lo), "f"(hi)); return r;
}
__device__ __forceinline__ ull pkdup(float v){ return pk2(v, v); }
__device__ __forceinline__ void upk2(ull p, float& lo, float& hi){
    asm("mov.b64 {%0, %1}, %2;" : "=f"(lo), "=f"(hi) : "l"(p));
}
__device__ __forceinline__ ull ffma2(ull a, ull b, ull c){
    ull d; asm("fma.rn.f32x2 %0, %1, %2, %3;" : "=l"(d) : "l"(a), "l"(b), "l"(c)); return d;
}
__device__ __forceinline__ unsigned f2tf(float f){
    unsigned t; asm("cvt.rna.tf32.f32 %0, %1;" : "=r"(t) : "f"(f)); return t;
}
__device__ __forceinline__ void cp16(unsigned* sp, const unsigned* gp){
    unsigned sa = (unsigned)__cvta_generic_to_shared(sp);
    asm volatile("cp.async.cg.shared.global [%0], [%1], 16;" :: "r"(sa), "l"(gp));
}

// ---- conv1 (+ gamma transpose fold): grid (64,4,2), 256 thr ----
__global__ void conv1_kernel(const float* __restrict__ x, const float* __restrict__ w,
                             const float* __restrict__ b, const float* __restrict__ g1,
                             const float* __restrict__ g2){
    __shared__ float sw[4800];
    __shared__ float sin_[3885];
    int bp = blockIdx.x, tile = blockIdx.y, z = blockIdx.z;
    int t = threadIdx.x;
    if (z == 0){
        int blk = bp*4 + tile;
        for (int i = t; i < 128; i += 256){
            int e = blk*128 + i;
            int which = e >> 14, idx = e & 16383;
            const float* g = which ? g2 : g1;
            g_gT[which][(idx & 127)*128 + (idx >> 7)] = g[idx];
        }
    }
    for (int e = t; e < 4800; e += 256) sw[e] = w[z*4800 + e];
    int ty0 = (tile>>1)*16, tx0 = (tile&1)*16;
    int iy0 = 2*ty0 - 2, ix0 = 2*tx0 - 2;
    const float* xb = x + bp*12288;
    for (int e = t; e < 3675; e += 256){
        int c = e/1225, rem = e - c*1225, r = rem/35, col = rem - r*35;
        int gy = iy0 + r, gx = ix0 + col;
        float v = 0.f;
        if (gy>=0 && gy<64 && gx>=0 && gx<64) v = xb[c*4096 + gy*64 + gx];
        sin_[(c*35 + r)*37 + col] = v;
    }
    __syncthreads();
    int px4 = t & 63, cog = t >> 6;
    int ly = px4 >> 2, lx0 = (px4 & 3)*4;
    float* ob = g_s1 + bp*131072;
    for (int p = 0; p < 2; p++){
        int col0 = cog*16 + p*8;
        float acc[8][4];
        #pragma unroll
        for (int i = 0; i < 8; i++){
            float bb = b[z*64 + col0 + i];
            #pragma unroll
            for (int j = 0; j < 4; j++) acc[i][j] = bb;
        }
        #pragma unroll 1
        for (int c = 0; c < 3; c++){
            #pragma unroll
            for (int ky = 0; ky < 5; ky++){
                #pragma unroll
                for (int kx = 0; kx < 5; kx++){
                    float xv[4];
                    #pragma unroll
                    for (int j = 0; j < 4; j++)
                        xv[j] = sin_[(c*35 + 2*ly + ky)*37 + 2*lx0 + 2*j + kx];
                    #pragma unroll
                    for (int i = 0; i < 8; i++){
                        float wv = sw[(col0+i)*75 + c*25 + ky*5 + kx];
                        #pragma unroll
                        for (int j = 0; j < 4; j++) acc[i][j] = fmaf(wv, xv[j], acc[i][j]);
                    }
                }
            }
        }
        #pragma unroll
        for (int i = 0; i < 8; i++){
            float4 o = make_float4(acc[i][0], acc[i][1], acc[i][2], acc[i][3]);
            *reinterpret_cast<float4*>(ob + (z*64+col0+i)*1024 + (ty0+ly)*32 + tx0 + lx0) = o;
        }
    }
}

// ---- GDN in-place (f32x2) + W tf32-convert fold on stage 1 ----
__global__ void gdn_kernel(int stage, const float* __restrict__ beta,
                           const float* __restrict__ w2, const float* __restrict__ w3){
    __shared__ float sA[2048];
    __shared__ float sB[1088];
    int HW = (stage == 1) ? 1024 : 256;
    float* x = (stage == 1) ? g_s1 : g_s2;
    const float* gT = g_gT[stage-1];
    int chunks = HW >> 6;
    int bp = blockIdx.x / chunks;
    int p0 = (blockIdx.x - bp*chunks) * 64;
    int t = threadIdx.x;
    if (stage == 1){
        int base2 = blockIdx.x * 400;
        for (int i = t; i < 400; i += 256) g_w2tf[base2 + i] = f2tf(w2[base2 + i]);
        int base3 = blockIdx.x * 216;
        for (int i = t; i < 216; i += 256) g_w3tf[base3 + i] = f2tf(w3[base3 + i]);
    }
    int i = t >> 4, j = t & 15;
    float* xb = x + bp*128*HW;
    ull acc[8][2];
    #pragma unroll
    for (int ii = 0; ii < 8; ii++){
        float bb = beta[i*8 + ii];
        acc[ii][0] = pkdup(bb); acc[ii][1] = pkdup(bb);
    }
    for (int c0 = 0; c0 < 128; c0 += 16){
        __syncthreads();
        for (int e = t; e < 2048; e += 256) sA[e] = gT[c0*128 + e];
        for (int e = t; e < 1024; e += 256){
            int cc = e >> 6, p = e & 63;
            float v = xb[(c0+cc)*HW + p0 + p];
            sB[cc*68 + p] = v*v;
        }
        __syncthreads();
        #pragma unroll
        for (int cc = 0; cc < 16; cc++){
            const ull* xp = reinterpret_cast<const ull*>(sB + cc*68 + j*4);
            ull x0 = xp[0], x1 = xp[1];
            float4 ga = *reinterpret_cast<const float4*>(sA + cc*128 + i*8);
            float4 gb = *reinterpret_cast<const float4*>(sA + cc*128 + i*8 + 4);
            float gs[8] = {ga.x,ga.y,ga.z,ga.w,gb.x,gb.y,gb.z,gb.w};
            #pragma unroll
            for (int ii = 0; ii < 8; ii++){
                ull wp = pkdup(gs[ii]);
                acc[ii][0] = ffma2(x0, wp, acc[ii][0]);
                acc[ii][1] = ffma2(x1, wp, acc[ii][1]);
            }
        }
    }
    #pragma unroll
    for (int ii = 0; ii < 8; ii++){
        int d = i*8 + ii;
        float a0,a1,a2,a3;
        upk2(acc[ii][0], a0, a1);
        upk2(acc[ii][1], a2, a3);
        float4 xv = *reinterpret_cast<const float4*>(xb + d*HW + p0 + j*4);
        float4 o;
        o.x = xv.x * rsqrtf(a0);
        o.y = xv.y * rsqrtf(a1);
        o.z = xv.z * rsqrtf(a2);
        o.w = xv.w * rsqrtf(a3);
        *reinterpret_cast<float4*>(xb + d*HW + p0 + j*4) = o;
    }
}

// ---- conv2 im2col (tf32 out): grid (800,64), 256 thr ----
__global__ void im2col2_kernel(){
    int bp = blockIdx.y;
    int t = threadIdx.x;
    int oy = t >> 4, ox = t & 15;
    const float* xb = g_s1 + bp*131072;
    unsigned* xc = g_xcol + bp*819200;
    #pragma unroll 1
    for (int kk = 0; kk < 4; kk++){
        int k = blockIdx.x*4 + kk;
        int ci = k / 25, r = k - ci*25;
        int ky = r / 5, kx = r - ky*5;
        int iy = 2*oy - 2 + ky, ix = 2*ox - 2 + kx;
        float v = 0.f;
        if (iy>=0 && iy<32 && ix>=0 && ix<32) v = xb[ci*1024 + iy*32 + ix];
        xc[k*256 + t] = f2tf(v);
    }
}

// ---- conv3 im2col (tf32 out): grid (288,64), 256 thr ----
__global__ void im2col3_kernel(){
    int bp = blockIdx.y;
    int t = threadIdx.x;
    int oy = t >> 4, ox = t & 15;
    const float* xb = g_s2 + bp*32768;
    unsigned* xc = g_x3col + bp*294912;
    #pragma unroll 1
    for (int kk = 0; kk < 4; kk++){
        int k = blockIdx.x*4 + kk;
        int ci = k / 9, r = k - ci*9;
        int ky = r / 3, kx = r - ky*3;
        int iy = oy - 1 + ky, ix = ox - 1 + kx;
        float v = 0.f;
        if (iy>=0 && iy<16 && ix>=0 && ix<16) v = xb[ci*256 + iy*16 + ix];
        xc[k*256 + t] = f2tf(v);
    }
}

// ---- conv2 GEMM, cp.async double-buffered. grid (64,4), 256 thr, 55296 B dyn ----
__global__ void __launch_bounds__(256) conv2gemm_kernel(const float* __restrict__ bias){
    extern __shared__ unsigned smu[];
    // layout: W buf0 [0,4608), W buf1 [4608,9216), X buf0 [9216,11520), X buf1 [11520,13824)
    int bp = blockIdx.x, n0b = blockIdx.y * 64;
    int t = threadIdx.x;
    int warp = t >> 5, lane = t & 31;
    int g = lane >> 2, tig = lane & 3;
    int m0 = (warp >> 1) * 32;
    int n0 = (warp & 1) * 32;
    float c[2][4][4];
    #pragma unroll
    for (int mt = 0; mt < 2; mt++)
        #pragma unroll
        for (int nt = 0; nt < 4; nt++)
            #pragma unroll
            for (int q = 0; q < 4; q++) c[mt][nt][q] = 0.f;
    const unsigned* xcb = g_xcol + bp*819200 + n0b;

    auto stage = [&](int kc, int buf){
        unsigned* dW = smu + buf*4608;
        unsigned* dX = smu + 9216 + buf*2304;
        #pragma unroll
        for (int s = 0; s < 4; s++){
            int e = t + s*256;                  // 1024 W segments
            int co = e >> 3, ks = (e & 7) * 4;
            cp16(&dW[co*36 + ks], &g_w2tf[co*3200 + kc + ks]);
        }
        #pragma unroll
        for (int s = 0; s < 2; s++){
            int e = t + s*256;                  // 512 X segments
            int kk = e >> 4, ps = (e & 15) * 4;
            cp16(&dX[kk*72 + ps], &xcb[(kc + kk)*256 + ps]);
        }
        asm volatile("cp.async.commit_group;" ::);
    };

    stage(0, 0);
    for (int it = 0; it < 100; it++){
        if (it + 1 < 100) stage((it+1)*32, (it+1) & 1);
        if (it + 1 < 100) asm volatile("cp.async.wait_group 1;" ::);
        else              asm volatile("cp.async.wait_group 0;" ::);
        __syncthreads();
        const unsigned* dW = smu + (it & 1)*4608;
        const unsigned* dX = smu + 9216 + (it & 1)*2304;
        #pragma unroll
        for (int ks = 0; ks < 4; ks++){
            int k0 = ks*8;
            unsigned a[2][4], bb[4][2];
            #pragma unroll
            for (int mt = 0; mt < 2; mt++){
                int m = m0 + mt*16;
                a[mt][0] = dW[(m+g)*36 + k0 + tig];
                a[mt][1] = dW[(m+g+8)*36 + k0 + tig];
                a[mt][2] = dW[(m+g)*36 + k0 + tig + 4];
                a[mt][3] = dW[(m+g+8)*36 + k0 + tig + 4];
            }
            #pragma unroll
            for (int nt = 0; nt < 4; nt++){
                int n = n0 + nt*8;
                bb[nt][0] = dX[(k0+tig)*72 + n + g];
                bb[nt][1] = dX[(k0+tig+4)*72 + n + g];
            }
            #pragma unroll
            for (int mt = 0; mt < 2; mt++)
                #pragma unroll
                for (int nt = 0; nt < 4; nt++)
                    asm volatile(
                        "mma.sync.aligned.m16n8k8.row.col.f32.tf32.tf32.f32 "
                        "{%0,%1,%2,%3}, {%4,%5,%6,%7}, {%8,%9}, {%0,%1,%2,%3};"
                        : "+f"(c[mt][nt][0]), "+f"(c[mt][nt][1]),
                          "+f"(c[mt][nt][2]), "+f"(c[mt][nt][3])
                        : "r"(a[mt][0]), "r"(a[mt][1]), "r"(a[mt][2]), "r"(a[mt][3]),
                          "r"(bb[nt][0]), "r"(bb[nt][1]));
        }
        __syncthreads();
    }
    float* ob = g_s2 + bp*32768;
    #pragma unroll
    for (int mt = 0; mt < 2; mt++){
        int coA = m0 + mt*16 + g;
        int coB = coA + 8;
        float bA = bias[coA], bB = bias[coB];
        #pragma unroll
        for (int nt = 0; nt < 4; nt++){
            int px = n0b + n0 + nt*8 + 2*tig;
            *reinterpret_cast<float2*>(ob + coA*256 + px) =
                make_float2(c[mt][nt][0] + bA, c[mt][nt][1] + bA);
            *reinterpret_cast<float2*>(ob + coB*256 + px) =
                make_float2(c[mt][nt][2] + bB, c[mt][nt][3] + bB);
        }
    }
}

// ---- conv3 GEMM, cp.async double-buffered. grid (64,4), 384 thr, 73728 B dyn ----
__global__ void __launch_bounds__(384) conv3gemm_kernel(const float* __restrict__ bias){
    extern __shared__ unsigned smu3[];
    // layout: W buf0 [0,6912), W buf1 [6912,13824), X buf0 [13824,16128), X buf1 [16128,18432)
    int bp = blockIdx.x, n0b = blockIdx.y * 64;
    int t = threadIdx.x;
    int warp = t >> 5, lane = t & 31;
    int g = lane >> 2, tig = lane & 3;
    int m0 = (warp >> 1) * 32;
    int n0 = (warp & 1) * 32;
    float c[2][4][4];
    #pragma unroll
    for (int mt = 0; mt < 2; mt++)
        #pragma unroll
        for (int nt = 0; nt < 4; nt++)
            #pragma unroll
            for (int q = 0; q < 4; q++) c[mt][nt][q] = 0.f;
    const unsigned* xcb = g_x3col + bp*294912 + n0b;

    auto stage = [&](int kc, int buf){
        unsigned* dW = smu3 + buf*6912;
        unsigned* dX = smu3 + 13824 + buf*2304;
        for (int e = t; e < 1536; e += 384){     // 192x8 W segments
            int co = e >> 3, ks = (e & 7) * 4;
            cp16(&dW[co*36 + ks], &g_w3tf[co*1152 + kc + ks]);
        }
        for (int e = t; e < 512; e += 384){
            int kk = e >> 4, ps = (e & 15) * 4;
            cp16(&dX[kk*72 + ps], &xcb[(kc + kk)*256 + ps]);
        }
        asm volatile("cp.async.commit_group;" ::);
    };

    stage(0, 0);
    for (int it = 0; it < 36; it++){
        if (it + 1 < 36) stage((it+1)*32, (it+1) & 1);
        if (it + 1 < 36) asm volatile("cp.async.wait_group 1;" ::);
        else             asm volatile("cp.async.wait_group 0;" ::);
        __syncthreads();
        const unsigned* dW = smu3 + (it & 1)*6912;
        const unsigned* dX = smu3 + 13824 + (it & 1)*2304;
        #pragma unroll
        for (int ks = 0; ks < 4; ks++){
            int k0 = ks*8;
            unsigned a[2][4], bb[4][2];
            #pragma unroll
            for (int mt = 0; mt < 2; mt++){
                int m = m0 + mt*16;
                a[mt][0] = dW[(m+g)*36 + k0 + tig];
                a[mt][1] = dW[(m+g+8)*36 + k0 + tig];
                a[mt][2] = dW[(m+g)*36 + k0 + tig + 4];
                a[mt][3] = dW[(m+g+8)*36 + k0 + tig + 4];
            }
            #pragma unroll
            for (int nt = 0; nt < 4; nt++){
                int n = n0 + nt*8;
                bb[nt][0] = dX[(k0+tig)*72 + n + g];
                bb[nt][1] = dX[(k0+tig+4)*72 + n + g];
            }
            #pragma unroll
            for (int mt = 0; mt < 2; mt++)
                #pragma unroll
                for (int nt = 0; nt < 4; nt++)
                    asm volatile(
                        "mma.sync.aligned.m16n8k8.row.col.f32.tf32.tf32.f32 "
                        "{%0,%1,%2,%3}, {%4,%5,%6,%7}, {%8,%9}, {%0,%1,%2,%3};"
                        : "+f"(c[mt][nt][0]), "+f"(c[mt][nt][1]),
                          "+f"(c[mt][nt][2]), "+f"(c[mt][nt][3])
                        : "r"(a[mt][0]), "r"(a[mt][1]), "r"(a[mt][2]), "r"(a[mt][3]),
                          "r"(bb[nt][0]), "r"(bb[nt][1]));
        }
        __syncthreads();
    }
    float* ob = g_y3 + bp*49152;
    #pragma unroll
    for (int mt = 0; mt < 2; mt++){
        int coA = m0 + mt*16 + g;
        int coB = coA + 8;
        float bA = bias[coA], bB = bias[coB];
        #pragma unroll
        for (int nt = 0; nt < 4; nt++){
            int px = n0b + n0 + nt*8 + 2*tig;
            *reinterpret_cast<float2*>(ob + coA*256 + px) =
                make_float2(c[mt][nt][0] + bA, c[mt][nt][1] + bA);
            *reinterpret_cast<float2*>(ob + coB*256 + px) =
                make_float2(c[mt][nt][2] + bB, c[mt][nt][3] + bB);
        }
    }
}

// ---- kv: LN + k_proj + v_proj. grid (64,5), 256 thr ----
__global__ void kv_kernel(const float* __restrict__ yg, const float* __restrict__ lnw,
                          const float* __restrict__ lnb, const float* __restrict__ Wk,
                          const float* __restrict__ Wv){
    __shared__ float s_kv[32*193];
    __shared__ float s_w[64*33];
    int bp = blockIdx.x;
    int r0 = blockIdx.y * 64;
    int t = threadIdx.x;
    int w = t >> 5, l = t & 31;
    for (int e = t; e < 6144; e += 256){
        int c = e >> 5, k = e & 31;
        s_kv[k*193 + c] = yg[bp*6144 + c*32 + k];
    }
    __syncthreads();
    {
        float lwv[6], lbv[6];
        #pragma unroll
        for (int i = 0; i < 6; i++){ lwv[i] = lnw[l+32*i]; lbv[i] = lnb[l+32*i]; }
        for (int ki = 0; ki < 4; ki++){
            int k = w*4 + ki;
            float v[6]; float s = 0.f;
            #pragma unroll
            for (int i = 0; i < 6; i++){ v[i] = s_kv[k*193 + l + 32*i]; s += v[i]; }
            #pragma unroll
            for (int o = 16; o > 0; o >>= 1) s += __shfl_xor_sync(0xffffffffu, s, o);
            float mu = s * (1.f/192.f);
            float vs = 0.f;
            #pragma unroll
            for (int i = 0; i < 6; i++){ float d = v[i]-mu; vs += d*d; }
            #pragma unroll
            for (int o = 16; o > 0; o >>= 1) vs += __shfl_xor_sync(0xffffffffu, vs, o);
            float rs = rsqrtf(vs * (1.f/192.f) + LN_EPS);
            #pragma unroll
            for (int i = 0; i < 6; i++)
                s_kv[k*193 + l + 32*i] = (v[i]-mu)*rs*lwv[i] + lbv[i];
        }
    }
    int kq = t & 7, rp = t >> 3;
    {
        float acc[2][4];
        #pragma unroll
        for (int i = 0; i < 2; i++)
            #pragma unroll
            for (int kk = 0; kk < 4; kk++) acc[i][kk] = 0.f;
        for (int c0 = 0; c0 < 192; c0 += 32){
            __syncthreads();
            for (int e = t; e < 2048; e += 256){
                int rr = e >> 5, cc = e & 31;
                int row = r0 + rr;
                s_w[rr*33 + cc] = (row < 128) ? Wk[row*192 + c0 + cc]
                                              : Wv[(row-128)*192 + c0 + cc];
            }
            __syncthreads();
            for (int cc = 0; cc < 32; cc++){
                float wv0 = s_w[(rp*2)*33 + cc], wv1 = s_w[(rp*2+1)*33 + cc];
                #pragma unroll
                for (int kk = 0; kk < 4; kk++){
                    float kvv = s_kv[(kq*4+kk)*193 + c0 + cc];
                    acc[0][kk] = fmaf(wv0, kvv, acc[0][kk]);
                    acc[1][kk] = fmaf(wv1, kvv, acc[1][kk]);
                }
            }
        }
        #pragma unroll
        for (int i = 0; i < 2; i++){
            int row = r0 + rp*2 + i;
            #pragma unroll
            for (int kk = 0; kk < 4; kk++){
                int k = kq*4 + kk;
                if (row < 128) g_kp[bp*4096 + k*128 + row] = acc[i][kk];
                else           g_vp[bp*6144 + k*192 + (row-128)] = acc[i][kk];
            }
        }
    }
}

// ---- attention: grid 512, 256 thr, 95872 B dyn smem ----
__global__ void attn_kernel(const float* __restrict__ lnqw, const float* __restrict__ lnqb,
                            const float* __restrict__ Wq, const float* __restrict__ vw,
                            const float* __restrict__ out_w, const float* __restrict__ out_b,
                            const float* __restrict__ lnow, const float* __restrict__ lnob,
                            float* __restrict__ out){
    extern __shared__ float sm[];
    float* s_qn  = sm;
    float* s_w   = sm + 6176;
    float* s_kp  = sm + 12512;
    float* s_e   = sm + 16736;
    float* s_ctx = sm + 17792;
    int bp = blockIdx.x >> 3;
    int q0 = (blockIdx.x & 7) << 5;
    int t = threadIdx.x;
    int w = t >> 5, l = t & 31;
    const float* y3 = g_y3 + bp*49152;
    for (int e = t; e < 6144; e += 256){
        int m = e >> 5, q = e & 31;
        s_qn[q*193 + m] = y3[m*256 + q0 + q];
    }
    for (int e = t; e < 4096; e += 256){
        int k = e >> 7;
        s_kp[k*132 + (e & 127)] = g_kp[bp*4096 + e];
    }
    __syncthreads();
    {
        float lwv[6], lbv[6];
        #pragma unroll
        for (int i = 0; i < 6; i++){ lwv[i] = lnqw[l+32*i]; lbv[i] = lnqb[l+32*i]; }
        for (int qi = 0; qi < 4; qi++){
            int q = w*4 + qi;
            float v[6]; float s = 0.f;
            #pragma unroll
            for (int i = 0; i < 6; i++){ v[i] = s_qn[q*193 + l + 32*i]; s += v[i]; }
            #pragma unroll
            for (int o = 16; o > 0; o >>= 1) s += __shfl_xor_sync(0xffffffffu, s, o);
            float mu = s * (1.f/192.f);
            float vs = 0.f;
            #pragma unroll
            for (int i = 0; i < 6; i++){ float d = v[i]-mu; vs += d*d; }
            #pragma unroll
            for (int o = 16; o > 0; o >>= 1) vs += __shfl_xor_sync(0xffffffffu, vs, o);
            float rs = rsqrtf(vs * (1.f/192.f) + LN_EPS);
            #pragma unroll
            for (int i = 0; i < 6; i++)
                s_qn[q*193 + l + 32*i] = (v[i]-mu)*rs*lwv[i] + lbv[i];
        }
    }
    float qp[4][4];
    #pragma unroll
    for (int a = 0; a < 4; a++)
        #pragma unroll
        for (int b2 = 0; b2 < 4; b2++) qp[a][b2] = 0.f;
    for (int c0 = 0; c0 < 192; c0 += 32){
        __syncthreads();
        for (int e = t; e < 4096; e += 256){
            int d = e >> 5, cc = e & 31;
            s_w[d*33 + cc] = Wq[d*192 + c0 + cc];
        }
        __syncthreads();
        for (int cc = 0; cc < 32; cc++){
            float wv[4], qv[4];
            #pragma unroll
            for (int j = 0; j < 4; j++) wv[j] = s_w[(l+32*j)*33 + cc];
            #pragma unroll
            for (int qi = 0; qi < 4; qi++) qv[qi] = s_qn[(w*4+qi)*193 + c0 + cc];
            #pragma unroll
            for (int qi = 0; qi < 4; qi++)
                #pragma unroll
                for (int j = 0; j < 4; j++) qp[qi][j] = fmaf(qv[qi], wv[j], qp[qi][j]);
        }
    }
    __syncthreads();
    float* s_vp = s_w;
    for (int e = t; e < 6144; e += 256){
        int k = e / 192, m = e - k*192;
        s_vp[k*193 + m] = g_vp[bp*6144 + e];
    }
    float vv[4];
    #pragma unroll
    for (int j = 0; j < 4; j++) vv[j] = vw[l + 32*j];
    for (int k = 0; k < 32; k++){
        float kp4[4];
        #pragma unroll
        for (int j = 0; j < 4; j++) kp4[j] = s_kp[k*132 + l + 32*j];
        #pragma unroll
        for (int qi = 0; qi < 4; qi++){
            float s = 0.f;
            #pragma unroll
            for (int j = 0; j < 4; j++)
                s = fmaf(tanh_fast(qp[qi][j] + kp4[j]), vv[j], s);
            #pragma unroll
            for (int o = 16; o > 0; o >>= 1) s += __shfl_xor_sync(0xffffffffu, s, o);
            if (l == 0) s_e[(w*4+qi)*33 + k] = s;
        }
    }
    __syncwarp();
    for (int qi = 0; qi < 4; qi++){
        int q = w*4 + qi;
        float ev = s_e[q*33 + l];
        float mx = ev;
        #pragma unroll
        for (int o = 16; o > 0; o >>= 1) mx = fmaxf(mx, __shfl_xor_sync(0xffffffffu, mx, o));
        float p = __expf(ev - mx);
        float s = p;
        #pragma unroll
        for (int o = 16; o > 0; o >>= 1) s += __shfl_xor_sync(0xffffffffu, s, o);
        s_e[q*33 + l] = p / s;
    }
    __syncthreads();
    {
        int qr = t >> 3, mg = t & 7;
        float acc[24];
        #pragma unroll
        for (int i = 0; i < 24; i++) acc[i] = 0.f;
        for (int k = 0; k < 32; k++){
            float a = s_e[qr*33 + k];
            #pragma unroll
            for (int i = 0; i < 24; i++)
                acc[i] = fmaf(a, s_vp[k*193 + mg + 8*i], acc[i]);
        }
        #pragma unroll
        for (int i = 0; i < 24; i++) s_ctx[qr*193 + mg + 8*i] = acc[i];
    }
    __syncthreads();
    {
        int qh = t >> 4, ng = t & 15;
        float acc0[12], acc1[12];
        #pragma unroll
        for (int i = 0; i < 12; i++){ acc0[i] = 0.f; acc1[i] = 0.f; }
        for (int m0 = 0; m0 < 192; m0 += 32){
            __syncthreads();
            for (int e = t; e < 6144; e += 256){
                int n = e >> 5, mm = e & 31;
                s_w[n*33 + mm] = out_w[n*192 + m0 + mm];
            }
            __syncthreads();
            for (int mm = 0; mm < 32; mm++){
                float c0v = s_ctx[(2*qh)*193 + m0 + mm];
                float c1v = s_ctx[(2*qh+1)*193 + m0 + mm];
                #pragma unroll
                for (int i = 0; i < 12; i++){
                    float wv = s_w[(ng+16*i)*33 + mm];
                    acc0[i] = fmaf(c0v, wv, acc0[i]);
                    acc1[i] = fmaf(c1v, wv, acc1[i]);
                }
            }
        }
        float val0[12], val1[12];
        float s0 = 0.f, s1 = 0.f;
        #pragma unroll
        for (int i = 0; i < 12; i++){
            int n = ng + 16*i;
            val0[i] = acc0[i] + out_b[n] + s_qn[(2*qh)*193 + n];
            val1[i] = acc1[i] + out_b[n] + s_qn[(2*qh+1)*193 + n];
            s0 += val0[i]; s1 += val1[i];
        }
        #pragma unroll
        for (int o = 8; o > 0; o >>= 1){
            s0 += __shfl_xor_sync(0xffffffffu, s0, o);
            s1 += __shfl_xor_sync(0xffffffffu, s1, o);
        }
        float mu0 = s0*(1.f/192.f), mu1 = s1*(1.f/192.f);
        float vs0 = 0.f, vs1 = 0.f;
        #pragma unroll
        for (int i = 0; i < 12; i++){
            float d0 = val0[i]-mu0, d1 = val1[i]-mu1;
            vs0 += d0*d0; vs1 += d1*d1;
        }
        #pragma unroll
        for (int o = 8; o > 0; o >>= 1){
            vs0 += __shfl_xor_sync(0xffffffffu, vs0, o);
            vs1 += __shfl_xor_sync(0xffffffffu, vs1, o);
        }
        float r0 = rsqrtf(vs0*(1.f/192.f) + LN_EPS);
        float r1 = rsqrtf(vs1*(1.f/192.f) + LN_EPS);
        __syncthreads();
        #pragma unroll
        for (int i = 0; i < 12; i++){
            int n = ng + 16*i;
            s_ctx[(2*qh)*193 + n]   = (val0[i]-mu0)*r0*lnow[n] + lnob[n];
            s_ctx[(2*qh+1)*193 + n] = (val1[i]-mu1)*r1*lnow[n] + lnob[n];
        }
    }
    __syncthreads();
    for (int e = t; e < 6144; e += 256){
        int n = e >> 5, q = e & 31;
        out[bp*49152 + n*256 + q0 + q] = s_ctx[q*193 + n];
    }
}

extern "C" void kernel_launch(void* const* d_in, const int* in_sizes, int n_in,
                              void* d_out, int out_size){
    const float* x_p    = (const float*)d_in[0];
    const float* y_g    = (const float*)d_in[1];
    const float* conv1w = (const float*)d_in[2];
    const float* conv1b = (const float*)d_in[3];
    const float* gamma1 = (const float*)d_in[4];
    const float* beta1  = (const float*)d_in[5];
    const float* conv2w = (const float*)d_in[6];
    const float* conv2b = (const float*)d_in[7];
    const float* gamma2 = (const float*)d_in[8];
    const float* beta2  = (const float*)d_in[9];
    const float* conv3w = (const float*)d_in[10];
    const float* conv3b = (const float*)d_in[11];
    const float* lnqw   = (const float*)d_in[12];
    const float* lnqb   = (const float*)d_in[13];
    const float* lnkw   = (const float*)d_in[14];
    const float* lnkb   = (const float*)d_in[15];
    const float* lnow   = (const float*)d_in[16];
    const float* lnob   = (const float*)d_in[17];
    const float* Wq     = (const float*)d_in[18];
    const float* Wk     = (const float*)d_in[19];
    const float* vw     = (const float*)d_in[20];
    const float* Wv     = (const float*)d_in[21];
    const float* outw   = (const float*)d_in[22];
    const float* outb   = (const float*)d_in[23];
    float* out = (float*)d_out;

    cudaFuncSetAttribute(attn_kernel, cudaFuncAttributeMaxDynamicSharedMemorySize, 98304);
    cudaFuncSetAttribute(conv2gemm_kernel, cudaFuncAttributeMaxDynamicSharedMemorySize, 55296);
    cudaFuncSetAttribute(conv3gemm_kernel, cudaFuncAttributeMaxDynamicSharedMemorySize, 73728);

    conv1_kernel<<<dim3(64,4,2), 256>>>(x_p, conv1w, conv1b, gamma1, gamma2);  // 0
    gdn_kernel<<<1024, 256>>>(1, beta1, conv2w, conv3w);                        // 1
    im2col2_kernel<<<dim3(800,64), 256>>>();                                    // 2
    conv2gemm_kernel<<<dim3(64,4), 256, 55296>>>(conv2b);                       // 3 (profiled)
    gdn_kernel<<<256, 256>>>(2, beta2, nullptr, nullptr);                       // 4
    im2col3_kernel<<<dim3(288,64), 256>>>();                                    // 5
    conv3gemm_kernel<<<dim3(64,4), 384, 73728>>>(conv3b);                       // 6
    kv_kernel<<<dim3(64,5), 256>>>(y_g, lnkw, lnkb, Wk, Wv);                    // 7
    attn_kernel<<<512, 256, 95872>>>(lnqw, lnqb, Wq, vw, outw, outb, lnow, lnob, out);
}

// round 11
// speedup vs baseline: 2.3760x; 1.0087x over previous
#include <cuda_runtime.h>

#define LN_EPS 1e-5f
typedef unsigned long long ull;

// ---- scratch ----
__device__ float g_s1[64*128*1024];
__device__ float g_s2[64*128*256];
__device__ float g_y3[64*192*256];
__device__ float g_kp[64*32*128];
__device__ float g_vp[64*32*192];
__device__ float g_gT[2][16384];
__device__ unsigned g_xcol[64*3200*256];
__device__ unsigned g_x3col[64*1152*256];
__device__ unsigned g_w2tf[128*3200];
__device__ unsigned g_w3tf[192*1152];

__device__ __forceinline__ float tanh_fast(float x){
    float y; asm("tanh.approx.f32 %0, %1;" : "=f"(y) : "f"(x)); return y;
}
__device__ __forceinline__ ull pk2(float lo, float hi){
    ull r; asm("mov.b64 %0, {%1, %2};" : "=l"(r) : "f"(lo), "f"(hi)); return r;
}
__device__ __forceinline__ ull pkdup(float v){ return pk2(v, v); }
__device__ __forceinline__ void upk2(ull p, float& lo, float& hi){
    asm("mov.b64 {%0, %1}, %2;" : "=f"(lo), "=f"(hi) : "l"(p));
}
__device__ __forceinline__ ull ffma2(ull a, ull b, ull c){
    ull d; asm("fma.rn.f32x2 %0, %1, %2, %3;" : "=l"(d) : "l"(a), "l"(b), "l"(c)); return d;
}
__device__ __forceinline__ unsigned f2tf(float f){
    unsigned t; asm("cvt.rna.tf32.f32 %0, %1;" : "=r"(t) : "f"(f)); return t;
}
__device__ __forceinline__ void cp16(unsigned* sp, const unsigned* gp){
    unsigned sa = (unsigned)__cvta_generic_to_shared(sp);
    asm volatile("cp.async.cg.shared.global [%0], [%1], 16;" :: "r"(sa), "l"(gp));
}

// ---- conv1 (+ gamma transpose fold): grid (64,4,2), 256 thr ----
__global__ void conv1_kernel(const float* __restrict__ x, const float* __restrict__ w,
                             const float* __restrict__ b, const float* __restrict__ g1,
                             const float* __restrict__ g2){
    __shared__ float sw[4800];
    __shared__ float sin_[3885];
    int bp = blockIdx.x, tile = blockIdx.y, z = blockIdx.z;
    int t = threadIdx.x;
    if (z == 0){
        int blk = bp*4 + tile;
        for (int i = t; i < 128; i += 256){
            int e = blk*128 + i;
            int which = e >> 14, idx = e & 16383;
            const float* g = which ? g2 : g1;
            g_gT[which][(idx & 127)*128 + (idx >> 7)] = g[idx];
        }
    }
    for (int e = t; e < 4800; e += 256) sw[e] = w[z*4800 + e];
    int ty0 = (tile>>1)*16, tx0 = (tile&1)*16;
    int iy0 = 2*ty0 - 2, ix0 = 2*tx0 - 2;
    const float* xb = x + bp*12288;
    for (int e = t; e < 3675; e += 256){
        int c = e/1225, rem = e - c*1225, r = rem/35, col = rem - r*35;
        int gy = iy0 + r, gx = ix0 + col;
        float v = 0.f;
        if (gy>=0 && gy<64 && gx>=0 && gx<64) v = xb[c*4096 + gy*64 + gx];
        sin_[(c*35 + r)*37 + col] = v;
    }
    __syncthreads();
    int px4 = t & 63, cog = t >> 6;
    int ly = px4 >> 2, lx0 = (px4 & 3)*4;
    float* ob = g_s1 + bp*131072;
    for (int p = 0; p < 2; p++){
        int col0 = cog*16 + p*8;
        float acc[8][4];
        #pragma unroll
        for (int i = 0; i < 8; i++){
            float bb = b[z*64 + col0 + i];
            #pragma unroll
            for (int j = 0; j < 4; j++) acc[i][j] = bb;
        }
        #pragma unroll 1
        for (int c = 0; c < 3; c++){
            #pragma unroll
            for (int ky = 0; ky < 5; ky++){
                #pragma unroll
                for (int kx = 0; kx < 5; kx++){
                    float xv[4];
                    #pragma unroll
                    for (int j = 0; j < 4; j++)
                        xv[j] = sin_[(c*35 + 2*ly + ky)*37 + 2*lx0 + 2*j + kx];
                    #pragma unroll
                    for (int i = 0; i < 8; i++){
                        float wv = sw[(col0+i)*75 + c*25 + ky*5 + kx];
                        #pragma unroll
                        for (int j = 0; j < 4; j++) acc[i][j] = fmaf(wv, xv[j], acc[i][j]);
                    }
                }
            }
        }
        #pragma unroll
        for (int i = 0; i < 8; i++){
            float4 o = make_float4(acc[i][0], acc[i][1], acc[i][2], acc[i][3]);
            *reinterpret_cast<float4*>(ob + (z*64+col0+i)*1024 + (ty0+ly)*32 + tx0 + lx0) = o;
        }
    }
}

// ---- GDN in-place (f32x2) + W tf32-convert fold on stage 1 ----
__global__ void gdn_kernel(int stage, const float* __restrict__ beta,
                           const float* __restrict__ w2, const float* __restrict__ w3){
    __shared__ float sA[2048];
    __shared__ float sB[1088];
    int HW = (stage == 1) ? 1024 : 256;
    float* x = (stage == 1) ? g_s1 : g_s2;
    const float* gT = g_gT[stage-1];
    int chunks = HW >> 6;
    int bp = blockIdx.x / chunks;
    int p0 = (blockIdx.x - bp*chunks) * 64;
    int t = threadIdx.x;
    if (stage == 1){
        int base2 = blockIdx.x * 400;
        for (int i = t; i < 400; i += 256) g_w2tf[base2 + i] = f2tf(w2[base2 + i]);
        int base3 = blockIdx.x * 216;
        for (int i = t; i < 216; i += 256) g_w3tf[base3 + i] = f2tf(w3[base3 + i]);
    }
    int i = t >> 4, j = t & 15;
    float* xb = x + bp*128*HW;
    ull acc[8][2];
    #pragma unroll
    for (int ii = 0; ii < 8; ii++){
        float bb = beta[i*8 + ii];
        acc[ii][0] = pkdup(bb); acc[ii][1] = pkdup(bb);
    }
    for (int c0 = 0; c0 < 128; c0 += 16){
        __syncthreads();
        for (int e = t; e < 2048; e += 256) sA[e] = gT[c0*128 + e];
        for (int e = t; e < 1024; e += 256){
            int cc = e >> 6, p = e & 63;
            float v = xb[(c0+cc)*HW + p0 + p];
            sB[cc*68 + p] = v*v;
        }
        __syncthreads();
        #pragma unroll
        for (int cc = 0; cc < 16; cc++){
            const ull* xp = reinterpret_cast<const ull*>(sB + cc*68 + j*4);
            ull x0 = xp[0], x1 = xp[1];
            float4 ga = *reinterpret_cast<const float4*>(sA + cc*128 + i*8);
            float4 gb = *reinterpret_cast<const float4*>(sA + cc*128 + i*8 + 4);
            float gs[8] = {ga.x,ga.y,ga.z,ga.w,gb.x,gb.y,gb.z,gb.w};
            #pragma unroll
            for (int ii = 0; ii < 8; ii++){
                ull wp = pkdup(gs[ii]);
                acc[ii][0] = ffma2(x0, wp, acc[ii][0]);
                acc[ii][1] = ffma2(x1, wp, acc[ii][1]);
            }
        }
    }
    #pragma unroll
    for (int ii = 0; ii < 8; ii++){
        int d = i*8 + ii;
        float a0,a1,a2,a3;
        upk2(acc[ii][0], a0, a1);
        upk2(acc[ii][1], a2, a3);
        float4 xv = *reinterpret_cast<const float4*>(xb + d*HW + p0 + j*4);
        float4 o;
        o.x = xv.x * rsqrtf(a0);
        o.y = xv.y * rsqrtf(a1);
        o.z = xv.z * rsqrtf(a2);
        o.w = xv.w * rsqrtf(a3);
        *reinterpret_cast<float4*>(xb + d*HW + p0 + j*4) = o;
    }
}

// ---- conv2 im2col (tf32 out): grid (800,64), 256 thr ----
__global__ void im2col2_kernel(){
    int bp = blockIdx.y;
    int t = threadIdx.x;
    int oy = t >> 4, ox = t & 15;
    const float* xb = g_s1 + bp*131072;
    unsigned* xc = g_xcol + bp*819200;
    #pragma unroll 1
    for (int kk = 0; kk < 4; kk++){
        int k = blockIdx.x*4 + kk;
        int ci = k / 25, r = k - ci*25;
        int ky = r / 5, kx = r - ky*5;
        int iy = 2*oy - 2 + ky, ix = 2*ox - 2 + kx;
        float v = 0.f;
        if (iy>=0 && iy<32 && ix>=0 && ix<32) v = xb[ci*1024 + iy*32 + ix];
        xc[k*256 + t] = f2tf(v);
    }
}

// ---- conv3 im2col (tf32 out): grid (288,64), 256 thr ----
__global__ void im2col3_kernel(){
    int bp = blockIdx.y;
    int t = threadIdx.x;
    int oy = t >> 4, ox = t & 15;
    const float* xb = g_s2 + bp*32768;
    unsigned* xc = g_x3col + bp*294912;
    #pragma unroll 1
    for (int kk = 0; kk < 4; kk++){
        int k = blockIdx.x*4 + kk;
        int ci = k / 9, r = k - ci*9;
        int ky = r / 3, kx = r - ky*3;
        int iy = oy - 1 + ky, ix = ox - 1 + kx;
        float v = 0.f;
        if (iy>=0 && iy<16 && ix>=0 && ix<16) v = xb[ci*256 + iy*16 + ix];
        xc[k*256 + t] = f2tf(v);
    }
}

// ---- conv2 GEMM, 3-stage cp.async pipeline. grid (64,4), 256 thr, 82944 B dyn ----
__global__ void __launch_bounds__(256) conv2gemm_kernel(const float* __restrict__ bias){
    extern __shared__ unsigned smu[];
    // W bufs: [0,4608),[4608,9216),[9216,13824); X bufs at 13824 + buf*2304
    int bp = blockIdx.x, n0b = blockIdx.y * 64;
    int t = threadIdx.x;
    int warp = t >> 5, lane = t & 31;
    int g = lane >> 2, tig = lane & 3;
    int m0 = (warp >> 1) * 32;
    int n0 = (warp & 1) * 32;
    float c[2][4][4];
    #pragma unroll
    for (int mt = 0; mt < 2; mt++)
        #pragma unroll
        for (int nt = 0; nt < 4; nt++)
            #pragma unroll
            for (int q = 0; q < 4; q++) c[mt][nt][q] = 0.f;
    const unsigned* xcb = g_xcol + bp*819200 + n0b;

    auto stage = [&](int kc, int buf){
        unsigned* dW = smu + buf*4608;
        unsigned* dX = smu + 13824 + buf*2304;
        #pragma unroll
        for (int s = 0; s < 4; s++){
            int e = t + s*256;
            int co = e >> 3, ks = (e & 7) * 4;
            cp16(&dW[co*36 + ks], &g_w2tf[co*3200 + kc + ks]);
        }
        #pragma unroll
        for (int s = 0; s < 2; s++){
            int e = t + s*256;
            int kk = e >> 4, ps = (e & 15) * 4;
            cp16(&dX[kk*72 + ps], &xcb[(kc + kk)*256 + ps]);
        }
        asm volatile("cp.async.commit_group;" ::);
    };

    stage(0, 0);
    stage(32, 1);
    for (int it = 0; it < 100; it++){
        if (it + 2 < 100) stage((it+2)*32, (it+2) % 3);
        if (it <= 97)      asm volatile("cp.async.wait_group 2;" ::);
        else if (it == 98) asm volatile("cp.async.wait_group 1;" ::);
        else               asm volatile("cp.async.wait_group 0;" ::);
        __syncthreads();
        const unsigned* dW = smu + (it % 3)*4608;
        const unsigned* dX = smu + 13824 + (it % 3)*2304;
        #pragma unroll
        for (int ks = 0; ks < 4; ks++){
            int k0 = ks*8;
            unsigned a[2][4], bb[4][2];
            #pragma unroll
            for (int mt = 0; mt < 2; mt++){
                int m = m0 + mt*16;
                a[mt][0] = dW[(m+g)*36 + k0 + tig];
                a[mt][1] = dW[(m+g+8)*36 + k0 + tig];
                a[mt][2] = dW[(m+g)*36 + k0 + tig + 4];
                a[mt][3] = dW[(m+g+8)*36 + k0 + tig + 4];
            }
            #pragma unroll
            for (int nt = 0; nt < 4; nt++){
                int n = n0 + nt*8;
                bb[nt][0] = dX[(k0+tig)*72 + n + g];
                bb[nt][1] = dX[(k0+tig+4)*72 + n + g];
            }
            #pragma unroll
            for (int mt = 0; mt < 2; mt++)
                #pragma unroll
                for (int nt = 0; nt < 4; nt++)
                    asm volatile(
                        "mma.sync.aligned.m16n8k8.row.col.f32.tf32.tf32.f32 "
                        "{%0,%1,%2,%3}, {%4,%5,%6,%7}, {%8,%9}, {%0,%1,%2,%3};"
                        : "+f"(c[mt][nt][0]), "+f"(c[mt][nt][1]),
                          "+f"(c[mt][nt][2]), "+f"(c[mt][nt][3])
                        : "r"(a[mt][0]), "r"(a[mt][1]), "r"(a[mt][2]), "r"(a[mt][3]),
                          "r"(bb[nt][0]), "r"(bb[nt][1]));
        }
        __syncthreads();
    }
    float* ob = g_s2 + bp*32768;
    #pragma unroll
    for (int mt = 0; mt < 2; mt++){
        int coA = m0 + mt*16 + g;
        int coB = coA + 8;
        float bA = bias[coA], bB = bias[coB];
        #pragma unroll
        for (int nt = 0; nt < 4; nt++){
            int px = n0b + n0 + nt*8 + 2*tig;
            *reinterpret_cast<float2*>(ob + coA*256 + px) =
                make_float2(c[mt][nt][0] + bA, c[mt][nt][1] + bA);
            *reinterpret_cast<float2*>(ob + coB*256 + px) =
                make_float2(c[mt][nt][2] + bB, c[mt][nt][3] + bB);
        }
    }
}

// ---- conv3 GEMM, 3-stage cp.async pipeline. grid (64,4), 384 thr, 110592 B dyn ----
__global__ void __launch_bounds__(384) conv3gemm_kernel(const float* __restrict__ bias){
    extern __shared__ unsigned smu3[];
    // W bufs: buf*6912 (3 bufs, 20736); X bufs at 20736 + buf*2304
    int bp = blockIdx.x, n0b = blockIdx.y * 64;
    int t = threadIdx.x;
    int warp = t >> 5, lane = t & 31;
    int g = lane >> 2, tig = lane & 3;
    int m0 = (warp >> 1) * 32;
    int n0 = (warp & 1) * 32;
    float c[2][4][4];
    #pragma unroll
    for (int mt = 0; mt < 2; mt++)
        #pragma unroll
        for (int nt = 0; nt < 4; nt++)
            #pragma unroll
            for (int q = 0; q < 4; q++) c[mt][nt][q] = 0.f;
    const unsigned* xcb = g_x3col + bp*294912 + n0b;

    auto stage = [&](int kc, int buf){
        unsigned* dW = smu3 + buf*6912;
        unsigned* dX = smu3 + 20736 + buf*2304;
        for (int e = t; e < 1536; e += 384){
            int co = e >> 3, ks = (e & 7) * 4;
            cp16(&dW[co*36 + ks], &g_w3tf[co*1152 + kc + ks]);
        }
        for (int e = t; e < 512; e += 384){
            int kk = e >> 4, ps = (e & 15) * 4;
            cp16(&dX[kk*72 + ps], &xcb[(kc + kk)*256 + ps]);
        }
        asm volatile("cp.async.commit_group;" ::);
    };

    stage(0, 0);
    stage(32, 1);
    for (int it = 0; it < 36; it++){
        if (it + 2 < 36) stage((it+2)*32, (it+2) % 3);
        if (it <= 33)      asm volatile("cp.async.wait_group 2;" ::);
        else if (it == 34) asm volatile("cp.async.wait_group 1;" ::);
        else               asm volatile("cp.async.wait_group 0;" ::);
        __syncthreads();
        const unsigned* dW = smu3 + (it % 3)*6912;
        const unsigned* dX = smu3 + 20736 + (it % 3)*2304;
        #pragma unroll
        for (int ks = 0; ks < 4; ks++){
            int k0 = ks*8;
            unsigned a[2][4], bb[4][2];
            #pragma unroll
            for (int mt = 0; mt < 2; mt++){
                int m = m0 + mt*16;
                a[mt][0] = dW[(m+g)*36 + k0 + tig];
                a[mt][1] = dW[(m+g+8)*36 + k0 + tig];
                a[mt][2] = dW[(m+g)*36 + k0 + tig + 4];
                a[mt][3] = dW[(m+g+8)*36 + k0 + tig + 4];
            }
            #pragma unroll
            for (int nt = 0; nt < 4; nt++){
                int n = n0 + nt*8;
                bb[nt][0] = dX[(k0+tig)*72 + n + g];
                bb[nt][1] = dX[(k0+tig+4)*72 + n + g];
            }
            #pragma unroll
            for (int mt = 0; mt < 2; mt++)
                #pragma unroll
                for (int nt = 0; nt < 4; nt++)
                    asm volatile(
                        "mma.sync.aligned.m16n8k8.row.col.f32.tf32.tf32.f32 "
                        "{%0,%1,%2,%3}, {%4,%5,%6,%7}, {%8,%9}, {%0,%1,%2,%3};"
                        : "+f"(c[mt][nt][0]), "+f"(c[mt][nt][1]),
                          "+f"(c[mt][nt][2]), "+f"(c[mt][nt][3])
                        : "r"(a[mt][0]), "r"(a[mt][1]), "r"(a[mt][2]), "r"(a[mt][3]),
                          "r"(bb[nt][0]), "r"(bb[nt][1]));
        }
        __syncthreads();
    }
    float* ob = g_y3 + bp*49152;
    #pragma unroll
    for (int mt = 0; mt < 2; mt++){
        int coA = m0 + mt*16 + g;
        int coB = coA + 8;
        float bA = bias[coA], bB = bias[coB];
        #pragma unroll
        for (int nt = 0; nt < 4; nt++){
            int px = n0b + n0 + nt*8 + 2*tig;
            *reinterpret_cast<float2*>(ob + coA*256 + px) =
                make_float2(c[mt][nt][0] + bA, c[mt][nt][1] + bA);
            *reinterpret_cast<float2*>(ob + coB*256 + px) =
                make_float2(c[mt][nt][2] + bB, c[mt][nt][3] + bB);
        }
    }
}

// ---- kv: LN + k_proj + v_proj. grid (64,5), 256 thr ----
__global__ void kv_kernel(const float* __restrict__ yg, const float* __restrict__ lnw,
                          const float* __restrict__ lnb, const float* __restrict__ Wk,
                          const float* __restrict__ Wv){
    __shared__ float s_kv[32*193];
    __shared__ float s_w[64*33];
    int bp = blockIdx.x;
    int r0 = blockIdx.y * 64;
    int t = threadIdx.x;
    int w = t >> 5, l = t & 31;
    for (int e = t; e < 6144; e += 256){
        int c = e >> 5, k = e & 31;
        s_kv[k*193 + c] = yg[bp*6144 + c*32 + k];
    }
    __syncthreads();
    {
        float lwv[6], lbv[6];
        #pragma unroll
        for (int i = 0; i < 6; i++){ lwv[i] = lnw[l+32*i]; lbv[i] = lnb[l+32*i]; }
        for (int ki = 0; ki < 4; ki++){
            int k = w*4 + ki;
            float v[6]; float s = 0.f;
            #pragma unroll
            for (int i = 0; i < 6; i++){ v[i] = s_kv[k*193 + l + 32*i]; s += v[i]; }
            #pragma unroll
            for (int o = 16; o > 0; o >>= 1) s += __shfl_xor_sync(0xffffffffu, s, o);
            float mu = s * (1.f/192.f);
            float vs = 0.f;
            #pragma unroll
            for (int i = 0; i < 6; i++){ float d = v[i]-mu; vs += d*d; }
            #pragma unroll
            for (int o = 16; o > 0; o >>= 1) vs += __shfl_xor_sync(0xffffffffu, vs, o);
            float rs = rsqrtf(vs * (1.f/192.f) + LN_EPS);
            #pragma unroll
            for (int i = 0; i < 6; i++)
                s_kv[k*193 + l + 32*i] = (v[i]-mu)*rs*lwv[i] + lbv[i];
        }
    }
    int kq = t & 7, rp = t >> 3;
    {
        float acc[2][4];
        #pragma unroll
        for (int i = 0; i < 2; i++)
            #pragma unroll
            for (int kk = 0; kk < 4; kk++) acc[i][kk] = 0.f;
        for (int c0 = 0; c0 < 192; c0 += 32){
            __syncthreads();
            for (int e = t; e < 2048; e += 256){
                int rr = e >> 5, cc = e & 31;
                int row = r0 + rr;
                s_w[rr*33 + cc] = (row < 128) ? Wk[row*192 + c0 + cc]
                                              : Wv[(row-128)*192 + c0 + cc];
            }
            __syncthreads();
            for (int cc = 0; cc < 32; cc++){
                float wv0 = s_w[(rp*2)*33 + cc], wv1 = s_w[(rp*2+1)*33 + cc];
                #pragma unroll
                for (int kk = 0; kk < 4; kk++){
                    float kvv = s_kv[(kq*4+kk)*193 + c0 + cc];
                    acc[0][kk] = fmaf(wv0, kvv, acc[0][kk]);
                    acc[1][kk] = fmaf(wv1, kvv, acc[1][kk]);
                }
            }
        }
        #pragma unroll
        for (int i = 0; i < 2; i++){
            int row = r0 + rp*2 + i;
            #pragma unroll
            for (int kk = 0; kk < 4; kk++){
                int k = kq*4 + kk;
                if (row < 128) g_kp[bp*4096 + k*128 + row] = acc[i][kk];
                else           g_vp[bp*6144 + k*192 + (row-128)] = acc[i][kk];
            }
        }
    }
}

// ---- attention: grid 512, 256 thr, 95872 B dyn smem ----
__global__ void attn_kernel(const float* __restrict__ lnqw, const float* __restrict__ lnqb,
                            const float* __restrict__ Wq, const float* __restrict__ vw,
                            const float* __restrict__ out_w, const float* __restrict__ out_b,
                            const float* __restrict__ lnow, const float* __restrict__ lnob,
                            float* __restrict__ out){
    extern __shared__ float sm[];
    float* s_qn  = sm;
    float* s_w   = sm + 6176;
    float* s_kp  = sm + 12512;
    float* s_e   = sm + 16736;
    float* s_ctx = sm + 17792;
    int bp = blockIdx.x >> 3;
    int q0 = (blockIdx.x & 7) << 5;
    int t = threadIdx.x;
    int w = t >> 5, l = t & 31;
    const float* y3 = g_y3 + bp*49152;
    for (int e = t; e < 6144; e += 256){
        int m = e >> 5, q = e & 31;
        s_qn[q*193 + m] = y3[m*256 + q0 + q];
    }
    for (int e = t; e < 4096; e += 256){
        int k = e >> 7;
        s_kp[k*132 + (e & 127)] = g_kp[bp*4096 + e];
    }
    __syncthreads();
    {
        float lwv[6], lbv[6];
        #pragma unroll
        for (int i = 0; i < 6; i++){ lwv[i] = lnqw[l+32*i]; lbv[i] = lnqb[l+32*i]; }
        for (int qi = 0; qi < 4; qi++){
            int q = w*4 + qi;
            float v[6]; float s = 0.f;
            #pragma unroll
            for (int i = 0; i < 6; i++){ v[i] = s_qn[q*193 + l + 32*i]; s += v[i]; }
            #pragma unroll
            for (int o = 16; o > 0; o >>= 1) s += __shfl_xor_sync(0xffffffffu, s, o);
            float mu = s * (1.f/192.f);
            float vs = 0.f;
            #pragma unroll
            for (int i = 0; i < 6; i++){ float d = v[i]-mu; vs += d*d; }
            #pragma unroll
            for (int o = 16; o > 0; o >>= 1) vs += __shfl_xor_sync(0xffffffffu, vs, o);
            float rs = rsqrtf(vs * (1.f/192.f) + LN_EPS);
            #pragma unroll
            for (int i = 0; i < 6; i++)
                s_qn[q*193 + l + 32*i] = (v[i]-mu)*rs*lwv[i] + lbv[i];
        }
    }
    float qp[4][4];
    #pragma unroll
    for (int a = 0; a < 4; a++)
        #pragma unroll
        for (int b2 = 0; b2 < 4; b2++) qp[a][b2] = 0.f;
    for (int c0 = 0; c0 < 192; c0 += 32){
        __syncthreads();
        for (int e = t; e < 4096; e += 256){
            int d = e >> 5, cc = e & 31;
            s_w[d*33 + cc] = Wq[d*192 + c0 + cc];
        }
        __syncthreads();
        for (int cc = 0; cc < 32; cc++){
            float wv[4], qv[4];
            #pragma unroll
            for (int j = 0; j < 4; j++) wv[j] = s_w[(l+32*j)*33 + cc];
            #pragma unroll
            for (int qi = 0; qi < 4; qi++) qv[qi] = s_qn[(w*4+qi)*193 + c0 + cc];
            #pragma unroll
            for (int qi = 0; qi < 4; qi++)
                #pragma unroll
                for (int j = 0; j < 4; j++) qp[qi][j] = fmaf(qv[qi], wv[j], qp[qi][j]);
        }
    }
    __syncthreads();
    float* s_vp = s_w;
    for (int e = t; e < 6144; e += 256){
        int k = e / 192, m = e - k*192;
        s_vp[k*193 + m] = g_vp[bp*6144 + e];
    }
    float vv[4];
    #pragma unroll
    for (int j = 0; j < 4; j++) vv[j] = vw[l + 32*j];
    for (int k = 0; k < 32; k++){
        float kp4[4];
        #pragma unroll
        for (int j = 0; j < 4; j++) kp4[j] = s_kp[k*132 + l + 32*j];
        #pragma unroll
        for (int qi = 0; qi < 4; qi++){
            float s = 0.f;
            #pragma unroll
            for (int j = 0; j < 4; j++)
                s = fmaf(tanh_fast(qp[qi][j] + kp4[j]), vv[j], s);
            #pragma unroll
            for (int o = 16; o > 0; o >>= 1) s += __shfl_xor_sync(0xffffffffu, s, o);
            if (l == 0) s_e[(w*4+qi)*33 + k] = s;
        }
    }
    __syncwarp();
    for (int qi = 0; qi < 4; qi++){
        int q = w*4 + qi;
        float ev = s_e[q*33 + l];
        float mx = ev;
        #pragma unroll
        for (int o = 16; o > 0; o >>= 1) mx = fmaxf(mx, __shfl_xor_sync(0xffffffffu, mx, o));
        float p = __expf(ev - mx);
        float s = p;
        #pragma unroll
        for (int o = 16; o > 0; o >>= 1) s += __shfl_xor_sync(0xffffffffu, s, o);
        s_e[q*33 + l] = p / s;
    }
    __syncthreads();
    {
        int qr = t >> 3, mg = t & 7;
        float acc[24];
        #pragma unroll
        for (int i = 0; i < 24; i++) acc[i] = 0.f;
        for (int k = 0; k < 32; k++){
            float a = s_e[qr*33 + k];
            #pragma unroll
            for (int i = 0; i < 24; i++)
                acc[i] = fmaf(a, s_vp[k*193 + mg + 8*i], acc[i]);
        }
        #pragma unroll
        for (int i = 0; i < 24; i++) s_ctx[qr*193 + mg + 8*i] = acc[i];
    }
    __syncthreads();
    {
        int qh = t >> 4, ng = t & 15;
        float acc0[12], acc1[12];
        #pragma unroll
        for (int i = 0; i < 12; i++){ acc0[i] = 0.f; acc1[i] = 0.f; }
        for (int m0 = 0; m0 < 192; m0 += 32){
            __syncthreads();
            for (int e = t; e < 6144; e += 256){
                int n = e >> 5, mm = e & 31;
                s_w[n*33 + mm] = out_w[n*192 + m0 + mm];
            }
            __syncthreads();
            for (int mm = 0; mm < 32; mm++){
                float c0v = s_ctx[(2*qh)*193 + m0 + mm];
                float c1v = s_ctx[(2*qh+1)*193 + m0 + mm];
                #pragma unroll
                for (int i = 0; i < 12; i++){
                    float wv = s_w[(ng+16*i)*33 + mm];
                    acc0[i] = fmaf(c0v, wv, acc0[i]);
                    acc1[i] = fmaf(c1v, wv, acc1[i]);
                }
            }
        }
        float val0[12], val1[12];
        float s0 = 0.f, s1 = 0.f;
        #pragma unroll
        for (int i = 0; i < 12; i++){
            int n = ng + 16*i;
            val0[i] = acc0[i] + out_b[n] + s_qn[(2*qh)*193 + n];
            val1[i] = acc1[i] + out_b[n] + s_qn[(2*qh+1)*193 + n];
            s0 += val0[i]; s1 += val1[i];
        }
        #pragma unroll
        for (int o = 8; o > 0; o >>= 1){
            s0 += __shfl_xor_sync(0xffffffffu, s0, o);
            s1 += __shfl_xor_sync(0xffffffffu, s1, o);
        }
        float mu0 = s0*(1.f/192.f), mu1 = s1*(1.f/192.f);
        float vs0 = 0.f, vs1 = 0.f;
        #pragma unroll
        for (int i = 0; i < 12; i++){
            float d0 = val0[i]-mu0, d1 = val1[i]-mu1;
            vs0 += d0*d0; vs1 += d1*d1;
        }
        #pragma unroll
        for (int o = 8; o > 0; o >>= 1){
            vs0 += __shfl_xor_sync(0xffffffffu, vs0, o);
            vs1 += __shfl_xor_sync(0xffffffffu, vs1, o);
        }
        float r0 = rsqrtf(vs0*(1.f/192.f) + LN_EPS);
        float r1 = rsqrtf(vs1*(1.f/192.f) + LN_EPS);
        __syncthreads();
        #pragma unroll
        for (int i = 0; i < 12; i++){
            int n = ng + 16*i;
            s_ctx[(2*qh)*193 + n]   = (val0[i]-mu0)*r0*lnow[n] + lnob[n];
            s_ctx[(2*qh+1)*193 + n] = (val1[i]-mu1)*r1*lnow[n] + lnob[n];
        }
    }
    __syncthreads();
    for (int e = t; e < 6144; e += 256){
        int n = e >> 5, q = e & 31;
        out[bp*49152 + n*256 + q0 + q] = s_ctx[q*193 + n];
    }
}

extern "C" void kernel_launch(void* const* d_in, const int* in_sizes, int n_in,
                              void* d_out, int out_size){
    const float* x_p    = (const float*)d_in[0];
    const float* y_g    = (const float*)d_in[1];
    const float* conv1w = (const float*)d_in[2];
    const float* conv1b = (const float*)d_in[3];
    const float* gamma1 = (const float*)d_in[4];
    const float* beta1  = (const float*)d_in[5];
    const float* conv2w = (const float*)d_in[6];
    const float* conv2b = (const float*)d_in[7];
    const float* gamma2 = (const float*)d_in[8];
    const float* beta2  = (const float*)d_in[9];
    const float* conv3w = (const float*)d_in[10];
    const float* conv3b = (const float*)d_in[11];
    const float* lnqw   = (const float*)d_in[12];
    const float* lnqb   = (const float*)d_in[13];
    const float* lnkw   = (const float*)d_in[14];
    const float* lnkb   = (const float*)d_in[15];
    const float* lnow   = (const float*)d_in[16];
    const float* lnob   = (const float*)d_in[17];
    const float* Wq     = (const float*)d_in[18];
    const float* Wk     = (const float*)d_in[19];
    const float* vw     = (const float*)d_in[20];
    const float* Wv     = (const float*)d_in[21];
    const float* outw   = (const float*)d_in[22];
    const float* outb   = (const float*)d_in[23];
    float* out = (float*)d_out;

    cudaFuncSetAttribute(attn_kernel, cudaFuncAttributeMaxDynamicSharedMemorySize, 98304);
    cudaFuncSetAttribute(conv2gemm_kernel, cudaFuncAttributeMaxDynamicSharedMemorySize, 82944);
    cudaFuncSetAttribute(conv3gemm_kernel, cudaFuncAttributeMaxDynamicSharedMemorySize, 110592);

    conv1_kernel<<<dim3(64,4,2), 256>>>(x_p, conv1w, conv1b, gamma1, gamma2);  // 0
    gdn_kernel<<<1024, 256>>>(1, beta1, conv2w, conv3w);                        // 1
    im2col2_kernel<<<dim3(800,64), 256>>>();                                    // 2
    conv2gemm_kernel<<<dim3(64,4), 256, 82944>>>(conv2b);                       // 3 (profiled)
    gdn_kernel<<<256, 256>>>(2, beta2, nullptr, nullptr);                       // 4
    im2col3_kernel<<<dim3(288,64), 256>>>();                                    // 5
    conv3gemm_kernel<<<dim3(64,4), 384, 110592>>>(conv3b);                      // 6
    kv_kernel<<<dim3(64,5), 256>>>(y_g, lnkw, lnkb, Wk, Wv);                    // 7
    attn_kernel<<<512, 256, 95872>>>(lnqw, lnqb, Wq, vw, outw, outb, lnow, lnob, out);
}

// round 13
// speedup vs baseline: 2.8549x; 1.2016x over previous
#include <cuda_runtime.h>
#include <cuda_fp16.h>

#define LN_EPS 1e-5f
typedef unsigned long long ull;

// ---- scratch ----
__device__ float g_s1[64*128*1024];
__device__ float g_s2[64*128*256];
__device__ float g_y3[64*192*256];
__device__ float g_kp[64*32*128];
__device__ float g_vp[64*32*192];
__device__ float g_gT[2][16384];
__device__ unsigned g_xcolh[64*1600*256];
__device__ unsigned g_x3colh[64*576*256];
__device__ unsigned g_w2h[128*1600];
__device__ unsigned g_w3h[192*576];

__device__ __forceinline__ float tanh_fast(float x){
    float y; asm("tanh.approx.f32 %0, %1;" : "=f"(y) : "f"(x)); return y;
}
__device__ __forceinline__ ull pk2(float lo, float hi){
    ull r; asm("mov.b64 %0, {%1, %2};" : "=l"(r) : "f"(lo), "f"(hi)); return r;
}
__device__ __forceinline__ ull pkdup(float v){ return pk2(v, v); }
__device__ __forceinline__ void upk2(ull p, float& lo, float& hi){
    asm("mov.b64 {%0, %1}, %2;" : "=f"(lo), "=f"(hi) : "l"(p));
}
__device__ __forceinline__ ull ffma2(ull a, ull b, ull c){
    ull d; asm("fma.rn.f32x2 %0, %1, %2, %3;" : "=l"(d) : "l"(a), "l"(b), "l"(c)); return d;
}
__device__ __forceinline__ unsigned packh(float v0, float v1){
    __half h0 = __float2half_rn(v0), h1 = __float2half_rn(v1);
    return (unsigned)__half_as_ushort(h0) | ((unsigned)__half_as_ushort(h1) << 16);
}
__device__ __forceinline__ void cp16(unsigned* sp, const unsigned* gp){
    unsigned sa = (unsigned)__cvta_generic_to_shared(sp);
    asm volatile("cp.async.cg.shared.global [%0], [%1], 16;" :: "r"(sa), "l"(gp));
}

// ---- conv1 (+ gamma transpose fold): grid (64,4,2), 256 thr ----
__global__ void conv1_kernel(const float* __restrict__ x, const float* __restrict__ w,
                             const float* __restrict__ b, const float* __restrict__ g1,
                             const float* __restrict__ g2){
    __shared__ float sw[4800];
    __shared__ float sin_[3885];
    int bp = blockIdx.x, tile = blockIdx.y, z = blockIdx.z;
    int t = threadIdx.x;
    if (z == 0){
        int blk = bp*4 + tile;
        for (int i = t; i < 128; i += 256){
            int e = blk*128 + i;
            int which = e >> 14, idx = e & 16383;
            const float* g = which ? g2 : g1;
            g_gT[which][(idx & 127)*128 + (idx >> 7)] = g[idx];
        }
    }
    for (int e = t; e < 4800; e += 256) sw[e] = w[z*4800 + e];
    int ty0 = (tile>>1)*16, tx0 = (tile&1)*16;
    int iy0 = 2*ty0 - 2, ix0 = 2*tx0 - 2;
    const float* xb = x + bp*12288;
    for (int e = t; e < 3675; e += 256){
        int c = e/1225, rem = e - c*1225, r = rem/35, col = rem - r*35;
        int gy = iy0 + r, gx = ix0 + col;
        float v = 0.f;
        if (gy>=0 && gy<64 && gx>=0 && gx<64) v = xb[c*4096 + gy*64 + gx];
        sin_[(c*35 + r)*37 + col] = v;
    }
    __syncthreads();
    int px4 = t & 63, cog = t >> 6;
    int ly = px4 >> 2, lx0 = (px4 & 3)*4;
    float* ob = g_s1 + bp*131072;
    for (int p = 0; p < 2; p++){
        int col0 = cog*16 + p*8;
        float acc[8][4];
        #pragma unroll
        for (int i = 0; i < 8; i++){
            float bb = b[z*64 + col0 + i];
            #pragma unroll
            for (int j = 0; j < 4; j++) acc[i][j] = bb;
        }
        #pragma unroll 1
        for (int c = 0; c < 3; c++){
            #pragma unroll
            for (int ky = 0; ky < 5; ky++){
                #pragma unroll
                for (int kx = 0; kx < 5; kx++){
                    float xv[4];
                    #pragma unroll
                    for (int j = 0; j < 4; j++)
                        xv[j] = sin_[(c*35 + 2*ly + ky)*37 + 2*lx0 + 2*j + kx];
                    #pragma unroll
                    for (int i = 0; i < 8; i++){
                        float wv = sw[(col0+i)*75 + c*25 + ky*5 + kx];
                        #pragma unroll
                        for (int j = 0; j < 4; j++) acc[i][j] = fmaf(wv, xv[j], acc[i][j]);
                    }
                }
            }
        }
        #pragma unroll
        for (int i = 0; i < 8; i++){
            float4 o = make_float4(acc[i][0], acc[i][1], acc[i][2], acc[i][3]);
            *reinterpret_cast<float4*>(ob + (z*64+col0+i)*1024 + (ty0+ly)*32 + tx0 + lx0) = o;
        }
    }
}

// ---- GDN in-place (f32x2) + W half-pack fold on stage 1 ----
__global__ void gdn_kernel(int stage, const float* __restrict__ beta,
                           const float* __restrict__ w2, const float* __restrict__ w3){
    __shared__ float sA[2048];
    __shared__ float sB[1088];
    int HW = (stage == 1) ? 1024 : 256;
    float* x = (stage == 1) ? g_s1 : g_s2;
    const float* gT = g_gT[stage-1];
    int chunks = HW >> 6;
    int bp = blockIdx.x / chunks;
    int p0 = (blockIdx.x - bp*chunks) * 64;
    int t = threadIdx.x;
    if (stage == 1){
        int b2 = blockIdx.x * 200;
        for (int i = t; i < 200; i += 256){
            int e = b2 + i;
            g_w2h[e] = packh(w2[2*e], w2[2*e+1]);
        }
        int b3 = blockIdx.x * 108;
        for (int i = t; i < 108; i += 256){
            int e = b3 + i;
            g_w3h[e] = packh(w3[2*e], w3[2*e+1]);
        }
    }
    int i = t >> 4, j = t & 15;
    float* xb = x + bp*128*HW;
    ull acc[8][2];
    #pragma unroll
    for (int ii = 0; ii < 8; ii++){
        float bb = beta[i*8 + ii];
        acc[ii][0] = pkdup(bb); acc[ii][1] = pkdup(bb);
    }
    for (int c0 = 0; c0 < 128; c0 += 16){
        __syncthreads();
        for (int e = t; e < 2048; e += 256) sA[e] = gT[c0*128 + e];
        for (int e = t; e < 1024; e += 256){
            int cc = e >> 6, p = e & 63;
            float v = xb[(c0+cc)*HW + p0 + p];
            sB[cc*68 + p] = v*v;
        }
        __syncthreads();
        #pragma unroll
        for (int cc = 0; cc < 16; cc++){
            const ull* xp = reinterpret_cast<const ull*>(sB + cc*68 + j*4);
            ull x0 = xp[0], x1 = xp[1];
            float4 ga = *reinterpret_cast<const float4*>(sA + cc*128 + i*8);
            float4 gb = *reinterpret_cast<const float4*>(sA + cc*128 + i*8 + 4);
            float gs[8] = {ga.x,ga.y,ga.z,ga.w,gb.x,gb.y,gb.z,gb.w};
            #pragma unroll
            for (int ii = 0; ii < 8; ii++){
                ull wp = pkdup(gs[ii]);
                acc[ii][0] = ffma2(x0, wp, acc[ii][0]);
                acc[ii][1] = ffma2(x1, wp, acc[ii][1]);
            }
        }
    }
    #pragma unroll
    for (int ii = 0; ii < 8; ii++){
        int d = i*8 + ii;
        float a0,a1,a2,a3;
        upk2(acc[ii][0], a0, a1);
        upk2(acc[ii][1], a2, a3);
        float4 xv = *reinterpret_cast<const float4*>(xb + d*HW + p0 + j*4);
        float4 o;
        o.x = xv.x * rsqrtf(a0);
        o.y = xv.y * rsqrtf(a1);
        o.z = xv.z * rsqrtf(a2);
        o.w = xv.w * rsqrtf(a3);
        *reinterpret_cast<float4*>(xb + d*HW + p0 + j*4) = o;
    }
}

// ---- conv2 im2col (half2-packed out): grid (800,64), 256 thr ----
__global__ void im2col2_kernel(){
    int bp = blockIdx.y;
    int t = threadIdx.x;
    int oy = t >> 4, ox = t & 15;
    const float* xb = g_s1 + bp*131072;
    unsigned* xc = g_xcolh + bp*409600;
    int base = blockIdx.x*4;
    #pragma unroll
    for (int kpi = 0; kpi < 2; kpi++){
        float v[2];
        #pragma unroll
        for (int h = 0; h < 2; h++){
            int k = base + kpi*2 + h;
            int ci = k / 25, r = k - ci*25;
            int ky = r / 5, kx = r - ky*5;
            int iy = 2*oy - 2 + ky, ix = 2*ox - 2 + kx;
            float vv = 0.f;
            if (iy>=0 && iy<32 && ix>=0 && ix<32) vv = xb[ci*1024 + iy*32 + ix];
            v[h] = vv;
        }
        xc[((base >> 1) + kpi)*256 + t] = packh(v[0], v[1]);
    }
}

// ---- conv3 im2col (half2-packed out): grid (288,64), 256 thr ----
__global__ void im2col3_kernel(){
    int bp = blockIdx.y;
    int t = threadIdx.x;
    int oy = t >> 4, ox = t & 15;
    const float* xb = g_s2 + bp*32768;
    unsigned* xc = g_x3colh + bp*147456;
    int base = blockIdx.x*4;
    #pragma unroll
    for (int kpi = 0; kpi < 2; kpi++){
        float v[2];
        #pragma unroll
        for (int h = 0; h < 2; h++){
            int k = base + kpi*2 + h;
            int ci = k / 9, r = k - ci*9;
            int ky = r / 3, kx = r - ky*3;
            int iy = oy - 1 + ky, ix = ox - 1 + kx;
            float vv = 0.f;
            if (iy>=0 && iy<16 && ix>=0 && ix<16) vv = xb[ci*256 + iy*16 + ix];
            v[h] = vv;
        }
        xc[((base >> 1) + kpi)*256 + t] = packh(v[0], v[1]);
    }
}

// ---- conv2 GEMM fp16, 3-stage cp.async. grid (64,4), 256 thr, 44544 B dyn ----
__global__ void __launch_bounds__(256) conv2gemm_kernel(const float* __restrict__ bias){
    extern __shared__ unsigned smu[];
    // W bufs: buf*2560 (128 rows x stride 20); X bufs at 7680 + buf*1152 (16 rows x stride 72)
    int bp = blockIdx.x, n0b = blockIdx.y * 64;
    int t = threadIdx.x;
    int warp = t >> 5, lane = t & 31;
    int g = lane >> 2, tig = lane & 3;
    int m0 = (warp >> 1) * 32;
    int n0 = (warp & 1) * 32;
    float c[2][4][4];
    #pragma unroll
    for (int mt = 0; mt < 2; mt++)
        #pragma unroll
        for (int nt = 0; nt < 4; nt++)
            #pragma unroll
            for (int q = 0; q < 4; q++) c[mt][nt][q] = 0.f;
    const unsigned* xcb = g_xcolh + bp*409600 + n0b;

    auto stage = [&](int kp0, int buf){
        unsigned* dW = smu + buf*2560;
        unsigned* dX = smu + 7680 + buf*1152;
        #pragma unroll
        for (int s = 0; s < 2; s++){
            int e = t + s*256;                 // 512 W cps: 128 rows x 16 words
            int co = e >> 2, kq = (e & 3) * 4;
            cp16(&dW[co*20 + kq], &g_w2h[co*1600 + kp0 + kq]);
        }
        {                                      // 256 X cps: 16 rows x 64 words
            int kk = t >> 4, ps = (t & 15) * 4;
            cp16(&dX[kk*72 + ps], &xcb[(kp0 + kk)*256 + ps]);
        }
        asm volatile("cp.async.commit_group;" ::);
    };

    stage(0, 0);
    stage(16, 1);
    for (int it = 0; it < 100; it++){
        if (it + 2 < 100) stage((it+2)*16, (it+2) % 3);
        if (it <= 97)      asm volatile("cp.async.wait_group 2;" ::);
        else if (it == 98) asm volatile("cp.async.wait_group 1;" ::);
        else               asm volatile("cp.async.wait_group 0;" ::);
        __syncthreads();
        const unsigned* dW = smu + (it % 3)*2560;
        const unsigned* dX = smu + 7680 + (it % 3)*1152;
        #pragma unroll
        for (int ks = 0; ks < 2; ks++){
            int kb = ks*8;
            unsigned a[2][4], bb[4][2];
            #pragma unroll
            for (int mt = 0; mt < 2; mt++){
                int m = m0 + mt*16;
                a[mt][0] = dW[(m+g)*20 + kb + tig];
                a[mt][1] = dW[(m+g+8)*20 + kb + tig];
                a[mt][2] = dW[(m+g)*20 + kb + 4 + tig];
                a[mt][3] = dW[(m+g+8)*20 + kb + 4 + tig];
            }
            #pragma unroll
            for (int nt = 0; nt < 4; nt++){
                int n = n0 + nt*8;
                bb[nt][0] = dX[(kb+tig)*72 + n + g];
                bb[nt][1] = dX[(kb+tig+4)*72 + n + g];
            }
            #pragma unroll
            for (int mt = 0; mt < 2; mt++)
                #pragma unroll
                for (int nt = 0; nt < 4; nt++)
                    asm volatile(
                        "mma.sync.aligned.m16n8k16.row.col.f32.f16.f16.f32 "
                        "{%0,%1,%2,%3}, {%4,%5,%6,%7}, {%8,%9}, {%0,%1,%2,%3};"
                        : "+f"(c[mt][nt][0]), "+f"(c[mt][nt][1]),
                          "+f"(c[mt][nt][2]), "+f"(c[mt][nt][3])
                        : "r"(a[mt][0]), "r"(a[mt][1]), "r"(a[mt][2]), "r"(a[mt][3]),
                          "r"(bb[nt][0]), "r"(bb[nt][1]));
        }
        __syncthreads();
    }
    float* ob = g_s2 + bp*32768;
    #pragma unroll
    for (int mt = 0; mt < 2; mt++){
        int coA = m0 + mt*16 + g;
        int coB = coA + 8;
        float bA = bias[coA], bB = bias[coB];
        #pragma unroll
        for (int nt = 0; nt < 4; nt++){
            int px = n0b + n0 + nt*8 + 2*tig;
            *reinterpret_cast<float2*>(ob + coA*256 + px) =
                make_float2(c[mt][nt][0] + bA, c[mt][nt][1] + bA);
            *reinterpret_cast<float2*>(ob + coB*256 + px) =
                make_float2(c[mt][nt][2] + bB, c[mt][nt][3] + bB);
        }
    }
}

// ---- conv3 GEMM fp16, 3-stage cp.async. grid (64,4), 384 thr, 59904 B dyn ----
__global__ void __launch_bounds__(384) conv3gemm_kernel(const float* __restrict__ bias){
    extern __shared__ unsigned smu3[];
    // W bufs: buf*3840 (192 rows x stride 20); X bufs at 11520 + buf*1152
    int bp = blockIdx.x, n0b = blockIdx.y * 64;
    int t = threadIdx.x;
    int warp = t >> 5, lane = t & 31;
    int g = lane >> 2, tig = lane & 3;
    int m0 = (warp >> 1) * 32;
    int n0 = (warp & 1) * 32;
    float c[2][4][4];
    #pragma unroll
    for (int mt = 0; mt < 2; mt++)
        #pragma unroll
        for (int nt = 0; nt < 4; nt++)
            #pragma unroll
            for (int q = 0; q < 4; q++) c[mt][nt][q] = 0.f;
    const unsigned* xcb = g_x3colh + bp*147456 + n0b;

    auto stage = [&](int kp0, int buf){
        unsigned* dW = smu3 + buf*3840;
        unsigned* dX = smu3 + 11520 + buf*1152;
        #pragma unroll
        for (int s = 0; s < 2; s++){
            int e = t + s*384;                 // 768 W cps: 192 rows x 16 words
            int co = e >> 2, kq = (e & 3) * 4;
            cp16(&dW[co*20 + kq], &g_w3h[co*576 + kp0 + kq]);
        }
        if (t < 256){                          // 256 X cps: 16 rows x 64 words
            int kk = t >> 4, ps = (t & 15) * 4;
            cp16(&dX[kk*72 + ps], &xcb[(kp0 + kk)*256 + ps]);
        }
        asm volatile("cp.async.commit_group;" ::);
    };

    stage(0, 0);
    stage(16, 1);
    for (int it = 0; it < 36; it++){
        if (it + 2 < 36) stage((it+2)*16, (it+2) % 3);
        if (it <= 33)      asm volatile("cp.async.wait_group 2;" ::);
        else if (it == 34) asm volatile("cp.async.wait_group 1;" ::);
        else               asm volatile("cp.async.wait_group 0;" ::);
        __syncthreads();
        const unsigned* dW = smu3 + (it % 3)*3840;
        const unsigned* dX = smu3 + 11520 + (it % 3)*1152;
        #pragma unroll
        for (int ks = 0; ks < 2; ks++){
            int kb = ks*8;
            unsigned a[2][4], bb[4][2];
            #pragma unroll
            for (int mt = 0; mt < 2; mt++){
                int m = m0 + mt*16;
                a[mt][0] = dW[(m+g)*20 + kb + tig];
                a[mt][1] = dW[(m+g+8)*20 + kb + tig];
                a[mt][2] = dW[(m+g)*20 + kb + 4 + tig];
                a[mt][3] = dW[(m+g+8)*20 + kb + 4 + tig];
            }
            #pragma unroll
            for (int nt = 0; nt < 4; nt++){
                int n = n0 + nt*8;
                bb[nt][0] = dX[(kb+tig)*72 + n + g];
                bb[nt][1] = dX[(kb+tig+4)*72 + n + g];
            }
            #pragma unroll
            for (int mt = 0; mt < 2; mt++)
                #pragma unroll
                for (int nt = 0; nt < 4; nt++)
                    asm volatile(
                        "mma.sync.aligned.m16n8k16.row.col.f32.f16.f16.f32 "
                        "{%0,%1,%2,%3}, {%4,%5,%6,%7}, {%8,%9}, {%0,%1,%2,%3};"
                        : "+f"(c[mt][nt][0]), "+f"(c[mt][nt][1]),
                          "+f"(c[mt][nt][2]), "+f"(c[mt][nt][3])
                        : "r"(a[mt][0]), "r"(a[mt][1]), "r"(a[mt][2]), "r"(a[mt][3]),
                          "r"(bb[nt][0]), "r"(bb[nt][1]));
        }
        __syncthreads();
    }
    float* ob = g_y3 + bp*49152;
    #pragma unroll
    for (int mt = 0; mt < 2; mt++){
        int coA = m0 + mt*16 + g;
        int coB = coA + 8;
        float bA = bias[coA], bB = bias[coB];
        #pragma unroll
        for (int nt = 0; nt < 4; nt++){
            int px = n0b + n0 + nt*8 + 2*tig;
            *reinterpret_cast<float2*>(ob + coA*256 + px) =
                make_float2(c[mt][nt][0] + bA, c[mt][nt][1] + bA);
            *reinterpret_cast<float2*>(ob + coB*256 + px) =
                make_float2(c[mt][nt][2] + bB, c[mt][nt][3] + bB);
        }
    }
}

// ---- kv: LN + k_proj + v_proj. grid (64,5), 256 thr ----
__global__ void kv_kernel(const float* __restrict__ yg, const float* __restrict__ lnw,
                          const float* __restrict__ lnb, const float* __restrict__ Wk,
                          const float* __restrict__ Wv){
    __shared__ float s_kv[32*193];
    __shared__ float s_w[64*33];
    int bp = blockIdx.x;
    int r0 = blockIdx.y * 64;
    int t = threadIdx.x;
    int w = t >> 5, l = t & 31;
    for (int e = t; e < 6144; e += 256){
        int c = e >> 5, k = e & 31;
        s_kv[k*193 + c] = yg[bp*6144 + c*32 + k];
    }
    __syncthreads();
    {
        float lwv[6], lbv[6];
        #pragma unroll
        for (int i = 0; i < 6; i++){ lwv[i] = lnw[l+32*i]; lbv[i] = lnb[l+32*i]; }
        for (int ki = 0; ki < 4; ki++){
            int k = w*4 + ki;
            float v[6]; float s = 0.f;
            #pragma unroll
            for (int i = 0; i < 6; i++){ v[i] = s_kv[k*193 + l + 32*i]; s += v[i]; }
            #pragma unroll
            for (int o = 16; o > 0; o >>= 1) s += __shfl_xor_sync(0xffffffffu, s, o);
            float mu = s * (1.f/192.f);
            float vs = 0.f;
            #pragma unroll
            for (int i = 0; i < 6; i++){ float d = v[i]-mu; vs += d*d; }
            #pragma unroll
            for (int o = 16; o > 0; o >>= 1) vs += __shfl_xor_sync(0xffffffffu, vs, o);
            float rs = rsqrtf(vs * (1.f/192.f) + LN_EPS);
            #pragma unroll
            for (int i = 0; i < 6; i++)
                s_kv[k*193 + l + 32*i] = (v[i]-mu)*rs*lwv[i] + lbv[i];
        }
    }
    int kq = t & 7, rp = t >> 3;
    {
        float acc[2][4];
        #pragma unroll
        for (int i = 0; i < 2; i++)
            #pragma unroll
            for (int kk = 0; kk < 4; kk++) acc[i][kk] = 0.f;
        for (int c0 = 0; c0 < 192; c0 += 32){
            __syncthreads();
            for (int e = t; e < 2048; e += 256){
                int rr = e >> 5, cc = e & 31;
                int row = r0 + rr;
                s_w[rr*33 + cc] = (row < 128) ? Wk[row*192 + c0 + cc]
                                              : Wv[(row-128)*192 + c0 + cc];
            }
            __syncthreads();
            for (int cc = 0; cc < 32; cc++){
                float wv0 = s_w[(rp*2)*33 + cc], wv1 = s_w[(rp*2+1)*33 + cc];
                #pragma unroll
                for (int kk = 0; kk < 4; kk++){
                    float kvv = s_kv[(kq*4+kk)*193 + c0 + cc];
                    acc[0][kk] = fmaf(wv0, kvv, acc[0][kk]);
                    acc[1][kk] = fmaf(wv1, kvv, acc[1][kk]);
                }
            }
        }
        #pragma unroll
        for (int i = 0; i < 2; i++){
            int row = r0 + rp*2 + i;
            #pragma unroll
            for (int kk = 0; kk < 4; kk++){
                int k = kq*4 + kk;
                if (row < 128) g_kp[bp*4096 + k*128 + row] = acc[i][kk];
                else           g_vp[bp*6144 + k*192 + (row-128)] = acc[i][kk];
            }
        }
    }
}

// ---- attention: grid 512, 256 thr, 95872 B dyn smem ----
__global__ void attn_kernel(const float* __restrict__ lnqw, const float* __restrict__ lnqb,
                            const float* __restrict__ Wq, const float* __restrict__ vw,
                            const float* __restrict__ out_w, const float* __restrict__ out_b,
                            const float* __restrict__ lnow, const float* __restrict__ lnob,
                            float* __restrict__ out){
    extern __shared__ float sm[];
    float* s_qn  = sm;
    float* s_w   = sm + 6176;
    float* s_kp  = sm + 12512;
    float* s_e   = sm + 16736;
    float* s_ctx = sm + 17792;
    int bp = blockIdx.x >> 3;
    int q0 = (blockIdx.x & 7) << 5;
    int t = threadIdx.x;
    int w = t >> 5, l = t & 31;
    const float* y3 = g_y3 + bp*49152;
    for (int e = t; e < 6144; e += 256){
        int m = e >> 5, q = e & 31;
        s_qn[q*193 + m] = y3[m*256 + q0 + q];
    }
    for (int e = t; e < 4096; e += 256){
        int k = e >> 7;
        s_kp[k*132 + (e & 127)] = g_kp[bp*4096 + e];
    }
    __syncthreads();
    {
        float lwv[6], lbv[6];
        #pragma unroll
        for (int i = 0; i < 6; i++){ lwv[i] = lnqw[l+32*i]; lbv[i] = lnqb[l+32*i]; }
        for (int qi = 0; qi < 4; qi++){
            int q = w*4 + qi;
            float v[6]; float s = 0.f;
            #pragma unroll
            for (int i = 0; i < 6; i++){ v[i] = s_qn[q*193 + l + 32*i]; s += v[i]; }
            #pragma unroll
            for (int o = 16; o > 0; o >>= 1) s += __shfl_xor_sync(0xffffffffu, s, o);
            float mu = s * (1.f/192.f);
            float vs = 0.f;
            #pragma unroll
            for (int i = 0; i < 6; i++){ float d = v[i]-mu; vs += d*d; }
            #pragma unroll
            for (int o = 16; o > 0; o >>= 1) vs += __shfl_xor_sync(0xffffffffu, vs, o);
            float rs = rsqrtf(vs * (1.f/192.f) + LN_EPS);
            #pragma unroll
            for (int i = 0; i < 6; i++)
                s_qn[q*193 + l + 32*i] = (v[i]-mu)*rs*lwv[i] + lbv[i];
        }
    }
    float qp[4][4];
    #pragma unroll
    for (int a = 0; a < 4; a++)
        #pragma unroll
        for (int b2 = 0; b2 < 4; b2++) qp[a][b2] = 0.f;
    for (int c0 = 0; c0 < 192; c0 += 32){
        __syncthreads();
        for (int e = t; e < 4096; e += 256){
            int d = e >> 5, cc = e & 31;
            s_w[d*33 + cc] = Wq[d*192 + c0 + cc];
        }
        __syncthreads();
        for (int cc = 0; cc < 32; cc++){
            float wv[4], qv[4];
            #pragma unroll
            for (int j = 0; j < 4; j++) wv[j] = s_w[(l+32*j)*33 + cc];
            #pragma unroll
            for (int qi = 0; qi < 4; qi++) qv[qi] = s_qn[(w*4+qi)*193 + c0 + cc];
            #pragma unroll
            for (int qi = 0; qi < 4; qi++)
                #pragma unroll
                for (int j = 0; j < 4; j++) qp[qi][j] = fmaf(qv[qi], wv[j], qp[qi][j]);
        }
    }
    __syncthreads();
    float* s_vp = s_w;
    for (int e = t; e < 6144; e += 256){
        int k = e / 192, m = e - k*192;
        s_vp[k*193 + m] = g_vp[bp*6144 + e];
    }
    float vv[4];
    #pragma unroll
    for (int j = 0; j < 4; j++) vv[j] = vw[l + 32*j];
    for (int k = 0; k < 32; k++){
        float kp4[4];
        #pragma unroll
        for (int j = 0; j < 4; j++) kp4[j] = s_kp[k*132 + l + 32*j];
        #pragma unroll
        for (int qi = 0; qi < 4; qi++){
            float s = 0.f;
            #pragma unroll
            for (int j = 0; j < 4; j++)
                s = fmaf(tanh_fast(qp[qi][j] + kp4[j]), vv[j], s);
            #pragma unroll
            for (int o = 16; o > 0; o >>= 1) s += __shfl_xor_sync(0xffffffffu, s, o);
            if (l == 0) s_e[(w*4+qi)*33 + k] = s;
        }
    }
    __syncwarp();
    for (int qi = 0; qi < 4; qi++){
        int q = w*4 + qi;
        float ev = s_e[q*33 + l];
        float mx = ev;
        #pragma unroll
        for (int o = 16; o > 0; o >>= 1) mx = fmaxf(mx, __shfl_xor_sync(0xffffffffu, mx, o));
        float p = __expf(ev - mx);
        float s = p;
        #pragma unroll
        for (int o = 16; o > 0; o >>= 1) s += __shfl_xor_sync(0xffffffffu, s, o);
        s_e[q*33 + l] = p / s;
    }
    __syncthreads();
    {
        int qr = t >> 3, mg = t & 7;
        float acc[24];
        #pragma unroll
        for (int i = 0; i < 24; i++) acc[i] = 0.f;
        for (int k = 0; k < 32; k++){
            float a = s_e[qr*33 + k];
            #pragma unroll
            for (int i = 0; i < 24; i++)
                acc[i] = fmaf(a, s_vp[k*193 + mg + 8*i], acc[i]);
        }
        #pragma unroll
        for (int i = 0; i < 24; i++) s_ctx[qr*193 + mg + 8*i] = acc[i];
    }
    __syncthreads();
    {
        int qh = t >> 4, ng = t & 15;
        float acc0[12], acc1[12];
        #pragma unroll
        for (int i = 0; i < 12; i++){ acc0[i] = 0.f; acc1[i] = 0.f; }
        for (int m0 = 0; m0 < 192; m0 += 32){
            __syncthreads();
            for (int e = t; e < 6144; e += 256){
                int n = e >> 5, mm = e & 31;
                s_w[n*33 + mm] = out_w[n*192 + m0 + mm];
            }
            __syncthreads();
            for (int mm = 0; mm < 32; mm++){
                float c0v = s_ctx[(2*qh)*193 + m0 + mm];
                float c1v = s_ctx[(2*qh+1)*193 + m0 + mm];
                #pragma unroll
                for (int i = 0; i < 12; i++){
                    float wv = s_w[(ng+16*i)*33 + mm];
                    acc0[i] = fmaf(c0v, wv, acc0[i]);
                    acc1[i] = fmaf(c1v, wv, acc1[i]);
                }
            }
        }
        float val0[12], val1[12];
        float s0 = 0.f, s1 = 0.f;
        #pragma unroll
        for (int i = 0; i < 12; i++){
            int n = ng + 16*i;
            val0[i] = acc0[i] + out_b[n] + s_qn[(2*qh)*193 + n];
            val1[i] = acc1[i] + out_b[n] + s_qn[(2*qh+1)*193 + n];
            s0 += val0[i]; s1 += val1[i];
        }
        #pragma unroll
        for (int o = 8; o > 0; o >>= 1){
            s0 += __shfl_xor_sync(0xffffffffu, s0, o);
            s1 += __shfl_xor_sync(0xffffffffu, s1, o);
        }
        float mu0 = s0*(1.f/192.f), mu1 = s1*(1.f/192.f);
        float vs0 = 0.f, vs1 = 0.f;
        #pragma unroll
        for (int i = 0; i < 12; i++){
            float d0 = val0[i]-mu0, d1 = val1[i]-mu1;
            vs0 += d0*d0; vs1 += d1*d1;
        }
        #pragma unroll
        for (int o = 8; o > 0; o >>= 1){
            vs0 += __shfl_xor_sync(0xffffffffu, vs0, o);
            vs1 += __shfl_xor_sync(0xffffffffu, vs1, o);
        }
        float r0 = rsqrtf(vs0*(1.f/192.f) + LN_EPS);
        float r1 = rsqrtf(vs1*(1.f/192.f) + LN_EPS);
        __syncthreads();
        #pragma unroll
        for (int i = 0; i < 12; i++){
            int n = ng + 16*i;
            s_ctx[(2*qh)*193 + n]   = (val0[i]-mu0)*r0*lnow[n] + lnob[n];
            s_ctx[(2*qh+1)*193 + n] = (val1[i]-mu1)*r1*lnow[n] + lnob[n];
        }
    }
    __syncthreads();
    for (int e = t; e < 6144; e += 256){
        int n = e >> 5, q = e & 31;
        out[bp*49152 + n*256 + q0 + q] = s_ctx[q*193 + n];
    }
}

extern "C" void kernel_launch(void* const* d_in, const int* in_sizes, int n_in,
                              void* d_out, int out_size){
    const float* x_p    = (const float*)d_in[0];
    const float* y_g    = (const float*)d_in[1];
    const float* conv1w = (const float*)d_in[2];
    const float* conv1b = (const float*)d_in[3];
    const float* gamma1 = (const float*)d_in[4];
    const float* beta1  = (const float*)d_in[5];
    const float* conv2w = (const float*)d_in[6];
    const float* conv2b = (const float*)d_in[7];
    const float* gamma2 = (const float*)d_in[8];
    const float* beta2  = (const float*)d_in[9];
    const float* conv3w = (const float*)d_in[10];
    const float* conv3b = (const float*)d_in[11];
    const float* lnqw   = (const float*)d_in[12];
    const float* lnqb   = (const float*)d_in[13];
    const float* lnkw   = (const float*)d_in[14];
    const float* lnkb   = (const float*)d_in[15];
    const float* lnow   = (const float*)d_in[16];
    const float* lnob   = (const float*)d_in[17];
    const float* Wq     = (const float*)d_in[18];
    const float* Wk     = (const float*)d_in[19];
    const float* vw     = (const float*)d_in[20];
    const float* Wv     = (const float*)d_in[21];
    const float* outw   = (const float*)d_in[22];
    const float* outb   = (const float*)d_in[23];
    float* out = (float*)d_out;

    cudaFuncSetAttribute(attn_kernel, cudaFuncAttributeMaxDynamicSharedMemorySize, 98304);
    cudaFuncSetAttribute(conv2gemm_kernel, cudaFuncAttributeMaxDynamicSharedMemorySize, 44544);
    cudaFuncSetAttribute(conv3gemm_kernel, cudaFuncAttributeMaxDynamicSharedMemorySize, 59904);

    conv1_kernel<<<dim3(64,4,2), 256>>>(x_p, conv1w, conv1b, gamma1, gamma2);  // 0
    gdn_kernel<<<1024, 256>>>(1, beta1, conv2w, conv3w);                        // 1
    im2col2_kernel<<<dim3(800,64), 256>>>();                                    // 2
    conv2gemm_kernel<<<dim3(64,4), 256, 44544>>>(conv2b);                       // 3 (profiled)
    gdn_kernel<<<256, 256>>>(2, beta2, nullptr, nullptr);                       // 4
    im2col3_kernel<<<dim3(288,64), 256>>>();                                    // 5
    conv3gemm_kernel<<<dim3(64,4), 384, 59904>>>(conv3b);                       // 6
    kv_kernel<<<dim3(64,5), 256>>>(y_g, lnkw, lnkb, Wk, Wv);                    // 7
    attn_kernel<<<512, 256, 95872>>>(lnqw, lnqb, Wq, vw, outw, outb, lnow, lnob, out);
}

// round 14
// speedup vs baseline: 3.4048x; 1.1926x over previous
#include <cuda_runtime.h>
#include <cuda_fp16.h>

#define LN_EPS 1e-5f
typedef unsigned long long ull;

// ---- scratch ----
__device__ float g_s1[64*128*1024];
__device__ float g_s2[64*128*256];
__device__ float g_y3[64*192*256];
__device__ float g_kp[64*32*128];
__device__ float g_vp[64*32*192];
__device__ float g_gT[2][16384];
__device__ unsigned g_xcolh[64*1600*256];
__device__ unsigned g_x3colh[64*576*256];
__device__ unsigned g_w2h[128*1600];
__device__ unsigned g_w3h[192*576];
__device__ unsigned g_owh[192*96];          // out_w half2-packed [n][mp]
__device__ unsigned g_ctxh[64*256*96];      // context fp16 [token][mp]
__device__ float g_qnT[64*192*256];         // normalized q, [bp][n][q]

__device__ __forceinline__ float tanh_fast(float x){
    float y; asm("tanh.approx.f32 %0, %1;" : "=f"(y) : "f"(x)); return y;
}
__device__ __forceinline__ ull pk2(float lo, float hi){
    ull r; asm("mov.b64 %0, {%1, %2};" : "=l"(r) : "f"(lo), "f"(hi)); return r;
}
__device__ __forceinline__ ull pkdup(float v){ return pk2(v, v); }
__device__ __forceinline__ void upk2(ull p, float& lo, float& hi){
    asm("mov.b64 {%0, %1}, %2;" : "=f"(lo), "=f"(hi) : "l"(p));
}
__device__ __forceinline__ ull ffma2(ull a, ull b, ull c){
    ull d; asm("fma.rn.f32x2 %0, %1, %2, %3;" : "=l"(d) : "l"(a), "l"(b), "l"(c)); return d;
}
__device__ __forceinline__ unsigned packh(float v0, float v1){
    __half h0 = __float2half_rn(v0), h1 = __float2half_rn(v1);
    return (unsigned)__half_as_ushort(h0) | ((unsigned)__half_as_ushort(h1) << 16);
}
__device__ __forceinline__ void cp16(unsigned* sp, const unsigned* gp){
    unsigned sa = (unsigned)__cvta_generic_to_shared(sp);
    asm volatile("cp.async.cg.shared.global [%0], [%1], 16;" :: "r"(sa), "l"(gp));
}

// ---- conv1 (+ gamma transpose fold): grid (64,4,2), 256 thr ----
__global__ void conv1_kernel(const float* __restrict__ x, const float* __restrict__ w,
                             const float* __restrict__ b, const float* __restrict__ g1,
                             const float* __restrict__ g2){
    __shared__ float sw[4800];
    __shared__ float sin_[3885];
    int bp = blockIdx.x, tile = blockIdx.y, z = blockIdx.z;
    int t = threadIdx.x;
    if (z == 0){
        int blk = bp*4 + tile;
        for (int i = t; i < 128; i += 256){
            int e = blk*128 + i;
            int which = e >> 14, idx = e & 16383;
            const float* g = which ? g2 : g1;
            g_gT[which][(idx & 127)*128 + (idx >> 7)] = g[idx];
        }
    }
    for (int e = t; e < 4800; e += 256) sw[e] = w[z*4800 + e];
    int ty0 = (tile>>1)*16, tx0 = (tile&1)*16;
    int iy0 = 2*ty0 - 2, ix0 = 2*tx0 - 2;
    const float* xb = x + bp*12288;
    for (int e = t; e < 3675; e += 256){
        int c = e/1225, rem = e - c*1225, r = rem/35, col = rem - r*35;
        int gy = iy0 + r, gx = ix0 + col;
        float v = 0.f;
        if (gy>=0 && gy<64 && gx>=0 && gx<64) v = xb[c*4096 + gy*64 + gx];
        sin_[(c*35 + r)*37 + col] = v;
    }
    __syncthreads();
    int px4 = t & 63, cog = t >> 6;
    int ly = px4 >> 2, lx0 = (px4 & 3)*4;
    float* ob = g_s1 + bp*131072;
    for (int p = 0; p < 2; p++){
        int col0 = cog*16 + p*8;
        float acc[8][4];
        #pragma unroll
        for (int i = 0; i < 8; i++){
            float bb = b[z*64 + col0 + i];
            #pragma unroll
            for (int j = 0; j < 4; j++) acc[i][j] = bb;
        }
        #pragma unroll 1
        for (int c = 0; c < 3; c++){
            #pragma unroll
            for (int ky = 0; ky < 5; ky++){
                #pragma unroll
                for (int kx = 0; kx < 5; kx++){
                    float xv[4];
                    #pragma unroll
                    for (int j = 0; j < 4; j++)
                        xv[j] = sin_[(c*35 + 2*ly + ky)*37 + 2*lx0 + 2*j + kx];
                    #pragma unroll
                    for (int i = 0; i < 8; i++){
                        float wv = sw[(col0+i)*75 + c*25 + ky*5 + kx];
                        #pragma unroll
                        for (int j = 0; j < 4; j++) acc[i][j] = fmaf(wv, xv[j], acc[i][j]);
                    }
                }
            }
        }
        #pragma unroll
        for (int i = 0; i < 8; i++){
            float4 o = make_float4(acc[i][0], acc[i][1], acc[i][2], acc[i][3]);
            *reinterpret_cast<float4*>(ob + (z*64+col0+i)*1024 + (ty0+ly)*32 + tx0 + lx0) = o;
        }
    }
}

// ---- GDN in-place (f32x2) + W half-pack fold on stage 1 ----
__global__ void gdn_kernel(int stage, const float* __restrict__ beta,
                           const float* __restrict__ w2, const float* __restrict__ w3,
                           const float* __restrict__ ow){
    __shared__ float sA[2048];
    __shared__ float sB[1088];
    int HW = (stage == 1) ? 1024 : 256;
    float* x = (stage == 1) ? g_s1 : g_s2;
    const float* gT = g_gT[stage-1];
    int chunks = HW >> 6;
    int bp = blockIdx.x / chunks;
    int p0 = (blockIdx.x - bp*chunks) * 64;
    int t = threadIdx.x;
    if (stage == 1){
        int b2 = blockIdx.x * 200;
        for (int i = t; i < 200; i += 256){
            int e = b2 + i;
            g_w2h[e] = packh(w2[2*e], w2[2*e+1]);
        }
        int b3 = blockIdx.x * 108;
        for (int i = t; i < 108; i += 256){
            int e = b3 + i;
            g_w3h[e] = packh(w3[2*e], w3[2*e+1]);
        }
        int b4 = blockIdx.x * 18;
        for (int i = t; i < 18; i += 256){
            int e = b4 + i;
            g_owh[e] = packh(ow[2*e], ow[2*e+1]);
        }
    }
    int i = t >> 4, j = t & 15;
    float* xb = x + bp*128*HW;
    ull acc[8][2];
    #pragma unroll
    for (int ii = 0; ii < 8; ii++){
        float bb = beta[i*8 + ii];
        acc[ii][0] = pkdup(bb); acc[ii][1] = pkdup(bb);
    }
    for (int c0 = 0; c0 < 128; c0 += 16){
        __syncthreads();
        for (int e = t; e < 2048; e += 256) sA[e] = gT[c0*128 + e];
        for (int e = t; e < 1024; e += 256){
            int cc = e >> 6, p = e & 63;
            float v = xb[(c0+cc)*HW + p0 + p];
            sB[cc*68 + p] = v*v;
        }
        __syncthreads();
        #pragma unroll
        for (int cc = 0; cc < 16; cc++){
            const ull* xp = reinterpret_cast<const ull*>(sB + cc*68 + j*4);
            ull x0 = xp[0], x1 = xp[1];
            float4 ga = *reinterpret_cast<const float4*>(sA + cc*128 + i*8);
            float4 gb = *reinterpret_cast<const float4*>(sA + cc*128 + i*8 + 4);
            float gs[8] = {ga.x,ga.y,ga.z,ga.w,gb.x,gb.y,gb.z,gb.w};
            #pragma unroll
            for (int ii = 0; ii < 8; ii++){
                ull wp = pkdup(gs[ii]);
                acc[ii][0] = ffma2(x0, wp, acc[ii][0]);
                acc[ii][1] = ffma2(x1, wp, acc[ii][1]);
            }
        }
    }
    #pragma unroll
    for (int ii = 0; ii < 8; ii++){
        int d = i*8 + ii;
        float a0,a1,a2,a3;
        upk2(acc[ii][0], a0, a1);
        upk2(acc[ii][1], a2, a3);
        float4 xv = *reinterpret_cast<const float4*>(xb + d*HW + p0 + j*4);
        float4 o;
        o.x = xv.x * rsqrtf(a0);
        o.y = xv.y * rsqrtf(a1);
        o.z = xv.z * rsqrtf(a2);
        o.w = xv.w * rsqrtf(a3);
        *reinterpret_cast<float4*>(xb + d*HW + p0 + j*4) = o;
    }
}

// ---- conv2 im2col (half2-packed out): grid (800,64), 256 thr ----
__global__ void im2col2_kernel(){
    int bp = blockIdx.y;
    int t = threadIdx.x;
    int oy = t >> 4, ox = t & 15;
    const float* xb = g_s1 + bp*131072;
    unsigned* xc = g_xcolh + bp*409600;
    int base = blockIdx.x*4;
    #pragma unroll
    for (int kpi = 0; kpi < 2; kpi++){
        float v[2];
        #pragma unroll
        for (int h = 0; h < 2; h++){
            int k = base + kpi*2 + h;
            int ci = k / 25, r = k - ci*25;
            int ky = r / 5, kx = r - ky*5;
            int iy = 2*oy - 2 + ky, ix = 2*ox - 2 + kx;
            float vv = 0.f;
            if (iy>=0 && iy<32 && ix>=0 && ix<32) vv = xb[ci*1024 + iy*32 + ix];
            v[h] = vv;
        }
        xc[((base >> 1) + kpi)*256 + t] = packh(v[0], v[1]);
    }
}

// ---- conv3 im2col (half2-packed out): grid (288,64), 256 thr ----
__global__ void im2col3_kernel(){
    int bp = blockIdx.y;
    int t = threadIdx.x;
    int oy = t >> 4, ox = t & 15;
    const float* xb = g_s2 + bp*32768;
    unsigned* xc = g_x3colh + bp*147456;
    int base = blockIdx.x*4;
    #pragma unroll
    for (int kpi = 0; kpi < 2; kpi++){
        float v[2];
        #pragma unroll
        for (int h = 0; h < 2; h++){
            int k = base + kpi*2 + h;
            int ci = k / 9, r = k - ci*9;
            int ky = r / 3, kx = r - ky*3;
            int iy = oy - 1 + ky, ix = ox - 1 + kx;
            float vv = 0.f;
            if (iy>=0 && iy<16 && ix>=0 && ix<16) vv = xb[ci*256 + iy*16 + ix];
            v[h] = vv;
        }
        xc[((base >> 1) + kpi)*256 + t] = packh(v[0], v[1]);
    }
}

// ---- conv2 GEMM fp16, 3-stage cp.async. grid (64,4), 256 thr, 44544 B dyn ----
__global__ void __launch_bounds__(256) conv2gemm_kernel(const float* __restrict__ bias){
    extern __shared__ unsigned smu[];
    int bp = blockIdx.x, n0b = blockIdx.y * 64;
    int t = threadIdx.x;
    int warp = t >> 5, lane = t & 31;
    int g = lane >> 2, tig = lane & 3;
    int m0 = (warp >> 1) * 32;
    int n0 = (warp & 1) * 32;
    float c[2][4][4];
    #pragma unroll
    for (int mt = 0; mt < 2; mt++)
        #pragma unroll
        for (int nt = 0; nt < 4; nt++)
            #pragma unroll
            for (int q = 0; q < 4; q++) c[mt][nt][q] = 0.f;
    const unsigned* xcb = g_xcolh + bp*409600 + n0b;

    auto stage = [&](int kp0, int buf){
        unsigned* dW = smu + buf*2560;
        unsigned* dX = smu + 7680 + buf*1152;
        #pragma unroll
        for (int s = 0; s < 2; s++){
            int e = t + s*256;
            int co = e >> 2, kq = (e & 3) * 4;
            cp16(&dW[co*20 + kq], &g_w2h[co*1600 + kp0 + kq]);
        }
        {
            int kk = t >> 4, ps = (t & 15) * 4;
            cp16(&dX[kk*72 + ps], &xcb[(kp0 + kk)*256 + ps]);
        }
        asm volatile("cp.async.commit_group;" ::);
    };

    stage(0, 0);
    stage(16, 1);
    for (int it = 0; it < 100; it++){
        if (it + 2 < 100) stage((it+2)*16, (it+2) % 3);
        if (it <= 97)      asm volatile("cp.async.wait_group 2;" ::);
        else if (it == 98) asm volatile("cp.async.wait_group 1;" ::);
        else               asm volatile("cp.async.wait_group 0;" ::);
        __syncthreads();
        const unsigned* dW = smu + (it % 3)*2560;
        const unsigned* dX = smu + 7680 + (it % 3)*1152;
        #pragma unroll
        for (int ks = 0; ks < 2; ks++){
            int kb = ks*8;
            unsigned a[2][4], bb[4][2];
            #pragma unroll
            for (int mt = 0; mt < 2; mt++){
                int m = m0 + mt*16;
                a[mt][0] = dW[(m+g)*20 + kb + tig];
                a[mt][1] = dW[(m+g+8)*20 + kb + tig];
                a[mt][2] = dW[(m+g)*20 + kb + 4 + tig];
                a[mt][3] = dW[(m+g+8)*20 + kb + 4 + tig];
            }
            #pragma unroll
            for (int nt = 0; nt < 4; nt++){
                int n = n0 + nt*8;
                bb[nt][0] = dX[(kb+tig)*72 + n + g];
                bb[nt][1] = dX[(kb+tig+4)*72 + n + g];
            }
            #pragma unroll
            for (int mt = 0; mt < 2; mt++)
                #pragma unroll
                for (int nt = 0; nt < 4; nt++)
                    asm volatile(
                        "mma.sync.aligned.m16n8k16.row.col.f32.f16.f16.f32 "
                        "{%0,%1,%2,%3}, {%4,%5,%6,%7}, {%8,%9}, {%0,%1,%2,%3};"
                        : "+f"(c[mt][nt][0]), "+f"(c[mt][nt][1]),
                          "+f"(c[mt][nt][2]), "+f"(c[mt][nt][3])
                        : "r"(a[mt][0]), "r"(a[mt][1]), "r"(a[mt][2]), "r"(a[mt][3]),
                          "r"(bb[nt][0]), "r"(bb[nt][1]));
        }
        __syncthreads();
    }
    float* ob = g_s2 + bp*32768;
    #pragma unroll
    for (int mt = 0; mt < 2; mt++){
        int coA = m0 + mt*16 + g;
        int coB = coA + 8;
        float bA = bias[coA], bB = bias[coB];
        #pragma unroll
        for (int nt = 0; nt < 4; nt++){
            int px = n0b + n0 + nt*8 + 2*tig;
            *reinterpret_cast<float2*>(ob + coA*256 + px) =
                make_float2(c[mt][nt][0] + bA, c[mt][nt][1] + bA);
            *reinterpret_cast<float2*>(ob + coB*256 + px) =
                make_float2(c[mt][nt][2] + bB, c[mt][nt][3] + bB);
        }
    }
}

// ---- conv3 GEMM fp16, 3-stage cp.async. grid (64,4), 384 thr, 59904 B dyn ----
__global__ void __launch_bounds__(384) conv3gemm_kernel(const float* __restrict__ bias){
    extern __shared__ unsigned smu3[];
    int bp = blockIdx.x, n0b = blockIdx.y * 64;
    int t = threadIdx.x;
    int warp = t >> 5, lane = t & 31;
    int g = lane >> 2, tig = lane & 3;
    int m0 = (warp >> 1) * 32;
    int n0 = (warp & 1) * 32;
    float c[2][4][4];
    #pragma unroll
    for (int mt = 0; mt < 2; mt++)
        #pragma unroll
        for (int nt = 0; nt < 4; nt++)
            #pragma unroll
            for (int q = 0; q < 4; q++) c[mt][nt][q] = 0.f;
    const unsigned* xcb = g_x3colh + bp*147456 + n0b;

    auto stage = [&](int kp0, int buf){
        unsigned* dW = smu3 + buf*3840;
        unsigned* dX = smu3 + 11520 + buf*1152;
        #pragma unroll
        for (int s = 0; s < 2; s++){
            int e = t + s*384;
            int co = e >> 2, kq = (e & 3) * 4;
            cp16(&dW[co*20 + kq], &g_w3h[co*576 + kp0 + kq]);
        }
        if (t < 256){
            int kk = t >> 4, ps = (t & 15) * 4;
            cp16(&dX[kk*72 + ps], &xcb[(kp0 + kk)*256 + ps]);
        }
        asm volatile("cp.async.commit_group;" ::);
    };

    stage(0, 0);
    stage(16, 1);
    for (int it = 0; it < 36; it++){
        if (it + 2 < 36) stage((it+2)*16, (it+2) % 3);
        if (it <= 33)      asm volatile("cp.async.wait_group 2;" ::);
        else if (it == 34) asm volatile("cp.async.wait_group 1;" ::);
        else               asm volatile("cp.async.wait_group 0;" ::);
        __syncthreads();
        const unsigned* dW = smu3 + (it % 3)*3840;
        const unsigned* dX = smu3 + 11520 + (it % 3)*1152;
        #pragma unroll
        for (int ks = 0; ks < 2; ks++){
            int kb = ks*8;
            unsigned a[2][4], bb[4][2];
            #pragma unroll
            for (int mt = 0; mt < 2; mt++){
                int m = m0 + mt*16;
                a[mt][0] = dW[(m+g)*20 + kb + tig];
                a[mt][1] = dW[(m+g+8)*20 + kb + tig];
                a[mt][2] = dW[(m+g)*20 + kb + 4 + tig];
                a[mt][3] = dW[(m+g+8)*20 + kb + 4 + tig];
            }
            #pragma unroll
            for (int nt = 0; nt < 4; nt++){
                int n = n0 + nt*8;
                bb[nt][0] = dX[(kb+tig)*72 + n + g];
                bb[nt][1] = dX[(kb+tig+4)*72 + n + g];
            }
            #pragma unroll
            for (int mt = 0; mt < 2; mt++)
                #pragma unroll
                for (int nt = 0; nt < 4; nt++)
                    asm volatile(
                        "mma.sync.aligned.m16n8k16.row.col.f32.f16.f16.f32 "
                        "{%0,%1,%2,%3}, {%4,%5,%6,%7}, {%8,%9}, {%0,%1,%2,%3};"
                        : "+f"(c[mt][nt][0]), "+f"(c[mt][nt][1]),
                          "+f"(c[mt][nt][2]), "+f"(c[mt][nt][3])
                        : "r"(a[mt][0]), "r"(a[mt][1]), "r"(a[mt][2]), "r"(a[mt][3]),
                          "r"(bb[nt][0]), "r"(bb[nt][1]));
        }
        __syncthreads();
    }
    float* ob = g_y3 + bp*49152;
    #pragma unroll
    for (int mt = 0; mt < 2; mt++){
        int coA = m0 + mt*16 + g;
        int coB = coA + 8;
        float bA = bias[coA], bB = bias[coB];
        #pragma unroll
        for (int nt = 0; nt < 4; nt++){
            int px = n0b + n0 + nt*8 + 2*tig;
            *reinterpret_cast<float2*>(ob + coA*256 + px) =
                make_float2(c[mt][nt][0] + bA, c[mt][nt][1] + bA);
            *reinterpret_cast<float2*>(ob + coB*256 + px) =
                make_float2(c[mt][nt][2] + bB, c[mt][nt][3] + bB);
        }
    }
}

// ---- kv: LN + k_proj + v_proj. grid (64,5), 256 thr ----
__global__ void kv_kernel(const float* __restrict__ yg, const float* __restrict__ lnw,
                          const float* __restrict__ lnb, const float* __restrict__ Wk,
                          const float* __restrict__ Wv){
    __shared__ float s_kv[32*193];
    __shared__ float s_w[64*33];
    int bp = blockIdx.x;
    int r0 = blockIdx.y * 64;
    int t = threadIdx.x;
    int w = t >> 5, l = t & 31;
    for (int e = t; e < 6144; e += 256){
        int c = e >> 5, k = e & 31;
        s_kv[k*193 + c] = yg[bp*6144 + c*32 + k];
    }
    __syncthreads();
    {
        float lwv[6], lbv[6];
        #pragma unroll
        for (int i = 0; i < 6; i++){ lwv[i] = lnw[l+32*i]; lbv[i] = lnb[l+32*i]; }
        for (int ki = 0; ki < 4; ki++){
            int k = w*4 + ki;
            float v[6]; float s = 0.f;
            #pragma unroll
            for (int i = 0; i < 6; i++){ v[i] = s_kv[k*193 + l + 32*i]; s += v[i]; }
            #pragma unroll
            for (int o = 16; o > 0; o >>= 1) s += __shfl_xor_sync(0xffffffffu, s, o);
            float mu = s * (1.f/192.f);
            float vs = 0.f;
            #pragma unroll
            for (int i = 0; i < 6; i++){ float d = v[i]-mu; vs += d*d; }
            #pragma unroll
            for (int o = 16; o > 0; o >>= 1) vs += __shfl_xor_sync(0xffffffffu, vs, o);
            float rs = rsqrtf(vs * (1.f/192.f) + LN_EPS);
            #pragma unroll
            for (int i = 0; i < 6; i++)
                s_kv[k*193 + l + 32*i] = (v[i]-mu)*rs*lwv[i] + lbv[i];
        }
    }
    int kq = t & 7, rp = t >> 3;
    {
        float acc[2][4];
        #pragma unroll
        for (int i = 0; i < 2; i++)
            #pragma unroll
            for (int kk = 0; kk < 4; kk++) acc[i][kk] = 0.f;
        for (int c0 = 0; c0 < 192; c0 += 32){
            __syncthreads();
            for (int e = t; e < 2048; e += 256){
                int rr = e >> 5, cc = e & 31;
                int row = r0 + rr;
                s_w[rr*33 + cc] = (row < 128) ? Wk[row*192 + c0 + cc]
                                              : Wv[(row-128)*192 + c0 + cc];
            }
            __syncthreads();
            for (int cc = 0; cc < 32; cc++){
                float wv0 = s_w[(rp*2)*33 + cc], wv1 = s_w[(rp*2+1)*33 + cc];
                #pragma unroll
                for (int kk = 0; kk < 4; kk++){
                    float kvv = s_kv[(kq*4+kk)*193 + c0 + cc];
                    acc[0][kk] = fmaf(wv0, kvv, acc[0][kk]);
                    acc[1][kk] = fmaf(wv1, kvv, acc[1][kk]);
                }
            }
        }
        #pragma unroll
        for (int i = 0; i < 2; i++){
            int row = r0 + rp*2 + i;
            #pragma unroll
            for (int kk = 0; kk < 4; kk++){
                int k = kq*4 + kk;
                if (row < 128) g_kp[bp*4096 + k*128 + row] = acc[i][kk];
                else           g_vp[bp*6144 + k*192 + (row-128)] = acc[i][kk];
            }
        }
    }
}

// ---- attention core: LN(q)+q_proj+energy+softmax+context. grid 512, 256 thr, 71168 B ----
__global__ void attn_kernel(const float* __restrict__ lnqw, const float* __restrict__ lnqb,
                            const float* __restrict__ Wq, const float* __restrict__ vw){
    extern __shared__ float sm[];
    float* s_qn  = sm;            // 32*193
    float* s_w   = sm + 6176;     // 192*33 (overlaid by vp)
    float* s_kp  = sm + 12512;    // 32*132
    float* s_e   = sm + 16736;    // 32*33
    int bp = blockIdx.x >> 3;
    int q0 = (blockIdx.x & 7) << 5;
    int t = threadIdx.x;
    int w = t >> 5, l = t & 31;
    const float* y3 = g_y3 + bp*49152;
    for (int e = t; e < 6144; e += 256){
        int m = e >> 5, q = e & 31;
        s_qn[q*193 + m] = y3[m*256 + q0 + q];
    }
    for (int e = t; e < 4096; e += 256){
        int k = e >> 7;
        s_kp[k*132 + (e & 127)] = g_kp[bp*4096 + e];
    }
    __syncthreads();
    {
        float lwv[6], lbv[6];
        #pragma unroll
        for (int i = 0; i < 6; i++){ lwv[i] = lnqw[l+32*i]; lbv[i] = lnqb[l+32*i]; }
        for (int qi = 0; qi < 4; qi++){
            int q = w*4 + qi;
            float v[6]; float s = 0.f;
            #pragma unroll
            for (int i = 0; i < 6; i++){ v[i] = s_qn[q*193 + l + 32*i]; s += v[i]; }
            #pragma unroll
            for (int o = 16; o > 0; o >>= 1) s += __shfl_xor_sync(0xffffffffu, s, o);
            float mu = s * (1.f/192.f);
            float vs = 0.f;
            #pragma unroll
            for (int i = 0; i < 6; i++){ float d = v[i]-mu; vs += d*d; }
            #pragma unroll
            for (int o = 16; o > 0; o >>= 1) vs += __shfl_xor_sync(0xffffffffu, vs, o);
            float rs = rsqrtf(vs * (1.f/192.f) + LN_EPS);
            #pragma unroll
            for (int i = 0; i < 6; i++)
                s_qn[q*193 + l + 32*i] = (v[i]-mu)*rs*lwv[i] + lbv[i];
        }
    }
    float qp[4][4];
    #pragma unroll
    for (int a = 0; a < 4; a++)
        #pragma unroll
        for (int b2 = 0; b2 < 4; b2++) qp[a][b2] = 0.f;
    for (int c0 = 0; c0 < 192; c0 += 32){
        __syncthreads();
        for (int e = t; e < 4096; e += 256){
            int d = e >> 5, cc = e & 31;
            s_w[d*33 + cc] = Wq[d*192 + c0 + cc];
        }
        __syncthreads();
        for (int cc = 0; cc < 32; cc++){
            float wv[4], qv[4];
            #pragma unroll
            for (int j = 0; j < 4; j++) wv[j] = s_w[(l+32*j)*33 + cc];
            #pragma unroll
            for (int qi = 0; qi < 4; qi++) qv[qi] = s_qn[(w*4+qi)*193 + c0 + cc];
            #pragma unroll
            for (int qi = 0; qi < 4; qi++)
                #pragma unroll
                for (int j = 0; j < 4; j++) qp[qi][j] = fmaf(qv[qi], wv[j], qp[qi][j]);
        }
    }
    __syncthreads();
    float* s_vp = s_w;
    for (int e = t; e < 6144; e += 256){
        int k = e / 192, m = e - k*192;
        s_vp[k*193 + m] = g_vp[bp*6144 + e];
    }
    float vv[4];
    #pragma unroll
    for (int j = 0; j < 4; j++) vv[j] = vw[l + 32*j];
    for (int k = 0; k < 32; k++){
        float kp4[4];
        #pragma unroll
        for (int j = 0; j < 4; j++) kp4[j] = s_kp[k*132 + l + 32*j];
        #pragma unroll
        for (int qi = 0; qi < 4; qi++){
            float s = 0.f;
            #pragma unroll
            for (int j = 0; j < 4; j++)
                s = fmaf(tanh_fast(qp[qi][j] + kp4[j]), vv[j], s);
            #pragma unroll
            for (int o = 16; o > 0; o >>= 1) s += __shfl_xor_sync(0xffffffffu, s, o);
            if (l == 0) s_e[(w*4+qi)*33 + k] = s;
        }
    }
    __syncwarp();
    for (int qi = 0; qi < 4; qi++){
        int q = w*4 + qi;
        float ev = s_e[q*33 + l];
        float mx = ev;
        #pragma unroll
        for (int o = 16; o > 0; o >>= 1) mx = fmaxf(mx, __shfl_xor_sync(0xffffffffu, mx, o));
        float p = __expf(ev - mx);
        float s = p;
        #pragma unroll
        for (int o = 16; o > 0; o >>= 1) s += __shfl_xor_sync(0xffffffffu, s, o);
        s_e[q*33 + l] = p / s;
    }
    __syncthreads();
    // context -> fp16 gmem directly
    {
        int qr = t >> 3, mg = t & 7;
        float acc[24];
        #pragma unroll
        for (int i = 0; i < 24; i++) acc[i] = 0.f;
        for (int k = 0; k < 32; k++){
            float a = s_e[qr*33 + k];
            #pragma unroll
            for (int i = 0; i < 24; i++)
                acc[i] = fmaf(a, s_vp[k*193 + mg + 8*i], acc[i]);
        }
        __half* ch = reinterpret_cast<__half*>(g_ctxh) + (ull)(bp*256 + q0 + qr)*192;
        #pragma unroll
        for (int i = 0; i < 24; i++)
            ch[mg + 8*i] = __float2half_rn(acc[i]);
    }
    // normalized q -> g_qnT [bp][n][q]
    for (int e = t; e < 6144; e += 256){
        int n = e >> 5, q = e & 31;
        g_qnT[bp*49152 + n*256 + q0 + q] = s_qn[q*193 + n];
    }
}

// ---- outproj: C[192,64] = out_w @ ctx^T, + bias + residual + LN + transpose ----
// grid (64,4), 384 thr, 55808 B dyn
__global__ void __launch_bounds__(384) outproj_kernel(const float* __restrict__ outb,
                                                      const float* __restrict__ lnow,
                                                      const float* __restrict__ lnob,
                                                      float* __restrict__ out){
    extern __shared__ unsigned smo[];
    // pipeline: W bufs buf*2304 (192 rows x stride 12), X bufs 6912 + buf*768 (64 rows x stride 12)
    float* se = reinterpret_cast<float*>(smo);        // epilogue overlay: 192 x 68
    float* red = se + 13056;                          // 896 floats
    int bp = blockIdx.x, q0b = blockIdx.y * 64;
    int t = threadIdx.x;
    int warp = t >> 5, lane = t & 31;
    int g = lane >> 2, tig = lane & 3;
    int m0 = (warp >> 1) * 32;       // 0..160
    int n0 = (warp & 1) * 32;        // 0/32
    float c[2][4][4];
    #pragma unroll
    for (int mt = 0; mt < 2; mt++)
        #pragma unroll
        for (int nt = 0; nt < 4; nt++)
            #pragma unroll
            for (int q = 0; q < 4; q++) c[mt][nt][q] = 0.f;
    const unsigned* ctxw = g_ctxh + (ull)(bp*256 + q0b)*96;

    auto stage = [&](int kp0, int buf){
        unsigned* dW = smo + buf*2304;
        unsigned* dX = smo + 6912 + buf*768;
        {   // 384 W cps: 192 rows x 8 words
            int co = t >> 1, ps = (t & 1) * 4;
            cp16(&dW[co*12 + ps], &g_owh[co*96 + kp0 + ps]);
        }
        if (t < 128){  // 128 X cps: 64 rows x 8 words
            int q = t >> 1, ps = (t & 1) * 4;
            cp16(&dX[q*12 + ps], &ctxw[q*96 + kp0 + ps]);
        }
        asm volatile("cp.async.commit_group;" ::);
    };

    stage(0, 0);
    stage(8, 1);
    for (int it = 0; it < 12; it++){
        if (it + 2 < 12) stage((it+2)*8, (it+2) % 3);
        if (it <= 9)       asm volatile("cp.async.wait_group 2;" ::);
        else if (it == 10) asm volatile("cp.async.wait_group 1;" ::);
        else               asm volatile("cp.async.wait_group 0;" ::);
        __syncthreads();
        const unsigned* dW = smo + (it % 3)*2304;
        const unsigned* dX = smo + 6912 + (it % 3)*768;
        unsigned a[2][4], bb[4][2];
        #pragma unroll
        for (int mt = 0; mt < 2; mt++){
            int m = m0 + mt*16;
            a[mt][0] = dW[(m+g)*12 + tig];
            a[mt][1] = dW[(m+g+8)*12 + tig];
            a[mt][2] = dW[(m+g)*12 + 4 + tig];
            a[mt][3] = dW[(m+g+8)*12 + 4 + tig];
        }
        #pragma unroll
        for (int nt = 0; nt < 4; nt++){
            int n = n0 + nt*8;
            bb[nt][0] = dX[(n+g)*12 + tig];
            bb[nt][1] = dX[(n+g)*12 + 4 + tig];
        }
        #pragma unroll
        for (int mt = 0; mt < 2; mt++)
            #pragma unroll
            for (int nt = 0; nt < 4; nt++)
                asm volatile(
                    "mma.sync.aligned.m16n8k16.row.col.f32.f16.f16.f32 "
                    "{%0,%1,%2,%3}, {%4,%5,%6,%7}, {%8,%9}, {%0,%1,%2,%3};"
                    : "+f"(c[mt][nt][0]), "+f"(c[mt][nt][1]),
                      "+f"(c[mt][nt][2]), "+f"(c[mt][nt][3])
                    : "r"(a[mt][0]), "r"(a[mt][1]), "r"(a[mt][2]), "r"(a[mt][3]),
                      "r"(bb[nt][0]), "r"(bb[nt][1]));
        __syncthreads();
    }
    // epilogue: to smem (overlays pipeline region; all reads done)
    #pragma unroll
    for (int mt = 0; mt < 2; mt++){
        int coA = m0 + mt*16 + g;
        int coB = coA + 8;
        #pragma unroll
        for (int nt = 0; nt < 4; nt++){
            int px = n0 + nt*8 + 2*tig;
            se[coA*68 + px]     = c[mt][nt][0];
            se[coA*68 + px + 1] = c[mt][nt][1];
            se[coB*68 + px]     = c[mt][nt][2];
            se[coB*68 + px + 1] = c[mt][nt][3];
        }
    }
    __syncthreads();
    // residual + LN over n (192) per q; seg covers 32 n
    int seg = t >> 6, tq = t & 63;
    float val[32];
    float s = 0.f, ss = 0.f;
    const float* qn = g_qnT + bp*49152 + q0b + tq;
    #pragma unroll
    for (int i = 0; i < 32; i++){
        int n = seg*32 + i;
        float v = se[n*68 + tq] + outb[n] + qn[n*256];
        val[i] = v;
        s += v; ss += v*v;
    }
    red[seg*64 + tq] = s;
    red[384 + seg*64 + tq] = ss;
    __syncthreads();
    if (t < 64){
        float st = 0.f, sst = 0.f;
        #pragma unroll
        for (int k = 0; k < 6; k++){ st += red[k*64 + t]; sst += red[384 + k*64 + t]; }
        float mu = st * (1.f/192.f);
        float var = sst * (1.f/192.f) - mu*mu;
        red[768 + t] = mu;
        red[832 + t] = rsqrtf(var + LN_EPS);
    }
    __syncthreads();
    float mu = red[768 + tq], rs = red[832 + tq];
    float* ob = out + bp*49152 + q0b + tq;
    #pragma unroll
    for (int i = 0; i < 32; i++){
        int n = seg*32 + i;
        ob[n*256] = (val[i] - mu)*rs*lnow[n] + lnob[n];
    }
}

extern "C" void kernel_launch(void* const* d_in, const int* in_sizes, int n_in,
                              void* d_out, int out_size){
    const float* x_p    = (const float*)d_in[0];
    const float* y_g    = (const float*)d_in[1];
    const float* conv1w = (const float*)d_in[2];
    const float* conv1b = (const float*)d_in[3];
    const float* gamma1 = (const float*)d_in[4];
    const float* beta1  = (const float*)d_in[5];
    const float* conv2w = (const float*)d_in[6];
    const float* conv2b = (const float*)d_in[7];
    const float* gamma2 = (const float*)d_in[8];
    const float* beta2  = (const float*)d_in[9];
    const float* conv3w = (const float*)d_in[10];
    const float* conv3b = (const float*)d_in[11];
    const float* lnqw   = (const float*)d_in[12];
    const float* lnqb   = (const float*)d_in[13];
    const float* lnkw   = (const float*)d_in[14];
    const float* lnkb   = (const float*)d_in[15];
    const float* lnow   = (const float*)d_in[16];
    const float* lnob   = (const float*)d_in[17];
    const float* Wq     = (const float*)d_in[18];
    const float* Wk     = (const float*)d_in[19];
    const float* vw     = (const float*)d_in[20];
    const float* Wv     = (const float*)d_in[21];
    const float* outw   = (const float*)d_in[22];
    const float* outb   = (const float*)d_in[23];
    float* out = (float*)d_out;

    cudaFuncSetAttribute(attn_kernel, cudaFuncAttributeMaxDynamicSharedMemorySize, 71168);
    cudaFuncSetAttribute(conv2gemm_kernel, cudaFuncAttributeMaxDynamicSharedMemorySize, 44544);
    cudaFuncSetAttribute(conv3gemm_kernel, cudaFuncAttributeMaxDynamicSharedMemorySize, 59904);
    cudaFuncSetAttribute(outproj_kernel, cudaFuncAttributeMaxDynamicSharedMemorySize, 55808);

    conv1_kernel<<<dim3(64,4,2), 256>>>(x_p, conv1w, conv1b, gamma1, gamma2);  // 0
    gdn_kernel<<<1024, 256>>>(1, beta1, conv2w, conv3w, outw);                  // 1
    im2col2_kernel<<<dim3(800,64), 256>>>();                                    // 2
    conv2gemm_kernel<<<dim3(64,4), 256, 44544>>>(conv2b);                       // 3 (profiled)
    gdn_kernel<<<256, 256>>>(2, beta2, nullptr, nullptr, nullptr);              // 4
    im2col3_kernel<<<dim3(288,64), 256>>>();                                    // 5
    conv3gemm_kernel<<<dim3(64,4), 384, 59904>>>(conv3b);                       // 6
    kv_kernel<<<dim3(64,5), 256>>>(y_g, lnkw, lnkb, Wk, Wv);                    // 7
    attn_kernel<<<512, 256, 71168>>>(lnqw, lnqb, Wq, vw);                       // 8
    outproj_kernel<<<dim3(64,4), 384, 55808>>>(outb, lnow, lnob, out);          // 9
}

// round 15
// speedup vs baseline: 3.4575x; 1.0155x over previous
#include <cuda_runtime.h>
#include <cuda_fp16.h>

#define LN_EPS 1e-5f
typedef unsigned long long ull;

// ---- scratch ----
__device__ float g_s1[64*128*1024];
__device__ float g_s2[64*128*256];
__device__ float g_y3[64*192*256];
__device__ float g_kp[64*32*128];
__device__ float g_vp[64*32*192];
__device__ float g_gT[2][16384];
__device__ unsigned g_xcolh[64*1600*256];
__device__ unsigned g_x3colh[64*576*256];
__device__ unsigned g_w2h[128*1600];
__device__ unsigned g_w3h[192*576];
__device__ unsigned g_owh[192*96];
__device__ unsigned g_wqh[128*96];          // Wq half2 [d][mp]
__device__ unsigned g_qnh[64*96*256];       // qn half2 [bp][mp][q]
__device__ float g_qp[64*128*256];          // q_proj [bp][d][q]
__device__ unsigned g_ctxh[64*256*96];      // context fp16 [token][mp]
__device__ float g_qnT[64*192*256];         // normalized q [bp][n][q]

__device__ __forceinline__ float tanh_fast(float x){
    float y; asm("tanh.approx.f32 %0, %1;" : "=f"(y) : "f"(x)); return y;
}
__device__ __forceinline__ ull pk2(float lo, float hi){
    ull r; asm("mov.b64 %0, {%1, %2};" : "=l"(r) : "f"(lo), "f"(hi)); return r;
}
__device__ __forceinline__ ull pkdup(float v){ return pk2(v, v); }
__device__ __forceinline__ void upk2(ull p, float& lo, float& hi){
    asm("mov.b64 {%0, %1}, %2;" : "=f"(lo), "=f"(hi) : "l"(p));
}
__device__ __forceinline__ ull ffma2(ull a, ull b, ull c){
    ull d; asm("fma.rn.f32x2 %0, %1, %2, %3;" : "=l"(d) : "l"(a), "l"(b), "l"(c)); return d;
}
__device__ __forceinline__ unsigned packh(float v0, float v1){
    __half h0 = __float2half_rn(v0), h1 = __float2half_rn(v1);
    return (unsigned)__half_as_ushort(h0) | ((unsigned)__half_as_ushort(h1) << 16);
}
__device__ __forceinline__ void cp16(unsigned* sp, const unsigned* gp){
    unsigned sa = (unsigned)__cvta_generic_to_shared(sp);
    asm volatile("cp.async.cg.shared.global [%0], [%1], 16;" :: "r"(sa), "l"(gp));
}

// ---- conv1 (+ gamma transpose fold): grid (64,4,2), 256 thr ----
__global__ void conv1_kernel(const float* __restrict__ x, const float* __restrict__ w,
                             const float* __restrict__ b, const float* __restrict__ g1,
                             const float* __restrict__ g2){
    __shared__ float sw[4800];
    __shared__ float sin_[3885];
    int bp = blockIdx.x, tile = blockIdx.y, z = blockIdx.z;
    int t = threadIdx.x;
    if (z == 0){
        int blk = bp*4 + tile;
        for (int i = t; i < 128; i += 256){
            int e = blk*128 + i;
            int which = e >> 14, idx = e & 16383;
            const float* g = which ? g2 : g1;
            g_gT[which][(idx & 127)*128 + (idx >> 7)] = g[idx];
        }
    }
    for (int e = t; e < 4800; e += 256) sw[e] = w[z*4800 + e];
    int ty0 = (tile>>1)*16, tx0 = (tile&1)*16;
    int iy0 = 2*ty0 - 2, ix0 = 2*tx0 - 2;
    const float* xb = x + bp*12288;
    for (int e = t; e < 3675; e += 256){
        int c = e/1225, rem = e - c*1225, r = rem/35, col = rem - r*35;
        int gy = iy0 + r, gx = ix0 + col;
        float v = 0.f;
        if (gy>=0 && gy<64 && gx>=0 && gx<64) v = xb[c*4096 + gy*64 + gx];
        sin_[(c*35 + r)*37 + col] = v;
    }
    __syncthreads();
    int px4 = t & 63, cog = t >> 6;
    int ly = px4 >> 2, lx0 = (px4 & 3)*4;
    float* ob = g_s1 + bp*131072;
    for (int p = 0; p < 2; p++){
        int col0 = cog*16 + p*8;
        float acc[8][4];
        #pragma unroll
        for (int i = 0; i < 8; i++){
            float bb = b[z*64 + col0 + i];
            #pragma unroll
            for (int j = 0; j < 4; j++) acc[i][j] = bb;
        }
        #pragma unroll 1
        for (int c = 0; c < 3; c++){
            #pragma unroll
            for (int ky = 0; ky < 5; ky++){
                #pragma unroll
                for (int kx = 0; kx < 5; kx++){
                    float xv[4];
                    #pragma unroll
                    for (int j = 0; j < 4; j++)
                        xv[j] = sin_[(c*35 + 2*ly + ky)*37 + 2*lx0 + 2*j + kx];
                    #pragma unroll
                    for (int i = 0; i < 8; i++){
                        float wv = sw[(col0+i)*75 + c*25 + ky*5 + kx];
                        #pragma unroll
                        for (int j = 0; j < 4; j++) acc[i][j] = fmaf(wv, xv[j], acc[i][j]);
                    }
                }
            }
        }
        #pragma unroll
        for (int i = 0; i < 8; i++){
            float4 o = make_float4(acc[i][0], acc[i][1], acc[i][2], acc[i][3]);
            *reinterpret_cast<float4*>(ob + (z*64+col0+i)*1024 + (ty0+ly)*32 + tx0 + lx0) = o;
        }
    }
}

// ---- GDN in-place (f32x2) + W half-pack folds on stage 1 ----
__global__ void gdn_kernel(int stage, const float* __restrict__ beta,
                           const float* __restrict__ w2, const float* __restrict__ w3,
                           const float* __restrict__ ow, const float* __restrict__ wq){
    __shared__ float sA[2048];
    __shared__ float sB[1088];
    int HW = (stage == 1) ? 1024 : 256;
    float* x = (stage == 1) ? g_s1 : g_s2;
    const float* gT = g_gT[stage-1];
    int chunks = HW >> 6;
    int bp = blockIdx.x / chunks;
    int p0 = (blockIdx.x - bp*chunks) * 64;
    int t = threadIdx.x;
    if (stage == 1){
        int b2 = blockIdx.x * 200;
        for (int i = t; i < 200; i += 256){
            int e = b2 + i;
            g_w2h[e] = packh(w2[2*e], w2[2*e+1]);
        }
        int b3 = blockIdx.x * 108;
        for (int i = t; i < 108; i += 256){
            int e = b3 + i;
            g_w3h[e] = packh(w3[2*e], w3[2*e+1]);
        }
        int b4 = blockIdx.x * 18;
        for (int i = t; i < 18; i += 256){
            int e = b4 + i;
            g_owh[e] = packh(ow[2*e], ow[2*e+1]);
        }
        int b5 = blockIdx.x * 12;
        for (int i = t; i < 12; i += 256){
            int e = b5 + i;
            g_wqh[e] = packh(wq[2*e], wq[2*e+1]);
        }
    }
    int i = t >> 4, j = t & 15;
    float* xb = x + bp*128*HW;
    ull acc[8][2];
    #pragma unroll
    for (int ii = 0; ii < 8; ii++){
        float bb = beta[i*8 + ii];
        acc[ii][0] = pkdup(bb); acc[ii][1] = pkdup(bb);
    }
    for (int c0 = 0; c0 < 128; c0 += 16){
        __syncthreads();
        for (int e = t; e < 2048; e += 256) sA[e] = gT[c0*128 + e];
        for (int e = t; e < 1024; e += 256){
            int cc = e >> 6, p = e & 63;
            float v = xb[(c0+cc)*HW + p0 + p];
            sB[cc*68 + p] = v*v;
        }
        __syncthreads();
        #pragma unroll
        for (int cc = 0; cc < 16; cc++){
            const ull* xp = reinterpret_cast<const ull*>(sB + cc*68 + j*4);
            ull x0 = xp[0], x1 = xp[1];
            float4 ga = *reinterpret_cast<const float4*>(sA + cc*128 + i*8);
            float4 gb = *reinterpret_cast<const float4*>(sA + cc*128 + i*8 + 4);
            float gs[8] = {ga.x,ga.y,ga.z,ga.w,gb.x,gb.y,gb.z,gb.w};
            #pragma unroll
            for (int ii = 0; ii < 8; ii++){
                ull wp = pkdup(gs[ii]);
                acc[ii][0] = ffma2(x0, wp, acc[ii][0]);
                acc[ii][1] = ffma2(x1, wp, acc[ii][1]);
            }
        }
    }
    #pragma unroll
    for (int ii = 0; ii < 8; ii++){
        int d = i*8 + ii;
        float a0,a1,a2,a3;
        upk2(acc[ii][0], a0, a1);
        upk2(acc[ii][1], a2, a3);
        float4 xv = *reinterpret_cast<const float4*>(xb + d*HW + p0 + j*4);
        float4 o;
        o.x = xv.x * rsqrtf(a0);
        o.y = xv.y * rsqrtf(a1);
        o.z = xv.z * rsqrtf(a2);
        o.w = xv.w * rsqrtf(a3);
        *reinterpret_cast<float4*>(xb + d*HW + p0 + j*4) = o;
    }
}

// ---- conv2 im2col (half2-packed out): grid (800,64), 256 thr ----
__global__ void im2col2_kernel(){
    int bp = blockIdx.y;
    int t = threadIdx.x;
    int oy = t >> 4, ox = t & 15;
    const float* xb = g_s1 + bp*131072;
    unsigned* xc = g_xcolh + bp*409600;
    int base = blockIdx.x*4;
    #pragma unroll
    for (int kpi = 0; kpi < 2; kpi++){
        float v[2];
        #pragma unroll
        for (int h = 0; h < 2; h++){
            int k = base + kpi*2 + h;
            int ci = k / 25, r = k - ci*25;
            int ky = r / 5, kx = r - ky*5;
            int iy = 2*oy - 2 + ky, ix = 2*ox - 2 + kx;
            float vv = 0.f;
            if (iy>=0 && iy<32 && ix>=0 && ix<32) vv = xb[ci*1024 + iy*32 + ix];
            v[h] = vv;
        }
        xc[((base >> 1) + kpi)*256 + t] = packh(v[0], v[1]);
    }
}

// ---- conv3 im2col (half2-packed out): grid (288,64), 256 thr ----
__global__ void im2col3_kernel(){
    int bp = blockIdx.y;
    int t = threadIdx.x;
    int oy = t >> 4, ox = t & 15;
    const float* xb = g_s2 + bp*32768;
    unsigned* xc = g_x3colh + bp*147456;
    int base = blockIdx.x*4;
    #pragma unroll
    for (int kpi = 0; kpi < 2; kpi++){
        float v[2];
        #pragma unroll
        for (int h = 0; h < 2; h++){
            int k = base + kpi*2 + h;
            int ci = k / 9, r = k - ci*9;
            int ky = r / 3, kx = r - ky*3;
            int iy = oy - 1 + ky, ix = ox - 1 + kx;
            float vv = 0.f;
            if (iy>=0 && iy<16 && ix>=0 && ix<16) vv = xb[ci*256 + iy*16 + ix];
            v[h] = vv;
        }
        xc[((base >> 1) + kpi)*256 + t] = packh(v[0], v[1]);
    }
}

// ---- conv2 GEMM fp16, 3-stage cp.async. grid (64,4), 256 thr, 44544 B dyn ----
__global__ void __launch_bounds__(256) conv2gemm_kernel(const float* __restrict__ bias){
    extern __shared__ unsigned smu[];
    int bp = blockIdx.x, n0b = blockIdx.y * 64;
    int t = threadIdx.x;
    int warp = t >> 5, lane = t & 31;
    int g = lane >> 2, tig = lane & 3;
    int m0 = (warp >> 1) * 32;
    int n0 = (warp & 1) * 32;
    float c[2][4][4];
    #pragma unroll
    for (int mt = 0; mt < 2; mt++)
        #pragma unroll
        for (int nt = 0; nt < 4; nt++)
            #pragma unroll
            for (int q = 0; q < 4; q++) c[mt][nt][q] = 0.f;
    const unsigned* xcb = g_xcolh + bp*409600 + n0b;

    auto stage = [&](int kp0, int buf){
        unsigned* dW = smu + buf*2560;
        unsigned* dX = smu + 7680 + buf*1152;
        #pragma unroll
        for (int s = 0; s < 2; s++){
            int e = t + s*256;
            int co = e >> 2, kq = (e & 3) * 4;
            cp16(&dW[co*20 + kq], &g_w2h[co*1600 + kp0 + kq]);
        }
        {
            int kk = t >> 4, ps = (t & 15) * 4;
            cp16(&dX[kk*72 + ps], &xcb[(kp0 + kk)*256 + ps]);
        }
        asm volatile("cp.async.commit_group;" ::);
    };

    stage(0, 0);
    stage(16, 1);
    for (int it = 0; it < 100; it++){
        if (it + 2 < 100) stage((it+2)*16, (it+2) % 3);
        if (it <= 97)      asm volatile("cp.async.wait_group 2;" ::);
        else if (it == 98) asm volatile("cp.async.wait_group 1;" ::);
        else               asm volatile("cp.async.wait_group 0;" ::);
        __syncthreads();
        const unsigned* dW = smu + (it % 3)*2560;
        const unsigned* dX = smu + 7680 + (it % 3)*1152;
        #pragma unroll
        for (int ks = 0; ks < 2; ks++){
            int kb = ks*8;
            unsigned a[2][4], bb[4][2];
            #pragma unroll
            for (int mt = 0; mt < 2; mt++){
                int m = m0 + mt*16;
                a[mt][0] = dW[(m+g)*20 + kb + tig];
                a[mt][1] = dW[(m+g+8)*20 + kb + tig];
                a[mt][2] = dW[(m+g)*20 + kb + 4 + tig];
                a[mt][3] = dW[(m+g+8)*20 + kb + 4 + tig];
            }
            #pragma unroll
            for (int nt = 0; nt < 4; nt++){
                int n = n0 + nt*8;
                bb[nt][0] = dX[(kb+tig)*72 + n + g];
                bb[nt][1] = dX[(kb+tig+4)*72 + n + g];
            }
            #pragma unroll
            for (int mt = 0; mt < 2; mt++)
                #pragma unroll
                for (int nt = 0; nt < 4; nt++)
                    asm volatile(
                        "mma.sync.aligned.m16n8k16.row.col.f32.f16.f16.f32 "
                        "{%0,%1,%2,%3}, {%4,%5,%6,%7}, {%8,%9}, {%0,%1,%2,%3};"
                        : "+f"(c[mt][nt][0]), "+f"(c[mt][nt][1]),
                          "+f"(c[mt][nt][2]), "+f"(c[mt][nt][3])
                        : "r"(a[mt][0]), "r"(a[mt][1]), "r"(a[mt][2]), "r"(a[mt][3]),
                          "r"(bb[nt][0]), "r"(bb[nt][1]));
        }
        __syncthreads();
    }
    float* ob = g_s2 + bp*32768;
    #pragma unroll
    for (int mt = 0; mt < 2; mt++){
        int coA = m0 + mt*16 + g;
        int coB = coA + 8;
        float bA = bias[coA], bB = bias[coB];
        #pragma unroll
        for (int nt = 0; nt < 4; nt++){
            int px = n0b + n0 + nt*8 + 2*tig;
            *reinterpret_cast<float2*>(ob + coA*256 + px) =
                make_float2(c[mt][nt][0] + bA, c[mt][nt][1] + bA);
            *reinterpret_cast<float2*>(ob + coB*256 + px) =
                make_float2(c[mt][nt][2] + bB, c[mt][nt][3] + bB);
        }
    }
}

// ---- conv3 GEMM fp16, 3-stage cp.async. grid (64,4), 384 thr, 59904 B dyn ----
__global__ void __launch_bounds__(384) conv3gemm_kernel(const float* __restrict__ bias){
    extern __shared__ unsigned smu3[];
    int bp = blockIdx.x, n0b = blockIdx.y * 64;
    int t = threadIdx.x;
    int warp = t >> 5, lane = t & 31;
    int g = lane >> 2, tig = lane & 3;
    int m0 = (warp >> 1) * 32;
    int n0 = (warp & 1) * 32;
    float c[2][4][4];
    #pragma unroll
    for (int mt = 0; mt < 2; mt++)
        #pragma unroll
        for (int nt = 0; nt < 4; nt++)
            #pragma unroll
            for (int q = 0; q < 4; q++) c[mt][nt][q] = 0.f;
    const unsigned* xcb = g_x3colh + bp*147456 + n0b;

    auto stage = [&](int kp0, int buf){
        unsigned* dW = smu3 + buf*3840;
        unsigned* dX = smu3 + 11520 + buf*1152;
        #pragma unroll
        for (int s = 0; s < 2; s++){
            int e = t + s*384;
            int co = e >> 2, kq = (e & 3) * 4;
            cp16(&dW[co*20 + kq], &g_w3h[co*576 + kp0 + kq]);
        }
        if (t < 256){
            int kk = t >> 4, ps = (t & 15) * 4;
            cp16(&dX[kk*72 + ps], &xcb[(kp0 + kk)*256 + ps]);
        }
        asm volatile("cp.async.commit_group;" ::);
    };

    stage(0, 0);
    stage(16, 1);
    for (int it = 0; it < 36; it++){
        if (it + 2 < 36) stage((it+2)*16, (it+2) % 3);
        if (it <= 33)      asm volatile("cp.async.wait_group 2;" ::);
        else if (it == 34) asm volatile("cp.async.wait_group 1;" ::);
        else               asm volatile("cp.async.wait_group 0;" ::);
        __syncthreads();
        const unsigned* dW = smu3 + (it % 3)*3840;
        const unsigned* dX = smu3 + 11520 + (it % 3)*1152;
        #pragma unroll
        for (int ks = 0; ks < 2; ks++){
            int kb = ks*8;
            unsigned a[2][4], bb[4][2];
            #pragma unroll
            for (int mt = 0; mt < 2; mt++){
                int m = m0 + mt*16;
                a[mt][0] = dW[(m+g)*20 + kb + tig];
                a[mt][1] = dW[(m+g+8)*20 + kb + tig];
                a[mt][2] = dW[(m+g)*20 + kb + 4 + tig];
                a[mt][3] = dW[(m+g+8)*20 + kb + 4 + tig];
            }
            #pragma unroll
            for (int nt = 0; nt < 4; nt++){
                int n = n0 + nt*8;
                bb[nt][0] = dX[(kb+tig)*72 + n + g];
                bb[nt][1] = dX[(kb+tig+4)*72 + n + g];
            }
            #pragma unroll
            for (int mt = 0; mt < 2; mt++)
                #pragma unroll
                for (int nt = 0; nt < 4; nt++)
                    asm volatile(
                        "mma.sync.aligned.m16n8k16.row.col.f32.f16.f16.f32 "
                        "{%0,%1,%2,%3}, {%4,%5,%6,%7}, {%8,%9}, {%0,%1,%2,%3};"
                        : "+f"(c[mt][nt][0]), "+f"(c[mt][nt][1]),
                          "+f"(c[mt][nt][2]), "+f"(c[mt][nt][3])
                        : "r"(a[mt][0]), "r"(a[mt][1]), "r"(a[mt][2]), "r"(a[mt][3]),
                          "r"(bb[nt][0]), "r"(bb[nt][1]));
        }
        __syncthreads();
    }
    float* ob = g_y3 + bp*49152;
    #pragma unroll
    for (int mt = 0; mt < 2; mt++){
        int coA = m0 + mt*16 + g;
        int coB = coA + 8;
        float bA = bias[coA], bB = bias[coB];
        #pragma unroll
        for (int nt = 0; nt < 4; nt++){
            int px = n0b + n0 + nt*8 + 2*tig;
            *reinterpret_cast<float2*>(ob + coA*256 + px) =
                make_float2(c[mt][nt][0] + bA, c[mt][nt][1] + bA);
            *reinterpret_cast<float2*>(ob + coB*256 + px) =
                make_float2(c[mt][nt][2] + bB, c[mt][nt][3] + bB);
        }
    }
}

// ---- qn: LN of y3 -> g_qnT (fp32) + g_qnh (half2). grid (64,8), 256 thr ----
__global__ void qn_kernel(const float* __restrict__ lnqw, const float* __restrict__ lnqb){
    __shared__ float s[192*33];
    int bp = blockIdx.x, q0 = blockIdx.y << 5;
    int t = threadIdx.x;
    int w = t >> 5, l = t & 31;
    const float* y3 = g_y3 + bp*49152;
    for (int e = t; e < 6144; e += 256){
        int m = e >> 5, qq = e & 31;
        s[m*33 + qq] = y3[m*256 + q0 + qq];
    }
    __syncthreads();
    {
        float lwv[6], lbv[6];
        #pragma unroll
        for (int i = 0; i < 6; i++){ lwv[i] = lnqw[l+32*i]; lbv[i] = lnqb[l+32*i]; }
        for (int qi = 0; qi < 4; qi++){
            int q = w*4 + qi;
            float v[6]; float sum = 0.f;
            #pragma unroll
            for (int i = 0; i < 6; i++){ v[i] = s[(l+32*i)*33 + q]; sum += v[i]; }
            #pragma unroll
            for (int o = 16; o > 0; o >>= 1) sum += __shfl_xor_sync(0xffffffffu, sum, o);
            float mu = sum * (1.f/192.f);
            float vs = 0.f;
            #pragma unroll
            for (int i = 0; i < 6; i++){ float d = v[i]-mu; vs += d*d; }
            #pragma unroll
            for (int o = 16; o > 0; o >>= 1) vs += __shfl_xor_sync(0xffffffffu, vs, o);
            float rs = rsqrtf(vs * (1.f/192.f) + LN_EPS);
            #pragma unroll
            for (int i = 0; i < 6; i++)
                s[(l+32*i)*33 + q] = (v[i]-mu)*rs*lwv[i] + lbv[i];
        }
    }
    __syncthreads();
    float* qt = g_qnT + bp*49152;
    for (int e = t; e < 6144; e += 256){
        int n = e >> 5, qq = e & 31;
        qt[n*256 + q0 + qq] = s[n*33 + qq];
    }
    unsigned* qh = g_qnh + bp*24576;
    for (int e = t; e < 3072; e += 256){
        int mp = e >> 5, qq = e & 31;
        qh[mp*256 + q0 + qq] = packh(s[(2*mp)*33 + qq], s[(2*mp+1)*33 + qq]);
    }
}

// ---- qproj GEMM fp16: QP[128d,256q] = Wq @ qn^T. grid (64,4), 256 thr, 44544 B ----
__global__ void __launch_bounds__(256) qproj_kernel(){
    extern __shared__ unsigned smq[];
    int bp = blockIdx.x, n0b = blockIdx.y * 64;
    int t = threadIdx.x;
    int warp = t >> 5, lane = t & 31;
    int g = lane >> 2, tig = lane & 3;
    int m0 = (warp >> 1) * 32;
    int n0 = (warp & 1) * 32;
    float c[2][4][4];
    #pragma unroll
    for (int mt = 0; mt < 2; mt++)
        #pragma unroll
        for (int nt = 0; nt < 4; nt++)
            #pragma unroll
            for (int q = 0; q < 4; q++) c[mt][nt][q] = 0.f;
    const unsigned* xcb = g_qnh + bp*24576 + n0b;

    auto stage = [&](int kp0, int buf){
        unsigned* dW = smq + buf*2560;
        unsigned* dX = smq + 7680 + buf*1152;
        #pragma unroll
        for (int s = 0; s < 2; s++){
            int e = t + s*256;
            int co = e >> 2, kq = (e & 3) * 4;
            cp16(&dW[co*20 + kq], &g_wqh[co*96 + kp0 + kq]);
        }
        {
            int kk = t >> 4, ps = (t & 15) * 4;
            cp16(&dX[kk*72 + ps], &xcb[(kp0 + kk)*256 + ps]);
        }
        asm volatile("cp.async.commit_group;" ::);
    };

    stage(0, 0);
    stage(16, 1);
    for (int it = 0; it < 6; it++){
        if (it + 2 < 6) stage((it+2)*16, (it+2) % 3);
        if (it <= 3)      asm volatile("cp.async.wait_group 2;" ::);
        else if (it == 4) asm volatile("cp.async.wait_group 1;" ::);
        else              asm volatile("cp.async.wait_group 0;" ::);
        __syncthreads();
        const unsigned* dW = smq + (it % 3)*2560;
        const unsigned* dX = smq + 7680 + (it % 3)*1152;
        #pragma unroll
        for (int ks = 0; ks < 2; ks++){
            int kb = ks*8;
            unsigned a[2][4], bb[4][2];
            #pragma unroll
            for (int mt = 0; mt < 2; mt++){
                int m = m0 + mt*16;
                a[mt][0] = dW[(m+g)*20 + kb + tig];
                a[mt][1] = dW[(m+g+8)*20 + kb + tig];
                a[mt][2] = dW[(m+g)*20 + kb + 4 + tig];
                a[mt][3] = dW[(m+g+8)*20 + kb + 4 + tig];
            }
            #pragma unroll
            for (int nt = 0; nt < 4; nt++){
                int n = n0 + nt*8;
                bb[nt][0] = dX[(kb+tig)*72 + n + g];
                bb[nt][1] = dX[(kb+tig+4)*72 + n + g];
            }
            #pragma unroll
            for (int mt = 0; mt < 2; mt++)
                #pragma unroll
                for (int nt = 0; nt < 4; nt++)
                    asm volatile(
                        "mma.sync.aligned.m16n8k16.row.col.f32.f16.f16.f32 "
                        "{%0,%1,%2,%3}, {%4,%5,%6,%7}, {%8,%9}, {%0,%1,%2,%3};"
                        : "+f"(c[mt][nt][0]), "+f"(c[mt][nt][1]),
                          "+f"(c[mt][nt][2]), "+f"(c[mt][nt][3])
                        : "r"(a[mt][0]), "r"(a[mt][1]), "r"(a[mt][2]), "r"(a[mt][3]),
                          "r"(bb[nt][0]), "r"(bb[nt][1]));
        }
        __syncthreads();
    }
    float* ob = g_qp + bp*32768;
    #pragma unroll
    for (int mt = 0; mt < 2; mt++){
        int coA = m0 + mt*16 + g;
        int coB = coA + 8;
        #pragma unroll
        for (int nt = 0; nt < 4; nt++){
            int px = n0b + n0 + nt*8 + 2*tig;
            *reinterpret_cast<float2*>(ob + coA*256 + px) =
                make_float2(c[mt][nt][0], c[mt][nt][1]);
            *reinterpret_cast<float2*>(ob + coB*256 + px) =
                make_float2(c[mt][nt][2], c[mt][nt][3]);
        }
    }
}

// ---- kv: LN + k_proj + v_proj. grid (64,5), 256 thr ----
__global__ void kv_kernel(const float* __restrict__ yg, const float* __restrict__ lnw,
                          const float* __restrict__ lnb, const float* __restrict__ Wk,
                          const float* __restrict__ Wv){
    __shared__ float s_kv[32*193];
    __shared__ float s_w[64*33];
    int bp = blockIdx.x;
    int r0 = blockIdx.y * 64;
    int t = threadIdx.x;
    int w = t >> 5, l = t & 31;
    for (int e = t; e < 6144; e += 256){
        int c = e >> 5, k = e & 31;
        s_kv[k*193 + c] = yg[bp*6144 + c*32 + k];
    }
    __syncthreads();
    {
        float lwv[6], lbv[6];
        #pragma unroll
        for (int i = 0; i < 6; i++){ lwv[i] = lnw[l+32*i]; lbv[i] = lnb[l+32*i]; }
        for (int ki = 0; ki < 4; ki++){
            int k = w*4 + ki;
            float v[6]; float s = 0.f;
            #pragma unroll
            for (int i = 0; i < 6; i++){ v[i] = s_kv[k*193 + l + 32*i]; s += v[i]; }
            #pragma unroll
            for (int o = 16; o > 0; o >>= 1) s += __shfl_xor_sync(0xffffffffu, s, o);
            float mu = s * (1.f/192.f);
            float vs = 0.f;
            #pragma unroll
            for (int i = 0; i < 6; i++){ float d = v[i]-mu; vs += d*d; }
            #pragma unroll
            for (int o = 16; o > 0; o >>= 1) vs += __shfl_xor_sync(0xffffffffu, vs, o);
            float rs = rsqrtf(vs * (1.f/192.f) + LN_EPS);
            #pragma unroll
            for (int i = 0; i < 6; i++)
                s_kv[k*193 + l + 32*i] = (v[i]-mu)*rs*lwv[i] + lbv[i];
        }
    }
    int kq = t & 7, rp = t >> 3;
    {
        float acc[2][4];
        #pragma unroll
        for (int i = 0; i < 2; i++)
            #pragma unroll
            for (int kk = 0; kk < 4; kk++) acc[i][kk] = 0.f;
        for (int c0 = 0; c0 < 192; c0 += 32){
            __syncthreads();
            for (int e = t; e < 2048; e += 256){
                int rr = e >> 5, cc = e & 31;
                int row = r0 + rr;
                s_w[rr*33 + cc] = (row < 128) ? Wk[row*192 + c0 + cc]
                                              : Wv[(row-128)*192 + c0 + cc];
            }
            __syncthreads();
            for (int cc = 0; cc < 32; cc++){
                float wv0 = s_w[(rp*2)*33 + cc], wv1 = s_w[(rp*2+1)*33 + cc];
                #pragma unroll
                for (int kk = 0; kk < 4; kk++){
                    float kvv = s_kv[(kq*4+kk)*193 + c0 + cc];
                    acc[0][kk] = fmaf(wv0, kvv, acc[0][kk]);
                    acc[1][kk] = fmaf(wv1, kvv, acc[1][kk]);
                }
            }
        }
        #pragma unroll
        for (int i = 0; i < 2; i++){
            int row = r0 + rp*2 + i;
            #pragma unroll
            for (int kk = 0; kk < 4; kk++){
                int k = kq*4 + kk;
                if (row < 128) g_kp[bp*4096 + k*128 + row] = acc[i][kk];
                else           g_vp[bp*6144 + k*192 + (row-128)] = acc[i][kk];
            }
        }
    }
}

// ---- attention core: energy+softmax+context. grid 512, 256 thr, 62720 B dyn ----
__global__ void attn_kernel(const float* __restrict__ vw){
    extern __shared__ float sm[];
    float* s_kp = sm;             // 32*132
    float* s_vp = sm + 4224;      // 32*193
    float* s_e  = sm + 10400;     // 32*33
    float* s_qp = sm + 11456;     // 128*33
    int bp = blockIdx.x >> 3;
    int q0 = (blockIdx.x & 7) << 5;
    int t = threadIdx.x;
    int w = t >> 5, l = t & 31;
    for (int e = t; e < 4096; e += 256){
        int k = e >> 7;
        s_kp[k*132 + (e & 127)] = g_kp[bp*4096 + e];
    }
    for (int e = t; e < 6144; e += 256){
        int k = e / 192, m = e - k*192;
        s_vp[k*193 + m] = g_vp[bp*6144 + e];
    }
    {
        const float* qpb = g_qp + bp*32768;
        for (int e = t; e < 4096; e += 256){
            int d = e >> 5, qq = e & 31;
            s_qp[d*33 + qq] = qpb[d*256 + q0 + qq];
        }
    }
    __syncthreads();
    float vv[4];
    #pragma unroll
    for (int j = 0; j < 4; j++) vv[j] = vw[l + 32*j];
    for (int k = 0; k < 32; k++){
        float kp4[4];
        #pragma unroll
        for (int j = 0; j < 4; j++) kp4[j] = s_kp[k*132 + l + 32*j];
        #pragma unroll
        for (int qi = 0; qi < 4; qi++){
            int q = w*4 + qi;
            float s = 0.f;
            #pragma unroll
            for (int j = 0; j < 4; j++)
                s = fmaf(tanh_fast(s_qp[(l+32*j)*33 + q] + kp4[j]), vv[j], s);
            #pragma unroll
            for (int o = 16; o > 0; o >>= 1) s += __shfl_xor_sync(0xffffffffu, s, o);
            if (l == 0) s_e[q*33 + k] = s;
        }
    }
    __syncwarp();
    for (int qi = 0; qi < 4; qi++){
        int q = w*4 + qi;
        float ev = s_e[q*33 + l];
        float mx = ev;
        #pragma unroll
        for (int o = 16; o > 0; o >>= 1) mx = fmaxf(mx, __shfl_xor_sync(0xffffffffu, mx, o));
        float p = __expf(ev - mx);
        float s = p;
        #pragma unroll
        for (int o = 16; o > 0; o >>= 1) s += __shfl_xor_sync(0xffffffffu, s, o);
        s_e[q*33 + l] = p / s;
    }
    __syncthreads();
    {
        int qr = t >> 3, mg = t & 7;
        float acc[24];
        #pragma unroll
        for (int i = 0; i < 24; i++) acc[i] = 0.f;
        for (int k = 0; k < 32; k++){
            float a = s_e[qr*33 + k];
            #pragma unroll
            for (int i = 0; i < 24; i++)
                acc[i] = fmaf(a, s_vp[k*193 + mg + 8*i], acc[i]);
        }
        __half* ch = reinterpret_cast<__half*>(g_ctxh) + (ull)(bp*256 + q0 + qr)*192;
        #pragma unroll
        for (int i = 0; i < 24; i++)
            ch[mg + 8*i] = __float2half_rn(acc[i]);
    }
}

// ---- outproj: C[192,64] = out_w @ ctx^T, + bias + residual + LN + transpose ----
__global__ void __launch_bounds__(384) outproj_kernel(const float* __restrict__ outb,
                                                      const float* __restrict__ lnow,
                                                      const float* __restrict__ lnob,
                                                      float* __restrict__ out){
    extern __shared__ unsigned smo[];
    float* se = reinterpret_cast<float*>(smo);
    float* red = se + 13056;
    int bp = blockIdx.x, q0b = blockIdx.y * 64;
    int t = threadIdx.x;
    int warp = t >> 5, lane = t & 31;
    int g = lane >> 2, tig = lane & 3;
    int m0 = (warp >> 1) * 32;
    int n0 = (warp & 1) * 32;
    float c[2][4][4];
    #pragma unroll
    for (int mt = 0; mt < 2; mt++)
        #pragma unroll
        for (int nt = 0; nt < 4; nt++)
            #pragma unroll
            for (int q = 0; q < 4; q++) c[mt][nt][q] = 0.f;
    const unsigned* ctxw = g_ctxh + (ull)(bp*256 + q0b)*96;

    auto stage = [&](int kp0, int buf){
        unsigned* dW = smo + buf*2304;
        unsigned* dX = smo + 6912 + buf*768;
        {
            int co = t >> 1, ps = (t & 1) * 4;
            cp16(&dW[co*12 + ps], &g_owh[co*96 + kp0 + ps]);
        }
        if (t < 128){
            int q = t >> 1, ps = (t & 1) * 4;
            cp16(&dX[q*12 + ps], &ctxw[q*96 + kp0 + ps]);
        }
        asm volatile("cp.async.commit_group;" ::);
    };

    stage(0, 0);
    stage(8, 1);
    for (int it = 0; it < 12; it++){
        if (it + 2 < 12) stage((it+2)*8, (it+2) % 3);
        if (it <= 9)       asm volatile("cp.async.wait_group 2;" ::);
        else if (it == 10) asm volatile("cp.async.wait_group 1;" ::);
        else               asm volatile("cp.async.wait_group 0;" ::);
        __syncthreads();
        const unsigned* dW = smo + (it % 3)*2304;
        const unsigned* dX = smo + 6912 + (it % 3)*768;
        unsigned a[2][4], bb[4][2];
        #pragma unroll
        for (int mt = 0; mt < 2; mt++){
            int m = m0 + mt*16;
            a[mt][0] = dW[(m+g)*12 + tig];
            a[mt][1] = dW[(m+g+8)*12 + tig];
            a[mt][2] = dW[(m+g)*12 + 4 + tig];
            a[mt][3] = dW[(m+g+8)*12 + 4 + tig];
        }
        #pragma unroll
        for (int nt = 0; nt < 4; nt++){
            int n = n0 + nt*8;
            bb[nt][0] = dX[(n+g)*12 + tig];
            bb[nt][1] = dX[(n+g)*12 + 4 + tig];
        }
        #pragma unroll
        for (int mt = 0; mt < 2; mt++)
            #pragma unroll
            for (int nt = 0; nt < 4; nt++)
                asm volatile(
                    "mma.sync.aligned.m16n8k16.row.col.f32.f16.f16.f32 "
                    "{%0,%1,%2,%3}, {%4,%5,%6,%7}, {%8,%9}, {%0,%1,%2,%3};"
                    : "+f"(c[mt][nt][0]), "+f"(c[mt][nt][1]),
                      "+f"(c[mt][nt][2]), "+f"(c[mt][nt][3])
                    : "r"(a[mt][0]), "r"(a[mt][1]), "r"(a[mt][2]), "r"(a[mt][3]),
                      "r"(bb[nt][0]), "r"(bb[nt][1]));
        __syncthreads();
    }
    #pragma unroll
    for (int mt = 0; mt < 2; mt++){
        int coA = m0 + mt*16 + g;
        int coB = coA + 8;
        #pragma unroll
        for (int nt = 0; nt < 4; nt++){
            int px = n0 + nt*8 + 2*tig;
            se[coA*68 + px]     = c[mt][nt][0];
            se[coA*68 + px + 1] = c[mt][nt][1];
            se[coB*68 + px]     = c[mt][nt][2];
            se[coB*68 + px + 1] = c[mt][nt][3];
        }
    }
    __syncthreads();
    int seg = t >> 6, tq = t & 63;
    float val[32];
    float s = 0.f, ss = 0.f;
    const float* qn = g_qnT + bp*49152 + q0b + tq;
    #pragma unroll
    for (int i = 0; i < 32; i++){
        int n = seg*32 + i;
        float v = se[n*68 + tq] + outb[n] + qn[n*256];
        val[i] = v;
        s += v; ss += v*v;
    }
    red[seg*64 + tq] = s;
    red[384 + seg*64 + tq] = ss;
    __syncthreads();
    if (t < 64){
        float st = 0.f, sst = 0.f;
        #pragma unroll
        for (int k = 0; k < 6; k++){ st += red[k*64 + t]; sst += red[384 + k*64 + t]; }
        float mu = st * (1.f/192.f);
        float var = sst * (1.f/192.f) - mu*mu;
        red[768 + t] = mu;
        red[832 + t] = rsqrtf(var + LN_EPS);
    }
    __syncthreads();
    float mu = red[768 + tq], rs = red[832 + tq];
    float* ob = out + bp*49152 + q0b + tq;
    #pragma unroll
    for (int i = 0; i < 32; i++){
        int n = seg*32 + i;
        ob[n*256] = (val[i] - mu)*rs*lnow[n] + lnob[n];
    }
}

extern "C" void kernel_launch(void* const* d_in, const int* in_sizes, int n_in,
                              void* d_out, int out_size){
    const float* x_p    = (const float*)d_in[0];
    const float* y_g    = (const float*)d_in[1];
    const float* conv1w = (const float*)d_in[2];
    const float* conv1b = (const float*)d_in[3];
    const float* gamma1 = (const float*)d_in[4];
    const float* beta1  = (const float*)d_in[5];
    const float* conv2w = (const float*)d_in[6];
    const float* conv2b = (const float*)d_in[7];
    const float* gamma2 = (const float*)d_in[8];
    const float* beta2  = (const float*)d_in[9];
    const float* conv3w = (const float*)d_in[10];
    const float* conv3b = (const float*)d_in[11];
    const float* lnqw   = (const float*)d_in[12];
    const float* lnqb   = (const float*)d_in[13];
    const float* lnkw   = (const float*)d_in[14];
    const float* lnkb   = (const float*)d_in[15];
    const float* lnow   = (const float*)d_in[16];
    const float* lnob   = (const float*)d_in[17];
    const float* Wq     = (const float*)d_in[18];
    const float* Wk     = (const float*)d_in[19];
    const float* vw     = (const float*)d_in[20];
    const float* Wv     = (const float*)d_in[21];
    const float* outw   = (const float*)d_in[22];
    const float* outb   = (const float*)d_in[23];
    float* out = (float*)d_out;

    cudaFuncSetAttribute(attn_kernel, cudaFuncAttributeMaxDynamicSharedMemorySize, 62720);
    cudaFuncSetAttribute(conv2gemm_kernel, cudaFuncAttributeMaxDynamicSharedMemorySize, 44544);
    cudaFuncSetAttribute(conv3gemm_kernel, cudaFuncAttributeMaxDynamicSharedMemorySize, 59904);
    cudaFuncSetAttribute(qproj_kernel, cudaFuncAttributeMaxDynamicSharedMemorySize, 44544);
    cudaFuncSetAttribute(outproj_kernel, cudaFuncAttributeMaxDynamicSharedMemorySize, 55808);

    conv1_kernel<<<dim3(64,4,2), 256>>>(x_p, conv1w, conv1b, gamma1, gamma2);     // 0
    gdn_kernel<<<1024, 256>>>(1, beta1, conv2w, conv3w, outw, Wq);                 // 1
    im2col2_kernel<<<dim3(800,64), 256>>>();                                       // 2
    conv2gemm_kernel<<<dim3(64,4), 256, 44544>>>(conv2b);                          // 3 (profiled)
    gdn_kernel<<<256, 256>>>(2, beta2, nullptr, nullptr, nullptr, nullptr);        // 4
    im2col3_kernel<<<dim3(288,64), 256>>>();                                       // 5
    conv3gemm_kernel<<<dim3(64,4), 384, 59904>>>(conv3b);                          // 6
    qn_kernel<<<dim3(64,8), 256>>>(lnqw, lnqb);                                    // 7
    qproj_kernel<<<dim3(64,4), 256, 44544>>>();                                    // 8
    kv_kernel<<<dim3(64,5), 256>>>(y_g, lnkw, lnkb, Wk, Wv);                       // 9
    attn_kernel<<<512, 256, 62720>>>(vw);                                          // 10
    outproj_kernel<<<dim3(64,4), 384, 55808>>>(outb, lnow, lnob, out);             // 11
}

// round 16
// speedup vs baseline: 3.6127x; 1.0449x over previous
#include <cuda_runtime.h>
#include <cuda_fp16.h>

#define LN_EPS 1e-5f
typedef unsigned long long ull;

// ---- scratch ----
__device__ float g_s1[64*128*1024];
__device__ float g_s2[64*128*256];
__device__ float g_y3[64*192*256];
__device__ float g_kp[64*32*128];
__device__ float g_vp[64*32*192];
__device__ float g_gT2[16384];              // gamma2 transposed (stage-2 FFMA gdn)
__device__ unsigned g_g1h[128*64];          // gamma1 half2 [d][cp]
__device__ unsigned g_xsqh[64*64*1024];     // x^2 half2 [bp][cp][px]
__device__ float g_rn[64*128*1024];         // rsqrt(norm) [bp][c][px]
__device__ unsigned g_xcolh[64*1600*256];
__device__ unsigned g_x3colh[64*576*256];
__device__ unsigned g_w2h[128*1600];
__device__ unsigned g_w3h[192*576];
__device__ unsigned g_owh[192*96];
__device__ unsigned g_wqh[128*96];
__device__ unsigned g_qnh[64*96*256];
__device__ float g_qp[64*128*256];
__device__ unsigned g_ctxh[64*256*96];
__device__ float g_qnT[64*192*256];

__device__ __forceinline__ float tanh_fast(float x){
    float y; asm("tanh.approx.f32 %0, %1;" : "=f"(y) : "f"(x)); return y;
}
__device__ __forceinline__ unsigned packh(float v0, float v1){
    __half h0 = __float2half_rn(v0), h1 = __float2half_rn(v1);
    return (unsigned)__half_as_ushort(h0) | ((unsigned)__half_as_ushort(h1) << 16);
}
__device__ __forceinline__ void cp16(unsigned* sp, const unsigned* gp){
    unsigned sa = (unsigned)__cvta_generic_to_shared(sp);
    asm volatile("cp.async.cg.shared.global [%0], [%1], 16;" :: "r"(sa), "l"(gp));
}

// ---- conv1 + all weight packs + xsq epilogue. grid (64,4,2), 256 thr ----
__global__ void conv1_kernel(const float* __restrict__ x, const float* __restrict__ w,
                             const float* __restrict__ b, const float* __restrict__ g1,
                             const float* __restrict__ g2, const float* __restrict__ w2,
                             const float* __restrict__ w3, const float* __restrict__ ow,
                             const float* __restrict__ wq){
    __shared__ float sw[4800];
    __shared__ float sin_[3885];
    int bp = blockIdx.x, tile = blockIdx.y, z = blockIdx.z;
    int t = threadIdx.x;
    if (z == 0){
        int blk = bp*4 + tile;   // 0..255
        for (int i = t; i < 64; i += 256){
            int e = blk*64 + i;  // gamma2 transpose, 16384
            g_gT2[(e & 127)*128 + (e >> 7)] = g2[e];
        }
        for (int i = t; i < 32; i += 256){
            int e = blk*32 + i;  // gamma1 half2, 8192
            int d = e >> 6, cp = e & 63;
            g_g1h[e] = packh(g1[d*128 + 2*cp], g1[d*128 + 2*cp + 1]);
        }
        for (int i = t; i < 800; i += 256){
            int e = blk*800 + i;
            g_w2h[e] = packh(w2[2*e], w2[2*e+1]);
        }
        for (int i = t; i < 432; i += 256){
            int e = blk*432 + i;
            g_w3h[e] = packh(w3[2*e], w3[2*e+1]);
        }
        for (int i = t; i < 72; i += 256){
            int e = blk*72 + i;
            g_owh[e] = packh(ow[2*e], ow[2*e+1]);
        }
        for (int i = t; i < 48; i += 256){
            int e = blk*48 + i;
            g_wqh[e] = packh(wq[2*e], wq[2*e+1]);
        }
    }
    for (int e = t; e < 4800; e += 256) sw[e] = w[z*4800 + e];
    int ty0 = (tile>>1)*16, tx0 = (tile&1)*16;
    int iy0 = 2*ty0 - 2, ix0 = 2*tx0 - 2;
    const float* xb = x + bp*12288;
    for (int e = t; e < 3675; e += 256){
        int c = e/1225, rem = e - c*1225, r = rem/35, col = rem - r*35;
        int gy = iy0 + r, gx = ix0 + col;
        float v = 0.f;
        if (gy>=0 && gy<64 && gx>=0 && gx<64) v = xb[c*4096 + gy*64 + gx];
        sin_[(c*35 + r)*37 + col] = v;
    }
    __syncthreads();
    int px4 = t & 63, cog = t >> 6;
    int ly = px4 >> 2, lx0 = (px4 & 3)*4;
    float* ob = g_s1 + bp*131072;
    unsigned* xsq = g_xsqh + bp*65536;
    int pxb = (ty0+ly)*32 + tx0 + lx0;
    for (int p = 0; p < 2; p++){
        int col0 = cog*16 + p*8;
        float acc[8][4];
        #pragma unroll
        for (int i = 0; i < 8; i++){
            float bb = b[z*64 + col0 + i];
            #pragma unroll
            for (int j = 0; j < 4; j++) acc[i][j] = bb;
        }
        #pragma unroll 1
        for (int c = 0; c < 3; c++){
            #pragma unroll
            for (int ky = 0; ky < 5; ky++){
                #pragma unroll
                for (int kx = 0; kx < 5; kx++){
                    float xv[4];
                    #pragma unroll
                    for (int j = 0; j < 4; j++)
                        xv[j] = sin_[(c*35 + 2*ly + ky)*37 + 2*lx0 + 2*j + kx];
                    #pragma unroll
                    for (int i = 0; i < 8; i++){
                        float wv = sw[(col0+i)*75 + c*25 + ky*5 + kx];
                        #pragma unroll
                        for (int j = 0; j < 4; j++) acc[i][j] = fmaf(wv, xv[j], acc[i][j]);
                    }
                }
            }
        }
        #pragma unroll
        for (int i = 0; i < 8; i++){
            float4 o = make_float4(acc[i][0], acc[i][1], acc[i][2], acc[i][3]);
            *reinterpret_cast<float4*>(ob + (z*64+col0+i)*1024 + pxb) = o;
        }
        #pragma unroll
        for (int i = 0; i < 4; i++){
            int cp = z*32 + (col0 >> 1) + i;
            #pragma unroll
            for (int j = 0; j < 4; j++){
                float a0 = acc[2*i][j], a1 = acc[2*i+1][j];
                xsq[cp*1024 + pxb + j] = packh(a0*a0, a1*a1);
            }
        }
    }
}

// ---- gdnGemm: rn = rsqrt(gamma1 @ xsq + beta1). grid (64,16), 256 thr, 44544 B ----
__global__ void __launch_bounds__(256) gdngemm_kernel(const float* __restrict__ beta){
    extern __shared__ unsigned smg[];
    int bp = blockIdx.x, n0b = blockIdx.y * 64;
    int t = threadIdx.x;
    int warp = t >> 5, lane = t & 31;
    int g = lane >> 2, tig = lane & 3;
    int m0 = (warp >> 1) * 32;
    int n0 = (warp & 1) * 32;
    float c[2][4][4];
    #pragma unroll
    for (int mt = 0; mt < 2; mt++)
        #pragma unroll
        for (int nt = 0; nt < 4; nt++)
            #pragma unroll
            for (int q = 0; q < 4; q++) c[mt][nt][q] = 0.f;
    const unsigned* xsb = g_xsqh + bp*65536 + n0b;

    auto stage = [&](int kp0, int buf){
        unsigned* dW = smg + buf*2560;
        unsigned* dX = smg + 7680 + buf*1152;
        #pragma unroll
        for (int s = 0; s < 2; s++){
            int e = t + s*256;
            int co = e >> 2, kq = (e & 3) * 4;
            cp16(&dW[co*20 + kq], &g_g1h[co*64 + kp0 + kq]);
        }
        {
            int kk = t >> 4, ps = (t & 15) * 4;
            cp16(&dX[kk*72 + ps], &xsb[(kp0 + kk)*1024 + ps]);
        }
        asm volatile("cp.async.commit_group;" ::);
    };

    stage(0, 0);
    stage(16, 1);
    for (int it = 0; it < 4; it++){
        if (it + 2 < 4) stage((it+2)*16, (it+2) % 3);
        if (it <= 1)      asm volatile("cp.async.wait_group 2;" ::);
        else if (it == 2) asm volatile("cp.async.wait_group 1;" ::);
        else              asm volatile("cp.async.wait_group 0;" ::);
        __syncthreads();
        const unsigned* dW = smg + (it % 3)*2560;
        const unsigned* dX = smg + 7680 + (it % 3)*1152;
        #pragma unroll
        for (int ks = 0; ks < 2; ks++){
            int kb = ks*8;
            unsigned a[2][4], bb[4][2];
            #pragma unroll
            for (int mt = 0; mt < 2; mt++){
                int m = m0 + mt*16;
                a[mt][0] = dW[(m+g)*20 + kb + tig];
                a[mt][1] = dW[(m+g+8)*20 + kb + tig];
                a[mt][2] = dW[(m+g)*20 + kb + 4 + tig];
                a[mt][3] = dW[(m+g+8)*20 + kb + 4 + tig];
            }
            #pragma unroll
            for (int nt = 0; nt < 4; nt++){
                int n = n0 + nt*8;
                bb[nt][0] = dX[(kb+tig)*72 + n + g];
                bb[nt][1] = dX[(kb+tig+4)*72 + n + g];
            }
            #pragma unroll
            for (int mt = 0; mt < 2; mt++)
                #pragma unroll
                for (int nt = 0; nt < 4; nt++)
                    asm volatile(
                        "mma.sync.aligned.m16n8k16.row.col.f32.f16.f16.f32 "
                        "{%0,%1,%2,%3}, {%4,%5,%6,%7}, {%8,%9}, {%0,%1,%2,%3};"
                        : "+f"(c[mt][nt][0]), "+f"(c[mt][nt][1]),
                          "+f"(c[mt][nt][2]), "+f"(c[mt][nt][3])
                        : "r"(a[mt][0]), "r"(a[mt][1]), "r"(a[mt][2]), "r"(a[mt][3]),
                          "r"(bb[nt][0]), "r"(bb[nt][1]));
        }
        __syncthreads();
    }
    float* rb = g_rn + bp*131072;
    #pragma unroll
    for (int mt = 0; mt < 2; mt++){
        int coA = m0 + mt*16 + g;
        int coB = coA + 8;
        float bA = beta[coA], bB = beta[coB];
        #pragma unroll
        for (int nt = 0; nt < 4; nt++){
            int px = n0b + n0 + nt*8 + 2*tig;
            *reinterpret_cast<float2*>(rb + coA*1024 + px) =
                make_float2(rsqrtf(c[mt][nt][0] + bA), rsqrtf(c[mt][nt][1] + bA));
            *reinterpret_cast<float2*>(rb + coB*1024 + px) =
                make_float2(rsqrtf(c[mt][nt][2] + bB), rsqrtf(c[mt][nt][3] + bB));
        }
    }
}

// ---- conv2 im2col (gdn scale fused): grid (800,64), 256 thr ----
__global__ void im2col2_kernel(){
    int bp = blockIdx.y;
    int t = threadIdx.x;
    int oy = t >> 4, ox = t & 15;
    const float* xb = g_s1 + bp*131072;
    const float* rnb = g_rn + bp*131072;
    unsigned* xc = g_xcolh + bp*409600;
    int base = blockIdx.x*4;
    #pragma unroll
    for (int kpi = 0; kpi < 2; kpi++){
        float v[2];
        #pragma unroll
        for (int h = 0; h < 2; h++){
            int k = base + kpi*2 + h;
            int ci = k / 25, r = k - ci*25;
            int ky = r / 5, kx = r - ky*5;
            int iy = 2*oy - 2 + ky, ix = 2*ox - 2 + kx;
            float vv = 0.f;
            if (iy>=0 && iy<32 && ix>=0 && ix<32){
                int idx = ci*1024 + iy*32 + ix;
                vv = xb[idx] * rnb[idx];
            }
            v[h] = vv;
        }
        xc[((base >> 1) + kpi)*256 + t] = packh(v[0], v[1]);
    }
}

// ---- conv3 im2col: grid (288,64), 256 thr ----
__global__ void im2col3_kernel(){
    int bp = blockIdx.y;
    int t = threadIdx.x;
    int oy = t >> 4, ox = t & 15;
    const float* xb = g_s2 + bp*32768;
    unsigned* xc = g_x3colh + bp*147456;
    int base = blockIdx.x*4;
    #pragma unroll
    for (int kpi = 0; kpi < 2; kpi++){
        float v[2];
        #pragma unroll
        for (int h = 0; h < 2; h++){
            int k = base + kpi*2 + h;
            int ci = k / 9, r = k - ci*9;
            int ky = r / 3, kx = r - ky*3;
            int iy = oy - 1 + ky, ix = ox - 1 + kx;
            float vv = 0.f;
            if (iy>=0 && iy<16 && ix>=0 && ix<16) vv = xb[ci*256 + iy*16 + ix];
            v[h] = vv;
        }
        xc[((base >> 1) + kpi)*256 + t] = packh(v[0], v[1]);
    }
}

// ---- conv2 GEMM fp16. grid (64,4), 256 thr, 44544 B ----
__global__ void __launch_bounds__(256) conv2gemm_kernel(const float* __restrict__ bias){
    extern __shared__ unsigned smu[];
    int bp = blockIdx.x, n0b = blockIdx.y * 64;
    int t = threadIdx.x;
    int warp = t >> 5, lane = t & 31;
    int g = lane >> 2, tig = lane & 3;
    int m0 = (warp >> 1) * 32;
    int n0 = (warp & 1) * 32;
    float c[2][4][4];
    #pragma unroll
    for (int mt = 0; mt < 2; mt++)
        #pragma unroll
        for (int nt = 0; nt < 4; nt++)
            #pragma unroll
            for (int q = 0; q < 4; q++) c[mt][nt][q] = 0.f;
    const unsigned* xcb = g_xcolh + bp*409600 + n0b;

    auto stage = [&](int kp0, int buf){
        unsigned* dW = smu + buf*2560;
        unsigned* dX = smu + 7680 + buf*1152;
        #pragma unroll
        for (int s = 0; s < 2; s++){
            int e = t + s*256;
            int co = e >> 2, kq = (e & 3) * 4;
            cp16(&dW[co*20 + kq], &g_w2h[co*1600 + kp0 + kq]);
        }
        {
            int kk = t >> 4, ps = (t & 15) * 4;
            cp16(&dX[kk*72 + ps], &xcb[(kp0 + kk)*256 + ps]);
        }
        asm volatile("cp.async.commit_group;" ::);
    };

    stage(0, 0);
    stage(16, 1);
    for (int it = 0; it < 100; it++){
        if (it + 2 < 100) stage((it+2)*16, (it+2) % 3);
        if (it <= 97)      asm volatile("cp.async.wait_group 2;" ::);
        else if (it == 98) asm volatile("cp.async.wait_group 1;" ::);
        else               asm volatile("cp.async.wait_group 0;" ::);
        __syncthreads();
        const unsigned* dW = smu + (it % 3)*2560;
        const unsigned* dX = smu + 7680 + (it % 3)*1152;
        #pragma unroll
        for (int ks = 0; ks < 2; ks++){
            int kb = ks*8;
            unsigned a[2][4], bb[4][2];
            #pragma unroll
            for (int mt = 0; mt < 2; mt++){
                int m = m0 + mt*16;
                a[mt][0] = dW[(m+g)*20 + kb + tig];
                a[mt][1] = dW[(m+g+8)*20 + kb + tig];
                a[mt][2] = dW[(m+g)*20 + kb + 4 + tig];
                a[mt][3] = dW[(m+g+8)*20 + kb + 4 + tig];
            }
            #pragma unroll
            for (int nt = 0; nt < 4; nt++){
                int n = n0 + nt*8;
                bb[nt][0] = dX[(kb+tig)*72 + n + g];
                bb[nt][1] = dX[(kb+tig+4)*72 + n + g];
            }
            #pragma unroll
            for (int mt = 0; mt < 2; mt++)
                #pragma unroll
                for (int nt = 0; nt < 4; nt++)
                    asm volatile(
                        "mma.sync.aligned.m16n8k16.row.col.f32.f16.f16.f32 "
                        "{%0,%1,%2,%3}, {%4,%5,%6,%7}, {%8,%9}, {%0,%1,%2,%3};"
                        : "+f"(c[mt][nt][0]), "+f"(c[mt][nt][1]),
                          "+f"(c[mt][nt][2]), "+f"(c[mt][nt][3])
                        : "r"(a[mt][0]), "r"(a[mt][1]), "r"(a[mt][2]), "r"(a[mt][3]),
                          "r"(bb[nt][0]), "r"(bb[nt][1]));
        }
        __syncthreads();
    }
    float* ob = g_s2 + bp*32768;
    #pragma unroll
    for (int mt = 0; mt < 2; mt++){
        int coA = m0 + mt*16 + g;
        int coB = coA + 8;
        float bA = bias[coA], bB = bias[coB];
        #pragma unroll
        for (int nt = 0; nt < 4; nt++){
            int px = n0b + n0 + nt*8 + 2*tig;
            *reinterpret_cast<float2*>(ob + coA*256 + px) =
                make_float2(c[mt][nt][0] + bA, c[mt][nt][1] + bA);
            *reinterpret_cast<float2*>(ob + coB*256 + px) =
                make_float2(c[mt][nt][2] + bB, c[mt][nt][3] + bB);
        }
    }
}

// ---- gdn stage 2 (FFMA, in-place on g_s2). grid 256, 256 thr ----
__global__ void gdn2_kernel(const float* __restrict__ beta){
    __shared__ float sA[2048];
    __shared__ float sB[1088];
    int bp = blockIdx.x >> 2;
    int p0 = (blockIdx.x & 3) * 64;
    int t = threadIdx.x;
    int i = t >> 4, j = t & 15;
    float* xb = g_s2 + bp*32768;
    float acc[8][4];
    #pragma unroll
    for (int ii = 0; ii < 8; ii++){
        float bb = beta[i*8 + ii];
        #pragma unroll
        for (int jj = 0; jj < 4; jj++) acc[ii][jj] = bb;
    }
    for (int c0 = 0; c0 < 128; c0 += 16){
        __syncthreads();
        for (int e = t; e < 2048; e += 256) sA[e] = g_gT2[c0*128 + e];
        for (int e = t; e < 1024; e += 256){
            int cc = e >> 6, p = e & 63;
            float v = xb[(c0+cc)*256 + p0 + p];
            sB[cc*68 + p] = v*v;
        }
        __syncthreads();
        #pragma unroll
        for (int cc = 0; cc < 16; cc++){
            float x0 = sB[cc*68 + j*4], x1 = sB[cc*68 + j*4 + 1];
            float x2 = sB[cc*68 + j*4 + 2], x3 = sB[cc*68 + j*4 + 3];
            float4 ga = *reinterpret_cast<const float4*>(sA + cc*128 + i*8);
            float4 gb = *reinterpret_cast<const float4*>(sA + cc*128 + i*8 + 4);
            float gs[8] = {ga.x,ga.y,ga.z,ga.w,gb.x,gb.y,gb.z,gb.w};
            #pragma unroll
            for (int ii = 0; ii < 8; ii++){
                acc[ii][0] = fmaf(gs[ii], x0, acc[ii][0]);
                acc[ii][1] = fmaf(gs[ii], x1, acc[ii][1]);
                acc[ii][2] = fmaf(gs[ii], x2, acc[ii][2]);
                acc[ii][3] = fmaf(gs[ii], x3, acc[ii][3]);
            }
        }
    }
    #pragma unroll
    for (int ii = 0; ii < 8; ii++){
        int d = i*8 + ii;
        float4 xv = *reinterpret_cast<const float4*>(xb + d*256 + p0 + j*4);
        float4 o;
        o.x = xv.x * rsqrtf(acc[ii][0]);
        o.y = xv.y * rsqrtf(acc[ii][1]);
        o.z = xv.z * rsqrtf(acc[ii][2]);
        o.w = xv.w * rsqrtf(acc[ii][3]);
        *reinterpret_cast<float4*>(xb + d*256 + p0 + j*4) = o;
    }
}

// ---- conv3 GEMM fp16. grid (64,4), 384 thr, 59904 B ----
__global__ void __launch_bounds__(384) conv3gemm_kernel(const float* __restrict__ bias){
    extern __shared__ unsigned smu3[];
    int bp = blockIdx.x, n0b = blockIdx.y * 64;
    int t = threadIdx.x;
    int warp = t >> 5, lane = t & 31;
    int g = lane >> 2, tig = lane & 3;
    int m0 = (warp >> 1) * 32;
    int n0 = (warp & 1) * 32;
    float c[2][4][4];
    #pragma unroll
    for (int mt = 0; mt < 2; mt++)
        #pragma unroll
        for (int nt = 0; nt < 4; nt++)
            #pragma unroll
            for (int q = 0; q < 4; q++) c[mt][nt][q] = 0.f;
    const unsigned* xcb = g_x3colh + bp*147456 + n0b;

    auto stage = [&](int kp0, int buf){
        unsigned* dW = smu3 + buf*3840;
        unsigned* dX = smu3 + 11520 + buf*1152;
        #pragma unroll
        for (int s = 0; s < 2; s++){
            int e = t + s*384;
            int co = e >> 2, kq = (e & 3) * 4;
            cp16(&dW[co*20 + kq], &g_w3h[co*576 + kp0 + kq]);
        }
        if (t < 256){
            int kk = t >> 4, ps = (t & 15) * 4;
            cp16(&dX[kk*72 + ps], &xcb[(kp0 + kk)*256 + ps]);
        }
        asm volatile("cp.async.commit_group;" ::);
    };

    stage(0, 0);
    stage(16, 1);
    for (int it = 0; it < 36; it++){
        if (it + 2 < 36) stage((it+2)*16, (it+2) % 3);
        if (it <= 33)      asm volatile("cp.async.wait_group 2;" ::);
        else if (it == 34) asm volatile("cp.async.wait_group 1;" ::);
        else               asm volatile("cp.async.wait_group 0;" ::);
        __syncthreads();
        const unsigned* dW = smu3 + (it % 3)*3840;
        const unsigned* dX = smu3 + 11520 + (it % 3)*1152;
        #pragma unroll
        for (int ks = 0; ks < 2; ks++){
            int kb = ks*8;
            unsigned a[2][4], bb[4][2];
            #pragma unroll
            for (int mt = 0; mt < 2; mt++){
                int m = m0 + mt*16;
                a[mt][0] = dW[(m+g)*20 + kb + tig];
                a[mt][1] = dW[(m+g+8)*20 + kb + tig];
                a[mt][2] = dW[(m+g)*20 + kb + 4 + tig];
                a[mt][3] = dW[(m+g+8)*20 + kb + 4 + tig];
            }
            #pragma unroll
            for (int nt = 0; nt < 4; nt++){
                int n = n0 + nt*8;
                bb[nt][0] = dX[(kb+tig)*72 + n + g];
                bb[nt][1] = dX[(kb+tig+4)*72 + n + g];
            }
            #pragma unroll
            for (int mt = 0; mt < 2; mt++)
                #pragma unroll
                for (int nt = 0; nt < 4; nt++)
                    asm volatile(
                        "mma.sync.aligned.m16n8k16.row.col.f32.f16.f16.f32 "
                        "{%0,%1,%2,%3}, {%4,%5,%6,%7}, {%8,%9}, {%0,%1,%2,%3};"
                        : "+f"(c[mt][nt][0]), "+f"(c[mt][nt][1]),
                          "+f"(c[mt][nt][2]), "+f"(c[mt][nt][3])
                        : "r"(a[mt][0]), "r"(a[mt][1]), "r"(a[mt][2]), "r"(a[mt][3]),
                          "r"(bb[nt][0]), "r"(bb[nt][1]));
        }
        __syncthreads();
    }
    float* ob = g_y3 + bp*49152;
    #pragma unroll
    for (int mt = 0; mt < 2; mt++){
        int coA = m0 + mt*16 + g;
        int coB = coA + 8;
        float bA = bias[coA], bB = bias[coB];
        #pragma unroll
        for (int nt = 0; nt < 4; nt++){
            int px = n0b + n0 + nt*8 + 2*tig;
            *reinterpret_cast<float2*>(ob + coA*256 + px) =
                make_float2(c[mt][nt][0] + bA, c[mt][nt][1] + bA);
            *reinterpret_cast<float2*>(ob + coB*256 + px) =
                make_float2(c[mt][nt][2] + bB, c[mt][nt][3] + bB);
        }
    }
}

// ---- qn: LN of y3 -> g_qnT + g_qnh. grid (64,8), 256 thr ----
__global__ void qn_kernel(const float* __restrict__ lnqw, const float* __restrict__ lnqb){
    __shared__ float s[192*33];
    int bp = blockIdx.x, q0 = blockIdx.y << 5;
    int t = threadIdx.x;
    int w = t >> 5, l = t & 31;
    const float* y3 = g_y3 + bp*49152;
    for (int e = t; e < 6144; e += 256){
        int m = e >> 5, qq = e & 31;
        s[m*33 + qq] = y3[m*256 + q0 + qq];
    }
    __syncthreads();
    {
        float lwv[6], lbv[6];
        #pragma unroll
        for (int i = 0; i < 6; i++){ lwv[i] = lnqw[l+32*i]; lbv[i] = lnqb[l+32*i]; }
        for (int qi = 0; qi < 4; qi++){
            int q = w*4 + qi;
            float v[6]; float sum = 0.f;
            #pragma unroll
            for (int i = 0; i < 6; i++){ v[i] = s[(l+32*i)*33 + q]; sum += v[i]; }
            #pragma unroll
            for (int o = 16; o > 0; o >>= 1) sum += __shfl_xor_sync(0xffffffffu, sum, o);
            float mu = sum * (1.f/192.f);
            float vs = 0.f;
            #pragma unroll
            for (int i = 0; i < 6; i++){ float d = v[i]-mu; vs += d*d; }
            #pragma unroll
            for (int o = 16; o > 0; o >>= 1) vs += __shfl_xor_sync(0xffffffffu, vs, o);
            float rs = rsqrtf(vs * (1.f/192.f) + LN_EPS);
            #pragma unroll
            for (int i = 0; i < 6; i++)
                s[(l+32*i)*33 + q] = (v[i]-mu)*rs*lwv[i] + lbv[i];
        }
    }
    __syncthreads();
    float* qt = g_qnT + bp*49152;
    for (int e = t; e < 6144; e += 256){
        int n = e >> 5, qq = e & 31;
        qt[n*256 + q0 + qq] = s[n*33 + qq];
    }
    unsigned* qh = g_qnh + bp*24576;
    for (int e = t; e < 3072; e += 256){
        int mp = e >> 5, qq = e & 31;
        qh[mp*256 + q0 + qq] = packh(s[(2*mp)*33 + qq], s[(2*mp+1)*33 + qq]);
    }
}

// ---- qproj GEMM fp16. grid (64,4), 256 thr, 44544 B ----
__global__ void __launch_bounds__(256) qproj_kernel(){
    extern __shared__ unsigned smq[];
    int bp = blockIdx.x, n0b = blockIdx.y * 64;
    int t = threadIdx.x;
    int warp = t >> 5, lane = t & 31;
    int g = lane >> 2, tig = lane & 3;
    int m0 = (warp >> 1) * 32;
    int n0 = (warp & 1) * 32;
    float c[2][4][4];
    #pragma unroll
    for (int mt = 0; mt < 2; mt++)
        #pragma unroll
        for (int nt = 0; nt < 4; nt++)
            #pragma unroll
            for (int q = 0; q < 4; q++) c[mt][nt][q] = 0.f;
    const unsigned* xcb = g_qnh + bp*24576 + n0b;

    auto stage = [&](int kp0, int buf){
        unsigned* dW = smq + buf*2560;
        unsigned* dX = smq + 7680 + buf*1152;
        #pragma unroll
        for (int s = 0; s < 2; s++){
            int e = t + s*256;
            int co = e >> 2, kq = (e & 3) * 4;
            cp16(&dW[co*20 + kq], &g_wqh[co*96 + kp0 + kq]);
        }
        {
            int kk = t >> 4, ps = (t & 15) * 4;
            cp16(&dX[kk*72 + ps], &xcb[(kp0 + kk)*256 + ps]);
        }
        asm volatile("cp.async.commit_group;" ::);
    };

    stage(0, 0);
    stage(16, 1);
    for (int it = 0; it < 6; it++){
        if (it + 2 < 6) stage((it+2)*16, (it+2) % 3);
        if (it <= 3)      asm volatile("cp.async.wait_group 2;" ::);
        else if (it == 4) asm volatile("cp.async.wait_group 1;" ::);
        else              asm volatile("cp.async.wait_group 0;" ::);
        __syncthreads();
        const unsigned* dW = smq + (it % 3)*2560;
        const unsigned* dX = smq + 7680 + (it % 3)*1152;
        #pragma unroll
        for (int ks = 0; ks < 2; ks++){
            int kb = ks*8;
            unsigned a[2][4], bb[4][2];
            #pragma unroll
            for (int mt = 0; mt < 2; mt++){
                int m = m0 + mt*16;
                a[mt][0] = dW[(m+g)*20 + kb + tig];
                a[mt][1] = dW[(m+g+8)*20 + kb + tig];
                a[mt][2] = dW[(m+g)*20 + kb + 4 + tig];
                a[mt][3] = dW[(m+g+8)*20 + kb + 4 + tig];
            }
            #pragma unroll
            for (int nt = 0; nt < 4; nt++){
                int n = n0 + nt*8;
                bb[nt][0] = dX[(kb+tig)*72 + n + g];
                bb[nt][1] = dX[(kb+tig+4)*72 + n + g];
            }
            #pragma unroll
            for (int mt = 0; mt < 2; mt++)
                #pragma unroll
                for (int nt = 0; nt < 4; nt++)
                    asm volatile(
                        "mma.sync.aligned.m16n8k16.row.col.f32.f16.f16.f32 "
                        "{%0,%1,%2,%3}, {%4,%5,%6,%7}, {%8,%9}, {%0,%1,%2,%3};"
                        : "+f"(c[mt][nt][0]), "+f"(c[mt][nt][1]),
                          "+f"(c[mt][nt][2]), "+f"(c[mt][nt][3])
                        : "r"(a[mt][0]), "r"(a[mt][1]), "r"(a[mt][2]), "r"(a[mt][3]),
                          "r"(bb[nt][0]), "r"(bb[nt][1]));
        }
        __syncthreads();
    }
    float* ob = g_qp + bp*32768;
    #pragma unroll
    for (int mt = 0; mt < 2; mt++){
        int coA = m0 + mt*16 + g;
        int coB = coA + 8;
        #pragma unroll
        for (int nt = 0; nt < 4; nt++){
            int px = n0b + n0 + nt*8 + 2*tig;
            *reinterpret_cast<float2*>(ob + coA*256 + px) =
                make_float2(c[mt][nt][0], c[mt][nt][1]);
            *reinterpret_cast<float2*>(ob + coB*256 + px) =
                make_float2(c[mt][nt][2], c[mt][nt][3]);
        }
    }
}

// ---- kv: LN + k_proj + v_proj. grid (64,5), 256 thr ----
__global__ void kv_kernel(const float* __restrict__ yg, const float* __restrict__ lnw,
                          const float* __restrict__ lnb, const float* __restrict__ Wk,
                          const float* __restrict__ Wv){
    __shared__ float s_kv[32*193];
    __shared__ float s_w[64*33];
    int bp = blockIdx.x;
    int r0 = blockIdx.y * 64;
    int t = threadIdx.x;
    int w = t >> 5, l = t & 31;
    for (int e = t; e < 6144; e += 256){
        int c = e >> 5, k = e & 31;
        s_kv[k*193 + c] = yg[bp*6144 + c*32 + k];
    }
    __syncthreads();
    {
        float lwv[6], lbv[6];
        #pragma unroll
        for (int i = 0; i < 6; i++){ lwv[i] = lnw[l+32*i]; lbv[i] = lnb[l+32*i]; }
        for (int ki = 0; ki < 4; ki++){
            int k = w*4 + ki;
            float v[6]; float s = 0.f;
            #pragma unroll
            for (int i = 0; i < 6; i++){ v[i] = s_kv[k*193 + l + 32*i]; s += v[i]; }
            #pragma unroll
            for (int o = 16; o > 0; o >>= 1) s += __shfl_xor_sync(0xffffffffu, s, o);
            float mu = s * (1.f/192.f);
            float vs = 0.f;
            #pragma unroll
            for (int i = 0; i < 6; i++){ float d = v[i]-mu; vs += d*d; }
            #pragma unroll
            for (int o = 16; o > 0; o >>= 1) vs += __shfl_xor_sync(0xffffffffu, vs, o);
            float rs = rsqrtf(vs * (1.f/192.f) + LN_EPS);
            #pragma unroll
            for (int i = 0; i < 6; i++)
                s_kv[k*193 + l + 32*i] = (v[i]-mu)*rs*lwv[i] + lbv[i];
        }
    }
    int kq = t & 7, rp = t >> 3;
    {
        float acc[2][4];
        #pragma unroll
        for (int i = 0; i < 2; i++)
            #pragma unroll
            for (int kk = 0; kk < 4; kk++) acc[i][kk] = 0.f;
        for (int c0 = 0; c0 < 192; c0 += 32){
            __syncthreads();
            for (int e = t; e < 2048; e += 256){
                int rr = e >> 5, cc = e & 31;
                int row = r0 + rr;
                s_w[rr*33 + cc] = (row < 128) ? Wk[row*192 + c0 + cc]
                                              : Wv[(row-128)*192 + c0 + cc];
            }
            __syncthreads();
            for (int cc = 0; cc < 32; cc++){
                float wv0 = s_w[(rp*2)*33 + cc], wv1 = s_w[(rp*2+1)*33 + cc];
                #pragma unroll
                for (int kk = 0; kk < 4; kk++){
                    float kvv = s_kv[(kq*4+kk)*193 + c0 + cc];
                    acc[0][kk] = fmaf(wv0, kvv, acc[0][kk]);
                    acc[1][kk] = fmaf(wv1, kvv, acc[1][kk]);
                }
            }
        }
        #pragma unroll
        for (int i = 0; i < 2; i++){
            int row = r0 + rp*2 + i;
            #pragma unroll
            for (int kk = 0; kk < 4; kk++){
                int k = kq*4 + kk;
                if (row < 128) g_kp[bp*4096 + k*128 + row] = acc[i][kk];
                else           g_vp[bp*6144 + k*192 + (row-128)] = acc[i][kk];
            }
        }
    }
}

// ---- attention core: energy+softmax+context. grid 512, 256 thr, 62720 B ----
__global__ void attn_kernel(const float* __restrict__ vw){
    extern __shared__ float sm[];
    float* s_kp = sm;
    float* s_vp = sm + 4224;
    float* s_e  = sm + 10400;
    float* s_qp = sm + 11456;
    int bp = blockIdx.x >> 3;
    int q0 = (blockIdx.x & 7) << 5;
    int t = threadIdx.x;
    int w = t >> 5, l = t & 31;
    for (int e = t; e < 4096; e += 256){
        int k = e >> 7;
        s_kp[k*132 + (e & 127)] = g_kp[bp*4096 + e];
    }
    for (int e = t; e < 6144; e += 256){
        int k = e / 192, m = e - k*192;
        s_vp[k*193 + m] = g_vp[bp*6144 + e];
    }
    {
        const float* qpb = g_qp + bp*32768;
        for (int e = t; e < 4096; e += 256){
            int d = e >> 5, qq = e & 31;
            s_qp[d*33 + qq] = qpb[d*256 + q0 + qq];
        }
    }
    __syncthreads();
    float vv[4];
    #pragma unroll
    for (int j = 0; j < 4; j++) vv[j] = vw[l + 32*j];
    for (int k = 0; k < 32; k++){
        float kp4[4];
        #pragma unroll
        for (int j = 0; j < 4; j++) kp4[j] = s_kp[k*132 + l + 32*j];
        #pragma unroll
        for (int qi = 0; qi < 4; qi++){
            int q = w*4 + qi;
            float s = 0.f;
            #pragma unroll
            for (int j = 0; j < 4; j++)
                s = fmaf(tanh_fast(s_qp[(l+32*j)*33 + q] + kp4[j]), vv[j], s);
            #pragma unroll
            for (int o = 16; o > 0; o >>= 1) s += __shfl_xor_sync(0xffffffffu, s, o);
            if (l == 0) s_e[q*33 + k] = s;
        }
    }
    __syncwarp();
    for (int qi = 0; qi < 4; qi++){
        int q = w*4 + qi;
        float ev = s_e[q*33 + l];
        float mx = ev;
        #pragma unroll
        for (int o = 16; o > 0; o >>= 1) mx = fmaxf(mx, __shfl_xor_sync(0xffffffffu, mx, o));
        float p = __expf(ev - mx);
        float s = p;
        #pragma unroll
        for (int o = 16; o > 0; o >>= 1) s += __shfl_xor_sync(0xffffffffu, s, o);
        s_e[q*33 + l] = p / s;
    }
    __syncthreads();
    {
        int qr = t >> 3, mg = t & 7;
        float acc[24];
        #pragma unroll
        for (int i = 0; i < 24; i++) acc[i] = 0.f;
        for (int k = 0; k < 32; k++){
            float a = s_e[qr*33 + k];
            #pragma unroll
            for (int i = 0; i < 24; i++)
                acc[i] = fmaf(a, s_vp[k*193 + mg + 8*i], acc[i]);
        }
        __half* ch = reinterpret_cast<__half*>(g_ctxh) + (ull)(bp*256 + q0 + qr)*192;
        #pragma unroll
        for (int i = 0; i < 24; i++)
            ch[mg + 8*i] = __float2half_rn(acc[i]);
    }
}

// ---- outproj: GEMM + bias + residual + LN + transpose. grid (64,4), 384 thr ----
__global__ void __launch_bounds__(384) outproj_kernel(const float* __restrict__ outb,
                                                      const float* __restrict__ lnow,
                                                      const float* __restrict__ lnob,
                                                      float* __restrict__ out){
    extern __shared__ unsigned smo[];
    float* se = reinterpret_cast<float*>(smo);
    float* red = se + 13056;
    int bp = blockIdx.x, q0b = blockIdx.y * 64;
    int t = threadIdx.x;
    int warp = t >> 5, lane = t & 31;
    int g = lane >> 2, tig = lane & 3;
    int m0 = (warp >> 1) * 32;
    int n0 = (warp & 1) * 32;
    float c[2][4][4];
    #pragma unroll
    for (int mt = 0; mt < 2; mt++)
        #pragma unroll
        for (int nt = 0; nt < 4; nt++)
            #pragma unroll
            for (int q = 0; q < 4; q++) c[mt][nt][q] = 0.f;
    const unsigned* ctxw = g_ctxh + (ull)(bp*256 + q0b)*96;

    auto stage = [&](int kp0, int buf){
        unsigned* dW = smo + buf*2304;
        unsigned* dX = smo + 6912 + buf*768;
        {
            int co = t >> 1, ps = (t & 1) * 4;
            cp16(&dW[co*12 + ps], &g_owh[co*96 + kp0 + ps]);
        }
        if (t < 128){
            int q = t >> 1, ps = (t & 1) * 4;
            cp16(&dX[q*12 + ps], &ctxw[q*96 + kp0 + ps]);
        }
        asm volatile("cp.async.commit_group;" ::);
    };

    stage(0, 0);
    stage(8, 1);
    for (int it = 0; it < 12; it++){
        if (it + 2 < 12) stage((it+2)*8, (it+2) % 3);
        if (it <= 9)       asm volatile("cp.async.wait_group 2;" ::);
        else if (it == 10) asm volatile("cp.async.wait_group 1;" ::);
        else               asm volatile("cp.async.wait_group 0;" ::);
        __syncthreads();
        const unsigned* dW = smo + (it % 3)*2304;
        const unsigned* dX = smo + 6912 + (it % 3)*768;
        unsigned a[2][4], bb[4][2];
        #pragma unroll
        for (int mt = 0; mt < 2; mt++){
            int m = m0 + mt*16;
            a[mt][0] = dW[(m+g)*12 + tig];
            a[mt][1] = dW[(m+g+8)*12 + tig];
            a[mt][2] = dW[(m+g)*12 + 4 + tig];
            a[mt][3] = dW[(m+g+8)*12 + 4 + tig];
        }
        #pragma unroll
        for (int nt = 0; nt < 4; nt++){
            int n = n0 + nt*8;
            bb[nt][0] = dX[(n+g)*12 + tig];
            bb[nt][1] = dX[(n+g)*12 + 4 + tig];
        }
        #pragma unroll
        for (int mt = 0; mt < 2; mt++)
            #pragma unroll
            for (int nt = 0; nt < 4; nt++)
                asm volatile(
                    "mma.sync.aligned.m16n8k16.row.col.f32.f16.f16.f32 "
                    "{%0,%1,%2,%3}, {%4,%5,%6,%7}, {%8,%9}, {%0,%1,%2,%3};"
                    : "+f"(c[mt][nt][0]), "+f"(c[mt][nt][1]),
                      "+f"(c[mt][nt][2]), "+f"(c[mt][nt][3])
                    : "r"(a[mt][0]), "r"(a[mt][1]), "r"(a[mt][2]), "r"(a[mt][3]),
                      "r"(bb[nt][0]), "r"(bb[nt][1]));
        __syncthreads();
    }
    #pragma unroll
    for (int mt = 0; mt < 2; mt++){
        int coA = m0 + mt*16 + g;
        int coB = coA + 8;
        #pragma unroll
        for (int nt = 0; nt < 4; nt++){
            int px = n0 + nt*8 + 2*tig;
            se[coA*68 + px]     = c[mt][nt][0];
            se[coA*68 + px + 1] = c[mt][nt][1];
            se[coB*68 + px]     = c[mt][nt][2];
            se[coB*68 + px + 1] = c[mt][nt][3];
        }
    }
    __syncthreads();
    int seg = t >> 6, tq = t & 63;
    float val[32];
    float s = 0.f, ss = 0.f;
    const float* qn = g_qnT + bp*49152 + q0b + tq;
    #pragma unroll
    for (int i = 0; i < 32; i++){
        int n = seg*32 + i;
        float v = se[n*68 + tq] + outb[n] + qn[n*256];
        val[i] = v;
        s += v; ss += v*v;
    }
    red[seg*64 + tq] = s;
    red[384 + seg*64 + tq] = ss;
    __syncthreads();
    if (t < 64){
        float st = 0.f, sst = 0.f;
        #pragma unroll
        for (int k = 0; k < 6; k++){ st += red[k*64 + t]; sst += red[384 + k*64 + t]; }
        float mu = st * (1.f/192.f);
        float var = sst * (1.f/192.f) - mu*mu;
        red[768 + t] = mu;
        red[832 + t] = rsqrtf(var + LN_EPS);
    }
    __syncthreads();
    float mu = red[768 + tq], rs = red[832 + tq];
    float* ob = out + bp*49152 + q0b + tq;
    #pragma unroll
    for (int i = 0; i < 32; i++){
        int n = seg*32 + i;
        ob[n*256] = (val[i] - mu)*rs*lnow[n] + lnob[n];
    }
}

extern "C" void kernel_launch(void* const* d_in, const int* in_sizes, int n_in,
                              void* d_out, int out_size){
    const float* x_p    = (const float*)d_in[0];
    const float* y_g    = (const float*)d_in[1];
    const float* conv1w = (const float*)d_in[2];
    const float* conv1b = (const float*)d_in[3];
    const float* gamma1 = (const float*)d_in[4];
    const float* beta1  = (const float*)d_in[5];
    const float* conv2w = (const float*)d_in[6];
    const float* conv2b = (const float*)d_in[7];
    const float* gamma2 = (const float*)d_in[8];
    const float* beta2  = (const float*)d_in[9];
    const float* conv3w = (const float*)d_in[10];
    const float* conv3b = (const float*)d_in[11];
    const float* lnqw   = (const float*)d_in[12];
    const float* lnqb   = (const float*)d_in[13];
    const float* lnkw   = (const float*)d_in[14];
    const float* lnkb   = (const float*)d_in[15];
    const float* lnow   = (const float*)d_in[16];
    const float* lnob   = (const float*)d_in[17];
    const float* Wq     = (const float*)d_in[18];
    const float* Wk     = (const float*)d_in[19];
    const float* vw     = (const float*)d_in[20];
    const float* Wv     = (const float*)d_in[21];
    const float* outw   = (const float*)d_in[22];
    const float* outb   = (const float*)d_in[23];
    float* out = (float*)d_out;

    cudaFuncSetAttribute(attn_kernel, cudaFuncAttributeMaxDynamicSharedMemorySize, 62720);
    cudaFuncSetAttribute(conv2gemm_kernel, cudaFuncAttributeMaxDynamicSharedMemorySize, 44544);
    cudaFuncSetAttribute(conv3gemm_kernel, cudaFuncAttributeMaxDynamicSharedMemorySize, 59904);
    cudaFuncSetAttribute(gdngemm_kernel, cudaFuncAttributeMaxDynamicSharedMemorySize, 44544);
    cudaFuncSetAttribute(qproj_kernel, cudaFuncAttributeMaxDynamicSharedMemorySize, 44544);
    cudaFuncSetAttribute(outproj_kernel, cudaFuncAttributeMaxDynamicSharedMemorySize, 55808);

    conv1_kernel<<<dim3(64,4,2), 256>>>(x_p, conv1w, conv1b, gamma1, gamma2,
                                        conv2w, conv3w, outw, Wq);                 // 0
    gdngemm_kernel<<<dim3(64,16), 256, 44544>>>(beta1);                            // 1
    im2col2_kernel<<<dim3(800,64), 256>>>();                                       // 2
    conv2gemm_kernel<<<dim3(64,4), 256, 44544>>>(conv2b);                          // 3 (profiled)
    gdn2_kernel<<<256, 256>>>(beta2);                                              // 4
    im2col3_kernel<<<dim3(288,64), 256>>>();                                       // 5
    conv3gemm_kernel<<<dim3(64,4), 384, 59904>>>(conv3b);                          // 6
    qn_kernel<<<dim3(64,8), 256>>>(lnqw, lnqb);                                    // 7
    qproj_kernel<<<dim3(64,4), 256, 44544>>>();                                    // 8
    kv_kernel<<<dim3(64,5), 256>>>(y_g, lnkw, lnkb, Wk, Wv);                       // 9
    attn_kernel<<<512, 256, 62720>>>(vw);                                          // 10
    outproj_kernel<<<dim3(64,4), 384, 55808>>>(outb, lnow, lnob, out);             // 11
}

// round 17
// speedup vs baseline: 3.6644x; 1.0143x over previous
#include <cuda_runtime.h>
#include <cuda_fp16.h>

#define LN_EPS 1e-5f
typedef unsigned long long ull;

// ---- scratch ----
__device__ float g_s1[64*128*1024];
__device__ float g_s2[64*128*256];
__device__ float g_y3[64*192*256];
__device__ float g_kp[64*32*128];
__device__ float g_vp[64*32*192];
__device__ float g_gT2[16384];
__device__ unsigned g_g1h[128*64];
__device__ unsigned g_xsqh[64*64*1024];
__device__ float g_xs[64*128*1024];         // gdn1-scaled x
__device__ unsigned g_xcolh[64*1600*256];
__device__ unsigned g_x3colh[64*576*256];
__device__ unsigned g_w2h[128*1600];
__device__ unsigned g_w3h[192*576];
__device__ unsigned g_owh[192*96];
__device__ unsigned g_wqh[128*96];
__device__ unsigned g_qnh[64*96*256];
__device__ float g_qp[64*128*256];
__device__ unsigned g_ctxh[64*256*96];
__device__ float g_qnT[64*192*256];

__device__ __forceinline__ float tanh_fast(float x){
    float y; asm("tanh.approx.f32 %0, %1;" : "=f"(y) : "f"(x)); return y;
}
__device__ __forceinline__ unsigned packh(float v0, float v1){
    __half h0 = __float2half_rn(v0), h1 = __float2half_rn(v1);
    return (unsigned)__half_as_ushort(h0) | ((unsigned)__half_as_ushort(h1) << 16);
}
__device__ __forceinline__ void cp16(unsigned* sp, const unsigned* gp){
    unsigned sa = (unsigned)__cvta_generic_to_shared(sp);
    asm volatile("cp.async.cg.shared.global [%0], [%1], 16;" :: "r"(sa), "l"(gp));
}

// ---- conv1 + weight packs + xsq epilogue. grid (64,4,2), 256 thr ----
__global__ void conv1_kernel(const float* __restrict__ x, const float* __restrict__ w,
                             const float* __restrict__ b, const float* __restrict__ g1,
                             const float* __restrict__ g2, const float* __restrict__ w2,
                             const float* __restrict__ w3, const float* __restrict__ ow,
                             const float* __restrict__ wq){
    __shared__ float sw[4800];
    __shared__ float sin_[3885];
    int bp = blockIdx.x, tile = blockIdx.y, z = blockIdx.z;
    int t = threadIdx.x;
    if (z == 0){
        int blk = bp*4 + tile;
        for (int i = t; i < 64; i += 256){
            int e = blk*64 + i;
            g_gT2[(e & 127)*128 + (e >> 7)] = g2[e];
        }
        for (int i = t; i < 32; i += 256){
            int e = blk*32 + i;
            int d = e >> 6, cp = e & 63;
            g_g1h[e] = packh(g1[d*128 + 2*cp], g1[d*128 + 2*cp + 1]);
        }
        for (int i = t; i < 800; i += 256){
            int e = blk*800 + i;
            g_w2h[e] = packh(w2[2*e], w2[2*e+1]);
        }
        for (int i = t; i < 432; i += 256){
            int e = blk*432 + i;
            g_w3h[e] = packh(w3[2*e], w3[2*e+1]);
        }
        for (int i = t; i < 72; i += 256){
            int e = blk*72 + i;
            g_owh[e] = packh(ow[2*e], ow[2*e+1]);
        }
        for (int i = t; i < 48; i += 256){
            int e = blk*48 + i;
            g_wqh[e] = packh(wq[2*e], wq[2*e+1]);
        }
    }
    for (int e = t; e < 4800; e += 256) sw[e] = w[z*4800 + e];
    int ty0 = (tile>>1)*16, tx0 = (tile&1)*16;
    int iy0 = 2*ty0 - 2, ix0 = 2*tx0 - 2;
    const float* xb = x + bp*12288;
    for (int e = t; e < 3675; e += 256){
        int c = e/1225, rem = e - c*1225, r = rem/35, col = rem - r*35;
        int gy = iy0 + r, gx = ix0 + col;
        float v = 0.f;
        if (gy>=0 && gy<64 && gx>=0 && gx<64) v = xb[c*4096 + gy*64 + gx];
        sin_[(c*35 + r)*37 + col] = v;
    }
    __syncthreads();
    int px4 = t & 63, cog = t >> 6;
    int ly = px4 >> 2, lx0 = (px4 & 3)*4;
    float* ob = g_s1 + bp*131072;
    unsigned* xsq = g_xsqh + bp*65536;
    int pxb = (ty0+ly)*32 + tx0 + lx0;
    for (int p = 0; p < 2; p++){
        int col0 = cog*16 + p*8;
        float acc[8][4];
        #pragma unroll
        for (int i = 0; i < 8; i++){
            float bb = b[z*64 + col0 + i];
            #pragma unroll
            for (int j = 0; j < 4; j++) acc[i][j] = bb;
        }
        #pragma unroll 1
        for (int c = 0; c < 3; c++){
            #pragma unroll
            for (int ky = 0; ky < 5; ky++){
                #pragma unroll
                for (int kx = 0; kx < 5; kx++){
                    float xv[4];
                    #pragma unroll
                    for (int j = 0; j < 4; j++)
                        xv[j] = sin_[(c*35 + 2*ly + ky)*37 + 2*lx0 + 2*j + kx];
                    #pragma unroll
                    for (int i = 0; i < 8; i++){
                        float wv = sw[(col0+i)*75 + c*25 + ky*5 + kx];
                        #pragma unroll
                        for (int j = 0; j < 4; j++) acc[i][j] = fmaf(wv, xv[j], acc[i][j]);
                    }
                }
            }
        }
        #pragma unroll
        for (int i = 0; i < 8; i++){
            float4 o = make_float4(acc[i][0], acc[i][1], acc[i][2], acc[i][3]);
            *reinterpret_cast<float4*>(ob + (z*64+col0+i)*1024 + pxb) = o;
        }
        #pragma unroll
        for (int i = 0; i < 4; i++){
            int cp = z*32 + (col0 >> 1) + i;
            #pragma unroll
            for (int j = 0; j < 4; j++){
                float a0 = acc[2*i][j], a1 = acc[2*i+1][j];
                xsq[cp*1024 + pxb + j] = packh(a0*a0, a1*a1);
            }
        }
    }
}

// ---- gdnGemm: writes x*rsqrt(gamma1@xsq+beta1). grid (64,16), 256 thr, 44544 B ----
__global__ void __launch_bounds__(256) gdngemm_kernel(const float* __restrict__ beta){
    extern __shared__ unsigned smg[];
    int bp = blockIdx.x, n0b = blockIdx.y * 64;
    int t = threadIdx.x;
    int warp = t >> 5, lane = t & 31;
    int g = lane >> 2, tig = lane & 3;
    int m0 = (warp >> 1) * 32;
    int n0 = (warp & 1) * 32;
    float c[2][4][4];
    #pragma unroll
    for (int mt = 0; mt < 2; mt++)
        #pragma unroll
        for (int nt = 0; nt < 4; nt++)
            #pragma unroll
            for (int q = 0; q < 4; q++) c[mt][nt][q] = 0.f;
    const unsigned* xsb = g_xsqh + bp*65536 + n0b;

    auto stage = [&](int kp0, int buf){
        unsigned* dW = smg + buf*2560;
        unsigned* dX = smg + 7680 + buf*1152;
        #pragma unroll
        for (int s = 0; s < 2; s++){
            int e = t + s*256;
            int co = e >> 2, kq = (e & 3) * 4;
            cp16(&dW[co*20 + kq], &g_g1h[co*64 + kp0 + kq]);
        }
        {
            int kk = t >> 4, ps = (t & 15) * 4;
            cp16(&dX[kk*72 + ps], &xsb[(kp0 + kk)*1024 + ps]);
        }
        asm volatile("cp.async.commit_group;" ::);
    };

    stage(0, 0);
    stage(16, 1);
    for (int it = 0; it < 4; it++){
        if (it + 2 < 4) stage((it+2)*16, (it+2) % 3);
        if (it <= 1)      asm volatile("cp.async.wait_group 2;" ::);
        else if (it == 2) asm volatile("cp.async.wait_group 1;" ::);
        else              asm volatile("cp.async.wait_group 0;" ::);
        __syncthreads();
        const unsigned* dW = smg + (it % 3)*2560;
        const unsigned* dX = smg + 7680 + (it % 3)*1152;
        #pragma unroll
        for (int ks = 0; ks < 2; ks++){
            int kb = ks*8;
            unsigned a[2][4], bb[4][2];
            #pragma unroll
            for (int mt = 0; mt < 2; mt++){
                int m = m0 + mt*16;
                a[mt][0] = dW[(m+g)*20 + kb + tig];
                a[mt][1] = dW[(m+g+8)*20 + kb + tig];
                a[mt][2] = dW[(m+g)*20 + kb + 4 + tig];
                a[mt][3] = dW[(m+g+8)*20 + kb + 4 + tig];
            }
            #pragma unroll
            for (int nt = 0; nt < 4; nt++){
                int n = n0 + nt*8;
                bb[nt][0] = dX[(kb+tig)*72 + n + g];
                bb[nt][1] = dX[(kb+tig+4)*72 + n + g];
            }
            #pragma unroll
            for (int mt = 0; mt < 2; mt++)
                #pragma unroll
                for (int nt = 0; nt < 4; nt++)
                    asm volatile(
                        "mma.sync.aligned.m16n8k16.row.col.f32.f16.f16.f32 "
                        "{%0,%1,%2,%3}, {%4,%5,%6,%7}, {%8,%9}, {%0,%1,%2,%3};"
                        : "+f"(c[mt][nt][0]), "+f"(c[mt][nt][1]),
                          "+f"(c[mt][nt][2]), "+f"(c[mt][nt][3])
                        : "r"(a[mt][0]), "r"(a[mt][1]), "r"(a[mt][2]), "r"(a[mt][3]),
                          "r"(bb[nt][0]), "r"(bb[nt][1]));
        }
        __syncthreads();
    }
    float* xs = g_xs + bp*131072;
    const float* xv = g_s1 + bp*131072;
    #pragma unroll
    for (int mt = 0; mt < 2; mt++){
        int coA = m0 + mt*16 + g;
        int coB = coA + 8;
        float bA = beta[coA], bB = beta[coB];
        #pragma unroll
        for (int nt = 0; nt < 4; nt++){
            int px = n0b + n0 + nt*8 + 2*tig;
            float2 xA = *reinterpret_cast<const float2*>(xv + coA*1024 + px);
            float2 xB = *reinterpret_cast<const float2*>(xv + coB*1024 + px);
            *reinterpret_cast<float2*>(xs + coA*1024 + px) =
                make_float2(xA.x*rsqrtf(c[mt][nt][0] + bA), xA.y*rsqrtf(c[mt][nt][1] + bA));
            *reinterpret_cast<float2*>(xs + coB*1024 + px) =
                make_float2(xB.x*rsqrtf(c[mt][nt][2] + bB), xB.y*rsqrtf(c[mt][nt][3] + bB));
        }
    }
}

// ---- conv2 im2col (reads scaled x): grid (800,64), 256 thr ----
__global__ void im2col2_kernel(){
    int bp = blockIdx.y;
    int t = threadIdx.x;
    int oy = t >> 4, ox = t & 15;
    const float* xb = g_xs + bp*131072;
    unsigned* xc = g_xcolh + bp*409600;
    int base = blockIdx.x*4;
    #pragma unroll
    for (int kpi = 0; kpi < 2; kpi++){
        float v[2];
        #pragma unroll
        for (int h = 0; h < 2; h++){
            int k = base + kpi*2 + h;
            int ci = k / 25, r = k - ci*25;
            int ky = r / 5, kx = r - ky*5;
            int iy = 2*oy - 2 + ky, ix = 2*ox - 2 + kx;
            float vv = 0.f;
            if (iy>=0 && iy<32 && ix>=0 && ix<32) vv = xb[ci*1024 + iy*32 + ix];
            v[h] = vv;
        }
        xc[((base >> 1) + kpi)*256 + t] = packh(v[0], v[1]);
    }
}

// ---- conv3 im2col: grid (288,64), 256 thr ----
__global__ void im2col3_kernel(){
    int bp = blockIdx.y;
    int t = threadIdx.x;
    int oy = t >> 4, ox = t & 15;
    const float* xb = g_s2 + bp*32768;
    unsigned* xc = g_x3colh + bp*147456;
    int base = blockIdx.x*4;
    #pragma unroll
    for (int kpi = 0; kpi < 2; kpi++){
        float v[2];
        #pragma unroll
        for (int h = 0; h < 2; h++){
            int k = base + kpi*2 + h;
            int ci = k / 9, r = k - ci*9;
            int ky = r / 3, kx = r - ky*3;
            int iy = oy - 1 + ky, ix = ox - 1 + kx;
            float vv = 0.f;
            if (iy>=0 && iy<16 && ix>=0 && ix<16) vv = xb[ci*256 + iy*16 + ix];
            v[h] = vv;
        }
        xc[((base >> 1) + kpi)*256 + t] = packh(v[0], v[1]);
    }
}

// ---- conv2 GEMM fp16, 32-kp chunks, 3-stage. grid (64,4), 256 thr, 82944 B ----
__global__ void __launch_bounds__(256) conv2gemm_kernel(const float* __restrict__ bias){
    extern __shared__ unsigned smu[];
    // W bufs: buf*4608 (128 rows x stride 36); X bufs at 13824 + buf*2304 (32 rows x stride 72)
    int bp = blockIdx.x, n0b = blockIdx.y * 64;
    int t = threadIdx.x;
    int warp = t >> 5, lane = t & 31;
    int g = lane >> 2, tig = lane & 3;
    int m0 = (warp >> 1) * 32;
    int n0 = (warp & 1) * 32;
    float c[2][4][4];
    #pragma unroll
    for (int mt = 0; mt < 2; mt++)
        #pragma unroll
        for (int nt = 0; nt < 4; nt++)
            #pragma unroll
            for (int q = 0; q < 4; q++) c[mt][nt][q] = 0.f;
    const unsigned* xcb = g_xcolh + bp*409600 + n0b;

    auto stage = [&](int kp0, int buf){
        unsigned* dW = smu + buf*4608;
        unsigned* dX = smu + 13824 + buf*2304;
        #pragma unroll
        for (int s = 0; s < 4; s++){
            int e = t + s*256;                 // 1024 W cps: 128 rows x 32 words
            int co = e >> 3, kq = (e & 7) * 4;
            cp16(&dW[co*36 + kq], &g_w2h[co*1600 + kp0 + kq]);
        }
        #pragma unroll
        for (int s = 0; s < 2; s++){
            int e = t + s*256;                 // 512 X cps: 32 rows x 64 words
            int kk = e >> 4, ps = (e & 15) * 4;
            cp16(&dX[kk*72 + ps], &xcb[(kp0 + kk)*256 + ps]);
        }
        asm volatile("cp.async.commit_group;" ::);
    };

    stage(0, 0);
    stage(32, 1);
    for (int it = 0; it < 50; it++){
        if (it + 2 < 50) stage((it+2)*32, (it+2) % 3);
        if (it <= 47)      asm volatile("cp.async.wait_group 2;" ::);
        else if (it == 48) asm volatile("cp.async.wait_group 1;" ::);
        else               asm volatile("cp.async.wait_group 0;" ::);
        __syncthreads();
        const unsigned* dW = smu + (it % 3)*4608;
        const unsigned* dX = smu + 13824 + (it % 3)*2304;
        #pragma unroll
        for (int ks = 0; ks < 4; ks++){
            int kb = ks*8;
            unsigned a[2][4], bb[4][2];
            #pragma unroll
            for (int mt = 0; mt < 2; mt++){
                int m = m0 + mt*16;
                a[mt][0] = dW[(m+g)*36 + kb + tig];
                a[mt][1] = dW[(m+g+8)*36 + kb + tig];
                a[mt][2] = dW[(m+g)*36 + kb + 4 + tig];
                a[mt][3] = dW[(m+g+8)*36 + kb + 4 + tig];
            }
            #pragma unroll
            for (int nt = 0; nt < 4; nt++){
                int n = n0 + nt*8;
                bb[nt][0] = dX[(kb+tig)*72 + n + g];
                bb[nt][1] = dX[(kb+tig+4)*72 + n + g];
            }
            #pragma unroll
            for (int mt = 0; mt < 2; mt++)
                #pragma unroll
                for (int nt = 0; nt < 4; nt++)
                    asm volatile(
                        "mma.sync.aligned.m16n8k16.row.col.f32.f16.f16.f32 "
                        "{%0,%1,%2,%3}, {%4,%5,%6,%7}, {%8,%9}, {%0,%1,%2,%3};"
                        : "+f"(c[mt][nt][0]), "+f"(c[mt][nt][1]),
                          "+f"(c[mt][nt][2]), "+f"(c[mt][nt][3])
                        : "r"(a[mt][0]), "r"(a[mt][1]), "r"(a[mt][2]), "r"(a[mt][3]),
                          "r"(bb[nt][0]), "r"(bb[nt][1]));
        }
        __syncthreads();
    }
    float* ob = g_s2 + bp*32768;
    #pragma unroll
    for (int mt = 0; mt < 2; mt++){
        int coA = m0 + mt*16 + g;
        int coB = coA + 8;
        float bA = bias[coA], bB = bias[coB];
        #pragma unroll
        for (int nt = 0; nt < 4; nt++){
            int px = n0b + n0 + nt*8 + 2*tig;
            *reinterpret_cast<float2*>(ob + coA*256 + px) =
                make_float2(c[mt][nt][0] + bA, c[mt][nt][1] + bA);
            *reinterpret_cast<float2*>(ob + coB*256 + px) =
                make_float2(c[mt][nt][2] + bB, c[mt][nt][3] + bB);
        }
    }
}

// ---- gdn stage 2 (FFMA, in-place). grid 256, 256 thr ----
__global__ void gdn2_kernel(const float* __restrict__ beta){
    __shared__ float sA[2048];
    __shared__ float sB[1088];
    int bp = blockIdx.x >> 2;
    int p0 = (blockIdx.x & 3) * 64;
    int t = threadIdx.x;
    int i = t >> 4, j = t & 15;
    float* xb = g_s2 + bp*32768;
    float acc[8][4];
    #pragma unroll
    for (int ii = 0; ii < 8; ii++){
        float bb = beta[i*8 + ii];
        #pragma unroll
        for (int jj = 0; jj < 4; jj++) acc[ii][jj] = bb;
    }
    for (int c0 = 0; c0 < 128; c0 += 16){
        __syncthreads();
        for (int e = t; e < 2048; e += 256) sA[e] = g_gT2[c0*128 + e];
        for (int e = t; e < 1024; e += 256){
            int cc = e >> 6, p = e & 63;
            float v = xb[(c0+cc)*256 + p0 + p];
            sB[cc*68 + p] = v*v;
        }
        __syncthreads();
        #pragma unroll
        for (int cc = 0; cc < 16; cc++){
            float x0 = sB[cc*68 + j*4], x1 = sB[cc*68 + j*4 + 1];
            float x2 = sB[cc*68 + j*4 + 2], x3 = sB[cc*68 + j*4 + 3];
            float4 ga = *reinterpret_cast<const float4*>(sA + cc*128 + i*8);
            float4 gb = *reinterpret_cast<const float4*>(sA + cc*128 + i*8 + 4);
            float gs[8] = {ga.x,ga.y,ga.z,ga.w,gb.x,gb.y,gb.z,gb.w};
            #pragma unroll
            for (int ii = 0; ii < 8; ii++){
                acc[ii][0] = fmaf(gs[ii], x0, acc[ii][0]);
                acc[ii][1] = fmaf(gs[ii], x1, acc[ii][1]);
                acc[ii][2] = fmaf(gs[ii], x2, acc[ii][2]);
                acc[ii][3] = fmaf(gs[ii], x3, acc[ii][3]);
            }
        }
    }
    #pragma unroll
    for (int ii = 0; ii < 8; ii++){
        int d = i*8 + ii;
        float4 xv = *reinterpret_cast<const float4*>(xb + d*256 + p0 + j*4);
        float4 o;
        o.x = xv.x * rsqrtf(acc[ii][0]);
        o.y = xv.y * rsqrtf(acc[ii][1]);
        o.z = xv.z * rsqrtf(acc[ii][2]);
        o.w = xv.w * rsqrtf(acc[ii][3]);
        *reinterpret_cast<float4*>(xb + d*256 + p0 + j*4) = o;
    }
}

// ---- conv3 GEMM fp16. grid (64,4), 384 thr, 59904 B ----
__global__ void __launch_bounds__(384) conv3gemm_kernel(const float* __restrict__ bias){
    extern __shared__ unsigned smu3[];
    int bp = blockIdx.x, n0b = blockIdx.y * 64;
    int t = threadIdx.x;
    int warp = t >> 5, lane = t & 31;
    int g = lane >> 2, tig = lane & 3;
    int m0 = (warp >> 1) * 32;
    int n0 = (warp & 1) * 32;
    float c[2][4][4];
    #pragma unroll
    for (int mt = 0; mt < 2; mt++)
        #pragma unroll
        for (int nt = 0; nt < 4; nt++)
            #pragma unroll
            for (int q = 0; q < 4; q++) c[mt][nt][q] = 0.f;
    const unsigned* xcb = g_x3colh + bp*147456 + n0b;

    auto stage = [&](int kp0, int buf){
        unsigned* dW = smu3 + buf*3840;
        unsigned* dX = smu3 + 11520 + buf*1152;
        #pragma unroll
        for (int s = 0; s < 2; s++){
            int e = t + s*384;
            int co = e >> 2, kq = (e & 3) * 4;
            cp16(&dW[co*20 + kq], &g_w3h[co*576 + kp0 + kq]);
        }
        if (t < 256){
            int kk = t >> 4, ps = (t & 15) * 4;
            cp16(&dX[kk*72 + ps], &xcb[(kp0 + kk)*256 + ps]);
        }
        asm volatile("cp.async.commit_group;" ::);
    };

    stage(0, 0);
    stage(16, 1);
    for (int it = 0; it < 36; it++){
        if (it + 2 < 36) stage((it+2)*16, (it+2) % 3);
        if (it <= 33)      asm volatile("cp.async.wait_group 2;" ::);
        else if (it == 34) asm volatile("cp.async.wait_group 1;" ::);
        else               asm volatile("cp.async.wait_group 0;" ::);
        __syncthreads();
        const unsigned* dW = smu3 + (it % 3)*3840;
        const unsigned* dX = smu3 + 11520 + (it % 3)*1152;
        #pragma unroll
        for (int ks = 0; ks < 2; ks++){
            int kb = ks*8;
            unsigned a[2][4], bb[4][2];
            #pragma unroll
            for (int mt = 0; mt < 2; mt++){
                int m = m0 + mt*16;
                a[mt][0] = dW[(m+g)*20 + kb + tig];
                a[mt][1] = dW[(m+g+8)*20 + kb + tig];
                a[mt][2] = dW[(m+g)*20 + kb + 4 + tig];
                a[mt][3] = dW[(m+g+8)*20 + kb + 4 + tig];
            }
            #pragma unroll
            for (int nt = 0; nt < 4; nt++){
                int n = n0 + nt*8;
                bb[nt][0] = dX[(kb+tig)*72 + n + g];
                bb[nt][1] = dX[(kb+tig+4)*72 + n + g];
            }
            #pragma unroll
            for (int mt = 0; mt < 2; mt++)
                #pragma unroll
                for (int nt = 0; nt < 4; nt++)
                    asm volatile(
                        "mma.sync.aligned.m16n8k16.row.col.f32.f16.f16.f32 "
                        "{%0,%1,%2,%3}, {%4,%5,%6,%7}, {%8,%9}, {%0,%1,%2,%3};"
                        : "+f"(c[mt][nt][0]), "+f"(c[mt][nt][1]),
                          "+f"(c[mt][nt][2]), "+f"(c[mt][nt][3])
                        : "r"(a[mt][0]), "r"(a[mt][1]), "r"(a[mt][2]), "r"(a[mt][3]),
                          "r"(bb[nt][0]), "r"(bb[nt][1]));
        }
        __syncthreads();
    }
    float* ob = g_y3 + bp*49152;
    #pragma unroll
    for (int mt = 0; mt < 2; mt++){
        int coA = m0 + mt*16 + g;
        int coB = coA + 8;
        float bA = bias[coA], bB = bias[coB];
        #pragma unroll
        for (int nt = 0; nt < 4; nt++){
            int px = n0b + n0 + nt*8 + 2*tig;
            *reinterpret_cast<float2*>(ob + coA*256 + px) =
                make_float2(c[mt][nt][0] + bA, c[mt][nt][1] + bA);
            *reinterpret_cast<float2*>(ob + coB*256 + px) =
                make_float2(c[mt][nt][2] + bB, c[mt][nt][3] + bB);
        }
    }
}

// ---- qn: LN of y3 -> g_qnT + g_qnh. grid (64,8), 256 thr ----
__global__ void qn_kernel(const float* __restrict__ lnqw, const float* __restrict__ lnqb){
    __shared__ float s[192*33];
    int bp = blockIdx.x, q0 = blockIdx.y << 5;
    int t = threadIdx.x;
    int w = t >> 5, l = t & 31;
    const float* y3 = g_y3 + bp*49152;
    for (int e = t; e < 6144; e += 256){
        int m = e >> 5, qq = e & 31;
        s[m*33 + qq] = y3[m*256 + q0 + qq];
    }
    __syncthreads();
    {
        float lwv[6], lbv[6];
        #pragma unroll
        for (int i = 0; i < 6; i++){ lwv[i] = lnqw[l+32*i]; lbv[i] = lnqb[l+32*i]; }
        for (int qi = 0; qi < 4; qi++){
            int q = w*4 + qi;
            float v[6]; float sum = 0.f;
            #pragma unroll
            for (int i = 0; i < 6; i++){ v[i] = s[(l+32*i)*33 + q]; sum += v[i]; }
            #pragma unroll
            for (int o = 16; o > 0; o >>= 1) sum += __shfl_xor_sync(0xffffffffu, sum, o);
            float mu = sum * (1.f/192.f);
            float vs = 0.f;
            #pragma unroll
            for (int i = 0; i < 6; i++){ float d = v[i]-mu; vs += d*d; }
            #pragma unroll
            for (int o = 16; o > 0; o >>= 1) vs += __shfl_xor_sync(0xffffffffu, vs, o);
            float rs = rsqrtf(vs * (1.f/192.f) + LN_EPS);
            #pragma unroll
            for (int i = 0; i < 6; i++)
                s[(l+32*i)*33 + q] = (v[i]-mu)*rs*lwv[i] + lbv[i];
        }
    }
    __syncthreads();
    float* qt = g_qnT + bp*49152;
    for (int e = t; e < 6144; e += 256){
        int n = e >> 5, qq = e & 31;
        qt[n*256 + q0 + qq] = s[n*33 + qq];
    }
    unsigned* qh = g_qnh + bp*24576;
    for (int e = t; e < 3072; e += 256){
        int mp = e >> 5, qq = e & 31;
        qh[mp*256 + q0 + qq] = packh(s[(2*mp)*33 + qq], s[(2*mp+1)*33 + qq]);
    }
}

// ---- qproj GEMM fp16. grid (64,4), 256 thr, 44544 B ----
__global__ void __launch_bounds__(256) qproj_kernel(){
    extern __shared__ unsigned smq[];
    int bp = blockIdx.x, n0b = blockIdx.y * 64;
    int t = threadIdx.x;
    int warp = t >> 5, lane = t & 31;
    int g = lane >> 2, tig = lane & 3;
    int m0 = (warp >> 1) * 32;
    int n0 = (warp & 1) * 32;
    float c[2][4][4];
    #pragma unroll
    for (int mt = 0; mt < 2; mt++)
        #pragma unroll
        for (int nt = 0; nt < 4; nt++)
            #pragma unroll
            for (int q = 0; q < 4; q++) c[mt][nt][q] = 0.f;
    const unsigned* xcb = g_qnh + bp*24576 + n0b;

    auto stage = [&](int kp0, int buf){
        unsigned* dW = smq + buf*2560;
        unsigned* dX = smq + 7680 + buf*1152;
        #pragma unroll
        for (int s = 0; s < 2; s++){
            int e = t + s*256;
            int co = e >> 2, kq = (e & 3) * 4;
            cp16(&dW[co*20 + kq], &g_wqh[co*96 + kp0 + kq]);
        }
        {
            int kk = t >> 4, ps = (t & 15) * 4;
            cp16(&dX[kk*72 + ps], &xcb[(kp0 + kk)*256 + ps]);
        }
        asm volatile("cp.async.commit_group;" ::);
    };

    stage(0, 0);
    stage(16, 1);
    for (int it = 0; it < 6; it++){
        if (it + 2 < 6) stage((it+2)*16, (it+2) % 3);
        if (it <= 3)      asm volatile("cp.async.wait_group 2;" ::);
        else if (it == 4) asm volatile("cp.async.wait_group 1;" ::);
        else              asm volatile("cp.async.wait_group 0;" ::);
        __syncthreads();
        const unsigned* dW = smq + (it % 3)*2560;
        const unsigned* dX = smq + 7680 + (it % 3)*1152;
        #pragma unroll
        for (int ks = 0; ks < 2; ks++){
            int kb = ks*8;
            unsigned a[2][4], bb[4][2];
            #pragma unroll
            for (int mt = 0; mt < 2; mt++){
                int m = m0 + mt*16;
                a[mt][0] = dW[(m+g)*20 + kb + tig];
                a[mt][1] = dW[(m+g+8)*20 + kb + tig];
                a[mt][2] = dW[(m+g)*20 + kb + 4 + tig];
                a[mt][3] = dW[(m+g+8)*20 + kb + 4 + tig];
            }
            #pragma unroll
            for (int nt = 0; nt < 4; nt++){
                int n = n0 + nt*8;
                bb[nt][0] = dX[(kb+tig)*72 + n + g];
                bb[nt][1] = dX[(kb+tig+4)*72 + n + g];
            }
            #pragma unroll
            for (int mt = 0; mt < 2; mt++)
                #pragma unroll
                for (int nt = 0; nt < 4; nt++)
                    asm volatile(
                        "mma.sync.aligned.m16n8k16.row.col.f32.f16.f16.f32 "
                        "{%0,%1,%2,%3}, {%4,%5,%6,%7}, {%8,%9}, {%0,%1,%2,%3};"
                        : "+f"(c[mt][nt][0]), "+f"(c[mt][nt][1]),
                          "+f"(c[mt][nt][2]), "+f"(c[mt][nt][3])
                        : "r"(a[mt][0]), "r"(a[mt][1]), "r"(a[mt][2]), "r"(a[mt][3]),
                          "r"(bb[nt][0]), "r"(bb[nt][1]));
        }
        __syncthreads();
    }
    float* ob = g_qp + bp*32768;
    #pragma unroll
    for (int mt = 0; mt < 2; mt++){
        int coA = m0 + mt*16 + g;
        int coB = coA + 8;
        #pragma unroll
        for (int nt = 0; nt < 4; nt++){
            int px = n0b + n0 + nt*8 + 2*tig;
            *reinterpret_cast<float2*>(ob + coA*256 + px) =
                make_float2(c[mt][nt][0], c[mt][nt][1]);
            *reinterpret_cast<float2*>(ob + coB*256 + px) =
                make_float2(c[mt][nt][2], c[mt][nt][3]);
        }
    }
}

// ---- kv: LN + k_proj + v_proj. grid (64,5), 256 thr ----
__global__ void kv_kernel(const float* __restrict__ yg, const float* __restrict__ lnw,
                          const float* __restrict__ lnb, const float* __restrict__ Wk,
                          const float* __restrict__ Wv){
    __shared__ float s_kv[32*193];
    __shared__ float s_w[64*33];
    int bp = blockIdx.x;
    int r0 = blockIdx.y * 64;
    int t = threadIdx.x;
    int w = t >> 5, l = t & 31;
    for (int e = t; e < 6144; e += 256){
        int c = e >> 5, k = e & 31;
        s_kv[k*193 + c] = yg[bp*6144 + c*32 + k];
    }
    __syncthreads();
    {
        float lwv[6], lbv[6];
        #pragma unroll
        for (int i = 0; i < 6; i++){ lwv[i] = lnw[l+32*i]; lbv[i] = lnb[l+32*i]; }
        for (int ki = 0; ki < 4; ki++){
            int k = w*4 + ki;
            float v[6]; float s = 0.f;
            #pragma unroll
            for (int i = 0; i < 6; i++){ v[i] = s_kv[k*193 + l + 32*i]; s += v[i]; }
            #pragma unroll
            for (int o = 16; o > 0; o >>= 1) s += __shfl_xor_sync(0xffffffffu, s, o);
            float mu = s * (1.f/192.f);
            float vs = 0.f;
            #pragma unroll
            for (int i = 0; i < 6; i++){ float d = v[i]-mu; vs += d*d; }
            #pragma unroll
            for (int o = 16; o > 0; o >>= 1) vs += __shfl_xor_sync(0xffffffffu, vs, o);
            float rs = rsqrtf(vs * (1.f/192.f) + LN_EPS);
            #pragma unroll
            for (int i = 0; i < 6; i++)
                s_kv[k*193 + l + 32*i] = (v[i]-mu)*rs*lwv[i] + lbv[i];
        }
    }
    int kq = t & 7, rp = t >> 3;
    {
        float acc[2][4];
        #pragma unroll
        for (int i = 0; i < 2; i++)
            #pragma unroll
            for (int kk = 0; kk < 4; kk++) acc[i][kk] = 0.f;
        for (int c0 = 0; c0 < 192; c0 += 32){
            __syncthreads();
            for (int e = t; e < 2048; e += 256){
                int rr = e >> 5, cc = e & 31;
                int row = r0 + rr;
                s_w[rr*33 + cc] = (row < 128) ? Wk[row*192 + c0 + cc]
                                              : Wv[(row-128)*192 + c0 + cc];
            }
            __syncthreads();
            for (int cc = 0; cc < 32; cc++){
                float wv0 = s_w[(rp*2)*33 + cc], wv1 = s_w[(rp*2+1)*33 + cc];
                #pragma unroll
                for (int kk = 0; kk < 4; kk++){
                    float kvv = s_kv[(kq*4+kk)*193 + c0 + cc];
                    acc[0][kk] = fmaf(wv0, kvv, acc[0][kk]);
                    acc[1][kk] = fmaf(wv1, kvv, acc[1][kk]);
                }
            }
        }
        #pragma unroll
        for (int i = 0; i < 2; i++){
            int row = r0 + rp*2 + i;
            #pragma unroll
            for (int kk = 0; kk < 4; kk++){
                int k = kq*4 + kk;
                if (row < 128) g_kp[bp*4096 + k*128 + row] = acc[i][kk];
                else           g_vp[bp*6144 + k*192 + (row-128)] = acc[i][kk];
            }
        }
    }
}

// ---- attention core. grid 512, 256 thr, 62720 B ----
__global__ void attn_kernel(const float* __restrict__ vw){
    extern __shared__ float sm[];
    float* s_kp = sm;
    float* s_vp = sm + 4224;
    float* s_e  = sm + 10400;
    float* s_qp = sm + 11456;
    int bp = blockIdx.x >> 3;
    int q0 = (blockIdx.x & 7) << 5;
    int t = threadIdx.x;
    int w = t >> 5, l = t & 31;
    for (int e = t; e < 4096; e += 256){
        int k = e >> 7;
        s_kp[k*132 + (e & 127)] = g_kp[bp*4096 + e];
    }
    for (int e = t; e < 6144; e += 256){
        int k = e / 192, m = e - k*192;
        s_vp[k*193 + m] = g_vp[bp*6144 + e];
    }
    {
        const float* qpb = g_qp + bp*32768;
        for (int e = t; e < 4096; e += 256){
            int d = e >> 5, qq = e & 31;
            s_qp[d*33 + qq] = qpb[d*256 + q0 + qq];
        }
    }
    __syncthreads();
    float vv[4];
    #pragma unroll
    for (int j = 0; j < 4; j++) vv[j] = vw[l + 32*j];
    for (int k = 0; k < 32; k++){
        float kp4[4];
        #pragma unroll
        for (int j = 0; j < 4; j++) kp4[j] = s_kp[k*132 + l + 32*j];
        #pragma unroll
        for (int qi = 0; qi < 4; qi++){
            int q = w*4 + qi;
            float s = 0.f;
            #pragma unroll
            for (int j = 0; j < 4; j++)
                s = fmaf(tanh_fast(s_qp[(l+32*j)*33 + q] + kp4[j]), vv[j], s);
            #pragma unroll
            for (int o = 16; o > 0; o >>= 1) s += __shfl_xor_sync(0xffffffffu, s, o);
            if (l == 0) s_e[q*33 + k] = s;
        }
    }
    __syncwarp();
    for (int qi = 0; qi < 4; qi++){
        int q = w*4 + qi;
        float ev = s_e[q*33 + l];
        float mx = ev;
        #pragma unroll
        for (int o = 16; o > 0; o >>= 1) mx = fmaxf(mx, __shfl_xor_sync(0xffffffffu, mx, o));
        float p = __expf(ev - mx);
        float s = p;
        #pragma unroll
        for (int o = 16; o > 0; o >>= 1) s += __shfl_xor_sync(0xffffffffu, s, o);
        s_e[q*33 + l] = p / s;
    }
    __syncthreads();
    {
        int qr = t >> 3, mg = t & 7;
        float acc[24];
        #pragma unroll
        for (int i = 0; i < 24; i++) acc[i] = 0.f;
        for (int k = 0; k < 32; k++){
            float a = s_e[qr*33 + k];
            #pragma unroll
            for (int i = 0; i < 24; i++)
                acc[i] = fmaf(a, s_vp[k*193 + mg + 8*i], acc[i]);
        }
        __half* ch = reinterpret_cast<__half*>(g_ctxh) + (ull)(bp*256 + q0 + qr)*192;
        #pragma unroll
        for (int i = 0; i < 24; i++)
            ch[mg + 8*i] = __float2half_rn(acc[i]);
    }
}

// ---- outproj: GEMM + bias + residual + LN + transpose. grid (64,4), 384 thr ----
__global__ void __launch_bounds__(384) outproj_kernel(const float* __restrict__ outb,
                                                      const float* __restrict__ lnow,
                                                      const float* __restrict__ lnob,
                                                      float* __restrict__ out){
    extern __shared__ unsigned smo[];
    float* se = reinterpret_cast<float*>(smo);
    float* red = se + 13056;
    int bp = blockIdx.x, q0b = blockIdx.y * 64;
    int t = threadIdx.x;
    int warp = t >> 5, lane = t & 31;
    int g = lane >> 2, tig = lane & 3;
    int m0 = (warp >> 1) * 32;
    int n0 = (warp & 1) * 32;
    float c[2][4][4];
    #pragma unroll
    for (int mt = 0; mt < 2; mt++)
        #pragma unroll
        for (int nt = 0; nt < 4; nt++)
            #pragma unroll
            for (int q = 0; q < 4; q++) c[mt][nt][q] = 0.f;
    const unsigned* ctxw = g_ctxh + (ull)(bp*256 + q0b)*96;

    auto stage = [&](int kp0, int buf){
        unsigned* dW = smo + buf*2304;
        unsigned* dX = smo + 6912 + buf*768;
        {
            int co = t >> 1, ps = (t & 1) * 4;
            cp16(&dW[co*12 + ps], &g_owh[co*96 + kp0 + ps]);
        }
        if (t < 128){
            int q = t >> 1, ps = (t & 1) * 4;
            cp16(&dX[q*12 + ps], &ctxw[q*96 + kp0 + ps]);
        }
        asm volatile("cp.async.commit_group;" ::);
    };

    stage(0, 0);
    stage(8, 1);
    for (int it = 0; it < 12; it++){
        if (it + 2 < 12) stage((it+2)*8, (it+2) % 3);
        if (it <= 9)       asm volatile("cp.async.wait_group 2;" ::);
        else if (it == 10) asm volatile("cp.async.wait_group 1;" ::);
        else               asm volatile("cp.async.wait_group 0;" ::);
        __syncthreads();
        const unsigned* dW = smo + (it % 3)*2304;
        const unsigned* dX = smo + 6912 + (it % 3)*768;
        unsigned a[2][4], bb[4][2];
        #pragma unroll
        for (int mt = 0; mt < 2; mt++){
            int m = m0 + mt*16;
            a[mt][0] = dW[(m+g)*12 + tig];
            a[mt][1] = dW[(m+g+8)*12 + tig];
            a[mt][2] = dW[(m+g)*12 + 4 + tig];
            a[mt][3] = dW[(m+g+8)*12 + 4 + tig];
        }
        #pragma unroll
        for (int nt = 0; nt < 4; nt++){
            int n = n0 + nt*8;
            bb[nt][0] = dX[(n+g)*12 + tig];
            bb[nt][1] = dX[(n+g)*12 + 4 + tig];
        }
        #pragma unroll
        for (int mt = 0; mt < 2; mt++)
            #pragma unroll
            for (int nt = 0; nt < 4; nt++)
                asm volatile(
                    "mma.sync.aligned.m16n8k16.row.col.f32.f16.f16.f32 "
                    "{%0,%1,%2,%3}, {%4,%5,%6,%7}, {%8,%9}, {%0,%1,%2,%3};"
                    : "+f"(c[mt][nt][0]), "+f"(c[mt][nt][1]),
                      "+f"(c[mt][nt][2]), "+f"(c[mt][nt][3])
                    : "r"(a[mt][0]), "r"(a[mt][1]), "r"(a[mt][2]), "r"(a[mt][3]),
                      "r"(bb[nt][0]), "r"(bb[nt][1]));
        __syncthreads();
    }
    #pragma unroll
    for (int mt = 0; mt < 2; mt++){
        int coA = m0 + mt*16 + g;
        int coB = coA + 8;
        #pragma unroll
        for (int nt = 0; nt < 4; nt++){
            int px = n0 + nt*8 + 2*tig;
            se[coA*68 + px]     = c[mt][nt][0];
            se[coA*68 + px + 1] = c[mt][nt][1];
            se[coB*68 + px]     = c[mt][nt][2];
            se[coB*68 + px + 1] = c[mt][nt][3];
        }
    }
    __syncthreads();
    int seg = t >> 6, tq = t & 63;
    float val[32];
    float s = 0.f, ss = 0.f;
    const float* qn = g_qnT + bp*49152 + q0b + tq;
    #pragma unroll
    for (int i = 0; i < 32; i++){
        int n = seg*32 + i;
        float v = se[n*68 + tq] + outb[n] + qn[n*256];
        val[i] = v;
        s += v; ss += v*v;
    }
    red[seg*64 + tq] = s;
    red[384 + seg*64 + tq] = ss;
    __syncthreads();
    if (t < 64){
        float st = 0.f, sst = 0.f;
        #pragma unroll
        for (int k = 0; k < 6; k++){ st += red[k*64 + t]; sst += red[384 + k*64 + t]; }
        float mu = st * (1.f/192.f);
        float var = sst * (1.f/192.f) - mu*mu;
        red[768 + t] = mu;
        red[832 + t] = rsqrtf(var + LN_EPS);
    }
    __syncthreads();
    float mu = red[768 + tq], rs = red[832 + tq];
    float* ob = out + bp*49152 + q0b + tq;
    #pragma unroll
    for (int i = 0; i < 32; i++){
        int n = seg*32 + i;
        ob[n*256] = (val[i] - mu)*rs*lnow[n] + lnob[n];
    }
}

extern "C" void kernel_launch(void* const* d_in, const int* in_sizes, int n_in,
                              void* d_out, int out_size){
    const float* x_p    = (const float*)d_in[0];
    const float* y_g    = (const float*)d_in[1];
    const float* conv1w = (const float*)d_in[2];
    const float* conv1b = (const float*)d_in[3];
    const float* gamma1 = (const float*)d_in[4];
    const float* beta1  = (const float*)d_in[5];
    const float* conv2w = (const float*)d_in[6];
    const float* conv2b = (const float*)d_in[7];
    const float* gamma2 = (const float*)d_in[8];
    const float* beta2  = (const float*)d_in[9];
    const float* conv3w = (const float*)d_in[10];
    const float* conv3b = (const float*)d_in[11];
    const float* lnqw   = (const float*)d_in[12];
    const float* lnqb   = (const float*)d_in[13];
    const float* lnkw   = (const float*)d_in[14];
    const float* lnkb   = (const float*)d_in[15];
    const float* lnow   = (const float*)d_in[16];
    const float* lnob   = (const float*)d_in[17];
    const float* Wq     = (const float*)d_in[18];
    const float* Wk     = (const float*)d_in[19];
    const float* vw     = (const float*)d_in[20];
    const float* Wv     = (const float*)d_in[21];
    const float* outw   = (const float*)d_in[22];
    const float* outb   = (const float*)d_in[23];
    float* out = (float*)d_out;

    cudaFuncSetAttribute(attn_kernel, cudaFuncAttributeMaxDynamicSharedMemorySize, 62720);
    cudaFuncSetAttribute(conv2gemm_kernel, cudaFuncAttributeMaxDynamicSharedMemorySize, 82944);
    cudaFuncSetAttribute(conv3gemm_kernel, cudaFuncAttributeMaxDynamicSharedMemorySize, 59904);
    cudaFuncSetAttribute(gdngemm_kernel, cudaFuncAttributeMaxDynamicSharedMemorySize, 44544);
    cudaFuncSetAttribute(qproj_kernel, cudaFuncAttributeMaxDynamicSharedMemorySize, 44544);
    cudaFuncSetAttribute(outproj_kernel, cudaFuncAttributeMaxDynamicSharedMemorySize, 55808);

    conv1_kernel<<<dim3(64,4,2), 256>>>(x_p, conv1w, conv1b, gamma1, gamma2,
                                        conv2w, conv3w, outw, Wq);                 // 0
    gdngemm_kernel<<<dim3(64,16), 256, 44544>>>(beta1);                            // 1
    im2col2_kernel<<<dim3(800,64), 256>>>();                                       // 2
    conv2gemm_kernel<<<dim3(64,4), 256, 82944>>>(conv2b);                          // 3 (profiled)
    gdn2_kernel<<<256, 256>>>(beta2);                                              // 4
    im2col3_kernel<<<dim3(288,64), 256>>>();                                       // 5
    conv3gemm_kernel<<<dim3(64,4), 384, 59904>>>(conv3b);                          // 6
    qn_kernel<<<dim3(64,8), 256>>>(lnqw, lnqb);                                    // 7
    qproj_kernel<<<dim3(64,4), 256, 44544>>>();                                    // 8
    kv_kernel<<<dim3(64,5), 256>>>(y_g, lnkw, lnkb, Wk, Wv);                       // 9
    attn_kernel<<<512, 256, 62720>>>(vw);                                          // 10
    outproj_kernel<<<dim3(64,4), 384, 55808>>>(outb, lnow, lnob, out);             // 11
}